// round 8
// baseline (speedup 1.0000x reference)
#include <cuda_runtime.h>
#include <cuda_bf16.h>
#include <cstdint>

#define H    512
#define NLAY 4
#define N2   32
#define BSZ  8
#define LSEQ 4096
#define MROWS (BSZ * LSEQ)     /* 32768 */
#define NC   32                /* scan chunks */
#define CL   (LSEQ / NC)       /* 128 steps per chunk */
#define LN_EPS 1e-5f

typedef unsigned long long u64;

// ---- static scratch (allocation-free rule). layout (B,L,H) row-major ----
__device__ __align__(256) float g_xA[(size_t)MROWS * H];            // 64MB
__device__ __align__(256) float g_xB[(size_t)MROWS * H];            // 64MB
__device__ __align__(256) __nv_bfloat16 g_Yhi [(size_t)MROWS * H];  // 32MB
__device__ __align__(256) __nv_bfloat16 g_Ymid[(size_t)MROWS * H];  // 32MB
__device__ __align__(256) __nv_bfloat16 g_Whi [(size_t)NLAY * 2 * H * H]; // 4MB (interleaved rows)
__device__ __align__(256) __nv_bfloat16 g_Wmid[(size_t)NLAY * 2 * H * H]; // 4MB
__device__ __align__(256) float g_bint[NLAY * 2 * H];               // interleaved bias
__device__ __align__(256) float g_Z[(size_t)MROWS * H];             // 64MB GLU output
__device__ __align__(256) float g_E[(size_t)BSZ * NC * H * N2 * 2]; // end states
__device__ __align__(256) float g_S[(size_t)BSZ * NC * H * N2 * 2]; // init states

// ---------------- packed f32x2 helpers ----------------
__device__ __forceinline__ u64 pk(float lo, float hi) {
    u64 r; asm("mov.b64 %0, {%1,%2};" : "=l"(r) : "f"(lo), "f"(hi)); return r;
}
__device__ __forceinline__ void upk(u64 v, float& lo, float& hi) {
    asm("mov.b64 {%0,%1}, %2;" : "=f"(lo), "=f"(hi) : "l"(v));
}
__device__ __forceinline__ u64 fma2(u64 a, u64 b, u64 c) {
    u64 d; asm("fma.rn.f32x2 %0, %1, %2, %3;" : "=l"(d) : "l"(a), "l"(b), "l"(c)); return d;
}
__device__ __forceinline__ u64 mul2(u64 a, u64 b) {
    u64 d; asm("mul.rn.f32x2 %0, %1, %2;" : "=l"(d) : "l"(a), "l"(b)); return d;
}
__device__ __forceinline__ void cpa16(void* dst, const void* src) {
    unsigned d = (unsigned)__cvta_generic_to_shared(dst);
    asm volatile("cp.async.cg.shared.global [%0], [%1], 16;" :: "r"(d), "l"(src));
}
__device__ __forceinline__ void ldsm4(uint32_t& r0, uint32_t& r1, uint32_t& r2,
                                      uint32_t& r3, const void* p) {
    uint32_t a = (uint32_t)__cvta_generic_to_shared(p);
    asm volatile("ldmatrix.sync.aligned.m8n8.x4.shared.b16 {%0,%1,%2,%3}, [%4];"
                 : "=r"(r0), "=r"(r1), "=r"(r2), "=r"(r3) : "r"(a));
}

// =====================================================================
// Shared coefficient computation for the scan kernels
// =====================================================================
__device__ __forceinline__ void scan_coeffs(
    const float* log_dt, const float* A_imag, const float* log_A_real,
    int layer, int h, int li, float* w_re, float* w_im, float* Are_o, float* Aim_o,
    float* dt_o)
{
    float dt = expf(log_dt[layer * H + h]);
    int pbase = (layer * H + h) * N2 + li * 4;
    float4 aim = *(const float4*)(A_imag + pbase);
    float4 lar = *(const float4*)(log_A_real + pbase);
    float aimv[4] = {aim.x, aim.y, aim.z, aim.w};
    float larv[4] = {lar.x, lar.y, lar.z, lar.w};
#pragma unroll
    for (int j = 0; j < 4; j++) {
        float Are = -expf(larv[j]);
        float e = expf(Are * dt);
        w_re[j] = e * cosf(aimv[j] * dt);
        w_im[j] = e * sinf(aimv[j] * dt);
        Are_o[j] = Are; Aim_o[j] = aimv[j];
    }
    *dt_o = dt;
}

// =====================================================================
// Pass 1: chunk-local end states, 4-step blocked recurrence.
// s <- w^4 s + w^3 u0 + w^2 u1 + w u2 + u3   (no per-step outputs)
// =====================================================================
__global__ __launch_bounds__(256) void ssm_pass1(
    const float* __restrict__ xin,
    const float* __restrict__ log_dt, const float* __restrict__ A_imag,
    const float* __restrict__ log_A_real, int layer)
{
    __shared__ float u_t[2][16][32];
    int tid = threadIdx.x;
    int b = blockIdx.x >> 4;
    int h0 = (blockIdx.x & 15) * 32;
    int c = blockIdx.y;
    int hloc = tid >> 3, li = tid & 7;
    int h = h0 + hloc;
    int lrow = tid >> 5, lcol = tid & 31;

    float w_re[4], w_im[4], Are[4], Aim[4], dt;
    scan_coeffs(log_dt, A_imag, log_A_real, layer, h, li, w_re, w_im, Are, Aim, &dt);
    // complex powers w^2, w^3, w^4
    float w2r[4], w2i[4], w3r[4], w3i[4], w4r[4], w4i[4];
#pragma unroll
    for (int j = 0; j < 4; j++) {
        w2r[j] = w_re[j] * w_re[j] - w_im[j] * w_im[j];
        w2i[j] = 2.0f * w_re[j] * w_im[j];
        w3r[j] = w2r[j] * w_re[j] - w2i[j] * w_im[j];
        w3i[j] = w2r[j] * w_im[j] + w2i[j] * w_re[j];
        w4r[j] = w2r[j] * w2r[j] - w2i[j] * w2i[j];
        w4i[j] = 2.0f * w2r[j] * w2i[j];
    }
    u64 wre[2]  = {pk(w_re[0], w_re[1]), pk(w_re[2], w_re[3])};
    u64 wim[2]  = {pk(w_im[0], w_im[1]), pk(w_im[2], w_im[3])};
    u64 w2re[2] = {pk(w2r[0], w2r[1]), pk(w2r[2], w2r[3])};
    u64 w2im[2] = {pk(w2i[0], w2i[1]), pk(w2i[2], w2i[3])};
    u64 w3re[2] = {pk(w3r[0], w3r[1]), pk(w3r[2], w3r[3])};
    u64 w3im[2] = {pk(w3i[0], w3i[1]), pk(w3i[2], w3i[3])};
    u64 w4re[2] = {pk(w4r[0], w4r[1]), pk(w4r[2], w4r[3])};
    u64 w4im[2] = {pk(w4i[0], w4i[1]), pk(w4i[2], w4i[3])};
    u64 nw4im[2]= {pk(-w4i[0], -w4i[1]), pk(-w4i[2], -w4i[3])};

    const float* xr = xin + ((size_t)b * LSEQ + (size_t)c * CL) * H + h0;
    u_t[0][lrow][lcol]     = xr[(size_t)lrow * H + lcol];
    u_t[0][lrow + 8][lcol] = xr[(size_t)(lrow + 8) * H + lcol];
    __syncthreads();

    u64 s2re[2] = {0ull, 0ull}, s2im[2] = {0ull, 0ull};
    for (int it = 0; it < CL / 16; it++) {
        int buf = it & 1, l0 = it * 16;
        float p0 = 0.f, p1 = 0.f;
        if (it + 1 < CL / 16) {
            p0 = xr[(size_t)(l0 + 16 + lrow) * H + lcol];
            p1 = xr[(size_t)(l0 + 24 + lrow) * H + lcol];
        }
#pragma unroll
        for (int k4 = 0; k4 < 4; k4++) {
            float u0 = u_t[buf][k4 * 4 + 0][hloc];
            float u1 = u_t[buf][k4 * 4 + 1][hloc];
            float u2 = u_t[buf][k4 * 4 + 2][hloc];
            float u3 = u_t[buf][k4 * 4 + 3][hloc];
            u64 u0p = pk(u0, u0), u1p = pk(u1, u1), u2p = pk(u2, u2), u3p = pk(u3, u3);
#pragma unroll
            for (int p = 0; p < 2; p++) {
                u64 tre = fma2(w3re[p], u0p, fma2(w2re[p], u1p, fma2(wre[p], u2p, u3p)));
                u64 tim = fma2(w3im[p], u0p, fma2(w2im[p], u1p, mul2(wim[p], u2p)));
                u64 nre = fma2(w4re[p], s2re[p], fma2(nw4im[p], s2im[p], tre));
                u64 nim = fma2(w4im[p], s2re[p], fma2(w4re[p], s2im[p], tim));
                s2re[p] = nre; s2im[p] = nim;
            }
        }
        if (it + 1 < CL / 16) {
            u_t[buf ^ 1][lrow][lcol] = p0;
            u_t[buf ^ 1][lrow + 8][lcol] = p1;
        }
        __syncthreads();
    }
    float r0, r1, r2, r3, i0, i1, i2, i3;
    upk(s2re[0], r0, r1); upk(s2re[1], r2, r3);
    upk(s2im[0], i0, i1); upk(s2im[1], i2, i3);
    float* Ep = g_E + ((((size_t)b * NC + c) * H + h) * 8 + li) * 8;
    ((float4*)Ep)[0] = make_float4(r0, i0, r1, i1);
    ((float4*)Ep)[1] = make_float4(r2, i2, r3, i3);
}

// =====================================================================
// Pass 2: prefix over chunks. (b,h,li) threads.
// =====================================================================
__global__ __launch_bounds__(256) void ssm_prefix(
    const float* __restrict__ log_dt, const float* __restrict__ A_imag,
    const float* __restrict__ log_A_real, int layer)
{
    int idx = blockIdx.x * 256 + threadIdx.x;
    int b = idx >> 12, rem = idx & 4095;
    int h = rem >> 3, li = rem & 7;

    float w_re[4], w_im[4], Are[4], Aim[4], dt;
    scan_coeffs(log_dt, A_imag, log_A_real, layer, h, li, w_re, w_im, Are, Aim, &dt);
    float Wr[4], Wi[4];
#pragma unroll
    for (int j = 0; j < 4; j++) {                  // w^CL = exp(dA*CL)
        float e = expf(Are[j] * dt * (float)CL);
        Wr[j] = e * cosf(Aim[j] * dt * (float)CL);
        Wi[j] = e * sinf(Aim[j] * dt * (float)CL);
    }
    float Ire[4] = {0,0,0,0}, Iim[4] = {0,0,0,0};
    for (int c = 0; c < NC; c++) {
        size_t off = ((((size_t)b * NC + c) * H + h) * 8 + li) * 8;
        float* Sp = g_S + off;
        ((float4*)Sp)[0] = make_float4(Ire[0], Iim[0], Ire[1], Iim[1]);
        ((float4*)Sp)[1] = make_float4(Ire[2], Iim[2], Ire[3], Iim[3]);
        const float* Ep = g_E + off;
        float4 e0 = ((const float4*)Ep)[0], e1 = ((const float4*)Ep)[1];
        float er[4] = {e0.x, e0.z, e1.x, e1.z};
        float ei[4] = {e0.y, e0.w, e1.y, e1.w};
#pragma unroll
        for (int j = 0; j < 4; j++) {
            float nr = fmaf(Wr[j], Ire[j], fmaf(-Wi[j], Iim[j], er[j]));
            float ni = fmaf(Wi[j], Ire[j], fmaf( Wr[j], Iim[j], ei[j]));
            Ire[j] = nr; Iim[j] = ni;
        }
    }
}

// =====================================================================
// Pass 3: full scan with init state, GELU, emit bf16 hi/mid planes.
// =====================================================================
__global__ __launch_bounds__(256) void ssm_pass3(
    const float* __restrict__ xin,
    const float* __restrict__ log_dt, const float* __restrict__ A_imag,
    const float* __restrict__ log_A_real, const float* __restrict__ Cp,
    const float* __restrict__ Dp, int layer)
{
    __shared__ float u_t[2][16][32];
    __shared__ float y_t[2][16][32];
    int tid = threadIdx.x;
    int b = blockIdx.x >> 4;
    int h0 = (blockIdx.x & 15) * 32;
    int c = blockIdx.y;
    int hloc = tid >> 3, li = tid & 7;
    int h = h0 + hloc;
    int lrow = tid >> 5, lcol = tid & 31;

    float w_re[4], w_im[4], Are[4], Aim[4], dt;
    scan_coeffs(log_dt, A_imag, log_A_real, layer, h, li, w_re, w_im, Are, Aim, &dt);
    int pbase = (layer * H + h) * N2 + li * 4;
    float4 c01 = *(const float4*)(Cp + 2 * pbase);
    float4 c23 = *(const float4*)(Cp + 2 * pbase + 4);
    float ccr[4] = {c01.x, c01.z, c23.x, c23.z};
    float cci[4] = {c01.y, c01.w, c23.y, c23.w};
    float cf_re[4], cf_im[4];
#pragma unroll
    for (int j = 0; j < 4; j++) {
        float nr = w_re[j] - 1.0f, ni = w_im[j];
        float tr = ccr[j] * nr - cci[j] * ni;
        float ti = ccr[j] * ni + cci[j] * nr;
        float inv = 2.0f / (Are[j] * Are[j] + Aim[j] * Aim[j]);
        cf_re[j] = (tr * Are[j] + ti * Aim[j]) * inv;
        cf_im[j] = (ti * Are[j] - tr * Aim[j]) * inv;
    }
    u64 w2re[2]  = {pk(w_re[0], w_re[1]),  pk(w_re[2], w_re[3])};
    u64 w2im[2]  = {pk(w_im[0], w_im[1]),  pk(w_im[2], w_im[3])};
    u64 nw2im[2] = {pk(-w_im[0], -w_im[1]), pk(-w_im[2], -w_im[3])};
    u64 cf2re[2] = {pk(cf_re[0], cf_re[1]), pk(cf_re[2], cf_re[3])};
    u64 ncf2im[2]= {pk(-cf_im[0], -cf_im[1]), pk(-cf_im[2], -cf_im[3])};
    float Dh = Dp[layer * H + h];

    const float* Sp = g_S + ((((size_t)b * NC + c) * H + h) * 8 + li) * 8;
    float4 sa = ((const float4*)Sp)[0], sb = ((const float4*)Sp)[1];
    u64 s2re[2] = {pk(sa.x, sa.z), pk(sb.x, sb.z)};
    u64 s2im[2] = {pk(sa.y, sa.w), pk(sb.y, sb.w)};

    const float* xr = xin + ((size_t)b * LSEQ + (size_t)c * CL) * H + h0;
    size_t yb = ((size_t)b * LSEQ + (size_t)c * CL) * H + h0;

    u_t[0][lrow][lcol]     = xr[(size_t)lrow * H + lcol];
    u_t[0][lrow + 8][lcol] = xr[(size_t)(lrow + 8) * H + lcol];
    __syncthreads();

    for (int it = 0; it < CL / 16; it++) {
        int buf = it & 1, l0 = it * 16;
        float p0 = 0.f, p1 = 0.f;
        if (it + 1 < CL / 16) {
            p0 = xr[(size_t)(l0 + 16 + lrow) * H + lcol];
            p1 = xr[(size_t)(l0 + 24 + lrow) * H + lcol];
        }
        float yl0 = 0.f, yl1 = 0.f;
#pragma unroll
        for (int k = 0; k < 16; k++) {
            float u = u_t[buf][k][hloc];
            u64 u2 = pk(u, u);
            u64 nre0 = fma2(w2re[0], s2re[0], fma2(nw2im[0], s2im[0], u2));
            u64 nim0 = fma2(w2im[0], s2re[0], mul2(w2re[0], s2im[0]));
            s2re[0] = nre0; s2im[0] = nim0;
            u64 c2 = mul2(cf2re[0], nre0);
            c2 = fma2(ncf2im[0], nim0, c2);
            u64 nre1 = fma2(w2re[1], s2re[1], fma2(nw2im[1], s2im[1], u2));
            u64 nim1 = fma2(w2im[1], s2re[1], mul2(w2re[1], s2im[1]));
            s2re[1] = nre1; s2im[1] = nim1;
            c2 = fma2(cf2re[1], nre1, c2);
            c2 = fma2(ncf2im[1], nim1, c2);
            float clo, chi; upk(c2, clo, chi);
            float cc = clo + chi;
            cc += __shfl_xor_sync(0xffffffffu, cc, 1);
            cc += __shfl_xor_sync(0xffffffffu, cc, 2);
            cc += __shfl_xor_sync(0xffffffffu, cc, 4);
            cc = fmaf(Dh, u, cc);
            if ((k & 7) == li) { if (k < 8) yl0 = cc; else yl1 = cc; }
        }
        yl0 = 0.5f * yl0 * (1.0f + erff(yl0 * 0.70710678118654752f));
        yl1 = 0.5f * yl1 * (1.0f + erff(yl1 * 0.70710678118654752f));
        y_t[buf][li][hloc] = yl0;
        y_t[buf][li + 8][hloc] = yl1;
        if (it + 1 < CL / 16) {
            u_t[buf ^ 1][lrow][lcol] = p0;
            u_t[buf ^ 1][lrow + 8][lcol] = p1;
        }
        __syncthreads();
        float v0 = y_t[buf][lrow][lcol];
        float v1 = y_t[buf][lrow + 8][lcol];
        size_t r0i = yb + (size_t)(l0 + lrow) * H + lcol;
        size_t r1i = r0i + 8 * H;
        __nv_bfloat16 h0b = __float2bfloat16(v0);
        g_Yhi[r0i] = h0b;
        g_Ymid[r0i] = __float2bfloat16(v0 - __bfloat162float(h0b));
        __nv_bfloat16 h1b = __float2bfloat16(v1);
        g_Yhi[r1i] = h1b;
        g_Ymid[r1i] = __float2bfloat16(v1 - __bfloat162float(h1b));
    }
}

// =====================================================================
// W prep: interleave rows (2i <- a-row i, 2i+1 <- g-row i+H) and split
// into bf16 hi/mid planes. Also interleave bias.
// =====================================================================
__global__ __launch_bounds__(256) void w_prep(const float* __restrict__ W,
                                              const float* __restrict__ bp) {
    size_t i = (size_t)blockIdx.x * 256 + threadIdx.x;   // over NLAY*2H*H
    int col = (int)(i % H);
    int k   = (int)((i / H) % (2 * H));
    int l   = (int)(i / ((size_t)H * 2 * H));
    int orig = (k >> 1) + (k & 1) * H;
    float v = W[((size_t)l * 2 * H + orig) * H + col];
    __nv_bfloat16 hi = __float2bfloat16(v);
    g_Whi[i] = hi;
    g_Wmid[i] = __float2bfloat16(v - __bfloat162float(hi));
    if (i < NLAY * 2 * H) {
        int kk = (int)(i % (2 * H));
        int ll = (int)(i / (2 * H));
        int og = (kk >> 1) + (kk & 1) * H;
        g_bint[i] = bp[ll * 2 * H + og];
    }
}

// =====================================================================
// GEMM + fused GLU: bf16 3-term split on mma.sync m16n8k16.
// CTA tile 128x128, K-tile 16, 3-stage cp.async (72KB dynamic smem),
// one __syncthreads per ktile. ldmatrix.x4 fragment loads.
// =====================================================================
#define PLANE 6144u            /* 128 rows * 48B */
#define BOFF  12288u           /* B planes start */
#define STAGE 24576u
#define GEMM_DSMEM (3 * STAGE)  /* 73728 */

__device__ __forceinline__ void mma_bf16(float* d, const uint32_t* a,
                                         uint32_t b0, uint32_t b1) {
    asm volatile(
        "mma.sync.aligned.m16n8k16.row.col.f32.bf16.bf16.f32 "
        "{%0,%1,%2,%3}, {%4,%5,%6,%7}, {%8,%9}, {%0,%1,%2,%3};"
        : "+f"(d[0]), "+f"(d[1]), "+f"(d[2]), "+f"(d[3])
        : "r"(a[0]), "r"(a[1]), "r"(a[2]), "r"(a[3]), "r"(b0), "r"(b1));
}

__global__ __launch_bounds__(256, 2) void conv_gemm(int layer)
{
    extern __shared__ __align__(16) char dsm[];

    int tid = threadIdx.x;
    int warp = tid >> 5, lane = tid & 31;
    int grp = lane >> 2, tq = lane & 3;
    int n0 = blockIdx.x * 128, m0 = blockIdx.y * 128;

    const __nv_bfloat16* Wh = g_Whi  + (size_t)layer * 2 * H * H;
    const __nv_bfloat16* Wm = g_Wmid + (size_t)layer * 2 * H * H;

    int wm = (warp >> 1) * 32, wn = (warp & 1) * 64;
    // ldmatrix per-lane offsets: row-within-16 and k-half
    int lrow8 = (lane & 7) + (lane & 8);
    int khalf = (lane >> 4) * 16;

    float acc[2][8][4];
#pragma unroll
    for (int mi = 0; mi < 2; mi++)
#pragma unroll
        for (int ni = 0; ni < 8; ni++)
#pragma unroll
            for (int r = 0; r < 4; r++) acc[mi][ni][r] = 0.0f;

    int fr = tid >> 1, fch = tid & 1;   // 256 threads = 128 rows x 2 chunks

#define LOAD_STAGE(KT, S)                                                        \
    do {                                                                         \
        char* sb = dsm + (unsigned)(S) * STAGE + (unsigned)(fr * 48 + fch * 16); \
        size_t soA = (size_t)(m0 + fr) * H + (KT) * 16 + fch * 8;                \
        size_t soB = (size_t)(n0 + fr) * H + (KT) * 16 + fch * 8;                \
        cpa16(sb,                g_Yhi + soA);                                   \
        cpa16(sb + PLANE,        g_Ymid + soA);                                  \
        cpa16(sb + BOFF,         Wh + soB);                                      \
        cpa16(sb + BOFF + PLANE, Wm + soB);                                      \
        asm volatile("cp.async.commit_group;" ::: "memory");                     \
    } while (0)

    LOAD_STAGE(0, 0);
    LOAD_STAGE(1, 1);

    const int NKT = H / 16;   // 32
    for (int kt = 0; kt < NKT; kt++) {
        int s = kt - (kt / 3) * 3;   // kt % 3
        if (kt + 2 < NKT) asm volatile("cp.async.wait_group 1;" ::: "memory");
        else              asm volatile("cp.async.wait_group 0;" ::: "memory");
        __syncthreads();
        if (kt + 2 < NKT) {
            int s2 = (kt + 2) - ((kt + 2) / 3) * 3;
            LOAD_STAGE(kt + 2, s2);
        }

        const char* sb = dsm + (unsigned)s * STAGE;
        uint32_t ah[2][4], am[2][4];
#pragma unroll
        for (int mi = 0; mi < 2; mi++) {
            const char* pa = sb + (unsigned)((wm + mi * 16 + lrow8) * 48) + khalf;
            ldsm4(ah[mi][0], ah[mi][1], ah[mi][2], ah[mi][3], pa);
            ldsm4(am[mi][0], am[mi][1], am[mi][2], am[mi][3], pa + PLANE);
        }
        uint32_t bh[8][2], bm[8][2];
#pragma unroll
        for (int p = 0; p < 4; p++) {
            const char* pb = sb + BOFF + (unsigned)((wn + p * 16 + lrow8) * 48) + khalf;
            // x4 delivers (b0 of ni, b0 of ni+1, b1 of ni, b1 of ni+1)
            ldsm4(bh[2 * p][0], bh[2 * p + 1][0], bh[2 * p][1], bh[2 * p + 1][1], pb);
            ldsm4(bm[2 * p][0], bm[2 * p + 1][0], bm[2 * p][1], bm[2 * p + 1][1],
                  pb + PLANE);
        }
#pragma unroll
        for (int ni = 0; ni < 8; ni++) {
#pragma unroll
            for (int mi = 0; mi < 2; mi++) {
                mma_bf16(acc[mi][ni], ah[mi], bh[ni][0], bh[ni][1]);
                mma_bf16(acc[mi][ni], am[mi], bh[ni][0], bh[ni][1]);
                mma_bf16(acc[mi][ni], ah[mi], bm[ni][0], bm[ni][1]);
            }
        }
    }

    // epilogue: bias + GLU, store a*sigmoid(g) to g_Z (h-index = col/2)
#pragma unroll
    for (int mi = 0; mi < 2; mi++)
#pragma unroll
        for (int ni = 0; ni < 8; ni++) {
            int r  = m0 + wm + mi * 16 + grp;
            int cb = wn + ni * 8 + tq * 2;
            float ba = g_bint[layer * 2 * H + n0 + cb];
            float bg = g_bint[layer * 2 * H + n0 + cb + 1];
            float a0 = acc[mi][ni][0] + ba, gg0 = acc[mi][ni][1] + bg;
            float a1 = acc[mi][ni][2] + ba, gg1 = acc[mi][ni][3] + bg;
            int hidx = (n0 + cb) >> 1;
            g_Z[(size_t)r * H + hidx]       = a0 / (1.0f + expf(-gg0));
            g_Z[(size_t)(r + 8) * H + hidx] = a1 / (1.0f + expf(-gg1));
        }
}

// =====================================================================
// Residual + LayerNorm. warp per row (512 contiguous floats).
// =====================================================================
__global__ __launch_bounds__(128) void res_ln(
    const float* __restrict__ xin, float* __restrict__ xout,
    const float* __restrict__ gamma, const float* __restrict__ beta, int layer)
{
    int row  = blockIdx.x * 4 + (threadIdx.x >> 5);
    int lane = threadIdx.x & 31;
    const float4* z4 = (const float4*)(g_Z + (size_t)row * H);
    const float4* x4 = (const float4*)(xin + (size_t)row * H);
    float4* o4       = (float4*)(xout + (size_t)row * H);
    const float4* g4 = (const float4*)(gamma + layer * H);
    const float4* e4 = (const float4*)(beta + layer * H);

    float4 v[4];
    float s = 0.0f, s2 = 0.0f;
#pragma unroll
    for (int j = 0; j < 4; j++) {
        float4 zz = z4[j * 32 + lane];
        float4 xv = x4[j * 32 + lane];
        float4 vv;
        vv.x = zz.x + xv.x; vv.y = zz.y + xv.y;
        vv.z = zz.z + xv.z; vv.w = zz.w + xv.w;
        v[j] = vv;
        s += vv.x + vv.y + vv.z + vv.w;
        s2 = fmaf(vv.x, vv.x, s2); s2 = fmaf(vv.y, vv.y, s2);
        s2 = fmaf(vv.z, vv.z, s2); s2 = fmaf(vv.w, vv.w, s2);
    }
#pragma unroll
    for (int o = 16; o; o >>= 1) {
        s  += __shfl_xor_sync(0xffffffffu, s, o);
        s2 += __shfl_xor_sync(0xffffffffu, s2, o);
    }
    float mu = s * (1.0f / H);
    float rs = rsqrtf(s2 * (1.0f / H) - mu * mu + LN_EPS);
#pragma unroll
    for (int j = 0; j < 4; j++) {
        float4 ga = g4[j * 32 + lane];
        float4 be = e4[j * 32 + lane];
        float4 vv = v[j], o;
        o.x = (vv.x - mu) * rs * ga.x + be.x;
        o.y = (vv.y - mu) * rs * ga.y + be.y;
        o.z = (vv.z - mu) * rs * ga.z + be.z;
        o.w = (vv.w - mu) * rs * ga.w + be.w;
        o4[j * 32 + lane] = o;
    }
}

// ================= launcher =================
extern "C" void kernel_launch(void* const* d_in, const int* in_sizes, int n_in,
                              void* d_out, int out_size)
{
    const float* x          = (const float*)d_in[0];
    const float* log_dt     = (const float*)d_in[1];
    const float* A_imag     = (const float*)d_in[2];
    const float* log_A_real = (const float*)d_in[3];
    const float* C          = (const float*)d_in[4];
    const float* D          = (const float*)d_in[5];
    const float* W          = (const float*)d_in[6];
    const float* bconv      = (const float*)d_in[7];
    const float* gamma      = (const float*)d_in[8];
    const float* beta       = (const float*)d_in[9];
    float* out = (float*)d_out;

    cudaFuncSetAttribute(conv_gemm, cudaFuncAttributeMaxDynamicSharedMemorySize,
                         GEMM_DSMEM);

    float* pA; cudaGetSymbolAddress((void**)&pA, g_xA);
    float* pB; cudaGetSymbolAddress((void**)&pB, g_xB);
    const float* xin[NLAY]  = {x,  pA, pB, pA};
    float*       xout[NLAY] = {pA, pB, pA, out};

    w_prep<<<(NLAY * 2 * H * H) / 256, 256>>>(W, bconv);

    for (int i = 0; i < NLAY; i++) {
        ssm_pass1<<<dim3(BSZ * (H / 32), NC), 256>>>(xin[i], log_dt, A_imag, log_A_real, i);
        ssm_prefix<<<BSZ * H * 8 / 256, 256>>>(log_dt, A_imag, log_A_real, i);
        ssm_pass3<<<dim3(BSZ * (H / 32), NC), 256>>>(xin[i], log_dt, A_imag, log_A_real,
                                                     C, D, i);
        conv_gemm<<<dim3(2 * H / 128, MROWS / 128), 256, GEMM_DSMEM>>>(i);
        res_ln<<<MROWS / 4, 128>>>(xin[i], xout[i], gamma, beta, i);
    }
}

// round 9
// speedup vs baseline: 1.0683x; 1.0683x over previous
#include <cuda_runtime.h>
#include <cuda_bf16.h>
#include <cstdint>

#define H     512
#define NLAY  4
#define N2    32
#define BSZ   8
#define LSEQ  4096
#define MROWS (BSZ * LSEQ)      /* 32768 */
#define NC    32                /* chunks per sequence */
#define CL    (LSEQ / NC)       /* 128 */
#define NINST (BSZ * NC)        /* 256 instances per h */
#define LN_EPS 1e-5f

// ---- static scratch. activations (B,L,H) row-major unless noted ----
__device__ __align__(256) float g_xA[(size_t)MROWS * H];
__device__ __align__(256) float g_xB[(size_t)MROWS * H];
__device__ __align__(256) __nv_bfloat16 g_Uhi [(size_t)MROWS * H];   // u (B,H,L)
__device__ __align__(256) __nv_bfloat16 g_Umid[(size_t)MROWS * H];
__device__ __align__(256) __nv_bfloat16 g_Yhi [(size_t)MROWS * H];   // gelu(y) (B,L,H)
__device__ __align__(256) __nv_bfloat16 g_Ymid[(size_t)MROWS * H];
__device__ __align__(256) float g_Yt[(size_t)MROWS * H];             // raw y (B,H,L)
__device__ __align__(256) __nv_bfloat16 g_Whi [(size_t)NLAY * 2 * H * H];
__device__ __align__(256) __nv_bfloat16 g_Wmid[(size_t)NLAY * 2 * H * H];
__device__ __align__(256) float g_bint[NLAY * 2 * H];
__device__ __align__(256) float g_Z[(size_t)MROWS * H];              // GLU out (B,L,H)
// Toeplitz machinery (per-layer rebuilt)
__device__ __align__(256) __nv_bfloat16 g_T2hi [(size_t)H * CL * 192];  // B2 [h][n=l][k]
__device__ __align__(256) __nv_bfloat16 g_T2mid[(size_t)H * CL * 192];
__device__ __align__(256) __nv_bfloat16 g_T1hi [(size_t)H * 64 * CL];   // B1 [h][e][j]
__device__ __align__(256) __nv_bfloat16 g_T1mid[(size_t)H * 64 * CL];
__device__ __align__(256) float g_E2[(size_t)H * NINST * 64];           // end states
__device__ __align__(256) __nv_bfloat16 g_Shi [(size_t)H * NINST * 64]; // init states
__device__ __align__(256) __nv_bfloat16 g_Smid[(size_t)H * NINST * 64];

// ---------------- helpers ----------------
__device__ __forceinline__ void cpa16(void* dst, const void* src) {
    unsigned d = (unsigned)__cvta_generic_to_shared(dst);
    asm volatile("cp.async.cg.shared.global [%0], [%1], 16;" :: "r"(d), "l"(src));
}
__device__ __forceinline__ void ldsm4(uint32_t& r0, uint32_t& r1, uint32_t& r2,
                                      uint32_t& r3, const void* p) {
    uint32_t a = (uint32_t)__cvta_generic_to_shared(p);
    asm volatile("ldmatrix.sync.aligned.m8n8.x4.shared.b16 {%0,%1,%2,%3}, [%4];"
                 : "=r"(r0), "=r"(r1), "=r"(r2), "=r"(r3) : "r"(a));
}
__device__ __forceinline__ void mma_bf16(float* d, const uint32_t* a,
                                         uint32_t b0, uint32_t b1) {
    asm volatile(
        "mma.sync.aligned.m16n8k16.row.col.f32.bf16.bf16.f32 "
        "{%0,%1,%2,%3}, {%4,%5,%6,%7}, {%8,%9}, {%0,%1,%2,%3};"
        : "+f"(d[0]), "+f"(d[1]), "+f"(d[2]), "+f"(d[3])
        : "r"(a[0]), "r"(a[1]), "r"(a[2]), "r"(a[3]), "r"(b0), "r"(b1));
}
__device__ __forceinline__ void bsplit(float v, __nv_bfloat16* hi_p,
                                       __nv_bfloat16* mid_p) {
    __nv_bfloat16 hi = __float2bfloat16(v);
    *hi_p = hi;
    *mid_p = __float2bfloat16(v - __bfloat162float(hi));
}

// per-(h, li) coefficients: w = exp(dA), used by prefix
__device__ __forceinline__ void scan_coeffs(
    const float* log_dt, const float* A_imag, const float* log_A_real,
    int layer, int h, int li, float* Are_o, float* Aim_o, float* dt_o)
{
    float dt = expf(log_dt[layer * H + h]);
    int pbase = (layer * H + h) * N2 + li * 4;
    float4 aim = *(const float4*)(A_imag + pbase);
    float4 lar = *(const float4*)(log_A_real + pbase);
    float aimv[4] = {aim.x, aim.y, aim.z, aim.w};
    float larv[4] = {lar.x, lar.y, lar.z, lar.w};
#pragma unroll
    for (int j = 0; j < 4; j++) {
        Are_o[j] = -expf(larv[j]);
        Aim_o[j] = aimv[j];
    }
    *dt_o = dt;
}

// =====================================================================
// xsplit: (B,L,H) fp32 -> (B,H,L) bf16 hi/mid
// =====================================================================
__global__ __launch_bounds__(256) void xsplit(const float* __restrict__ x) {
    __shared__ float tile[32][33];
    int b = blockIdx.z, h0 = blockIdx.x * 32, l0 = blockIdx.y * 32;
    int tx = threadIdx.x, ty = threadIdx.y;
#pragma unroll
    for (int j = 0; j < 32; j += 8)
        tile[ty + j][tx] = x[((size_t)b * LSEQ + l0 + ty + j) * H + h0 + tx];
    __syncthreads();
#pragma unroll
    for (int j = 0; j < 32; j += 8) {
        float v = tile[tx][ty + j];
        size_t o = ((size_t)(b * H + h0 + ty + j)) * LSEQ + l0 + tx;
        bsplit(v, g_Uhi + o, g_Umid + o);
    }
}

// =====================================================================
// tbuild: per-h Toeplitz kernel k[d], correction matrix V, end-state E.
// block per h (512 blocks x 256 thr).
// =====================================================================
__global__ __launch_bounds__(256) void tbuild(
    const float* __restrict__ log_dt, const float* __restrict__ A_imag,
    const float* __restrict__ log_A_real, const float* __restrict__ Cp,
    const float* __restrict__ Dp, int layer)
{
    __shared__ float wr[CL + 1][32], wi[CL + 1][32];
    __shared__ float scfr[32], scfi[32], skern[CL];
    __shared__ float sD;
    int h = blockIdx.x;
    int t = threadIdx.x;
    if (t == 0) sD = Dp[layer * H + h];
    if (t < 32) {
        int n = t;
        float dt = expf(log_dt[layer * H + h]);
        float Are = -expf(log_A_real[(layer * H + h) * N2 + n]);
        float Aim = A_imag[(layer * H + h) * N2 + n];
        float e1 = expf(Are * dt);
        float w1r = e1 * cosf(Aim * dt), w1i = e1 * sinf(Aim * dt);
        float nr = w1r - 1.0f, ni = w1i;
        float cr = Cp[((layer * H + h) * N2 + n) * 2 + 0];
        float ci = Cp[((layer * H + h) * N2 + n) * 2 + 1];
        float tr = cr * nr - ci * ni;
        float ti = cr * ni + ci * nr;
        float inv = 2.0f / (Are * Are + Aim * Aim);
        scfr[n] = (tr * Are + ti * Aim) * inv;
        scfi[n] = (ti * Are - tr * Aim) * inv;
        float pr = 1.0f, pi = 0.0f;
        for (int d = 0; d <= CL; d++) {
            wr[d][n] = pr; wi[d][n] = pi;
            float npr = pr * w1r - pi * w1i;
            float npi = pr * w1i + pi * w1r;
            pr = npr; pi = npi;
        }
    }
    __syncthreads();
    if (t < CL) {
        float acc = (t == 0) ? sD : 0.0f;
#pragma unroll 8
        for (int n = 0; n < 32; n++)
            acc += scfr[n] * wr[t][n] - scfi[n] * wi[t][n];
        skern[t] = acc;
    }
    __syncthreads();
    // B2 Toeplitz region [n=l][k<128]: T[n,k] = k<=n ? kern[n-k] : 0
    for (int idx = t; idx < CL * CL; idx += 256) {
        int n = idx >> 7, k = idx & 127;
        float v = (k <= n) ? skern[n - k] : 0.0f;
        size_t o = ((size_t)h * CL + n) * 192 + k;
        bsplit(v, g_T2hi + o, g_T2mid + o);
    }
    // B2 V region [n=l][128+e]: corr = Re(cf w^{l+1} s_init)
    for (int idx = t; idx < CL * 64; idx += 256) {
        int n = idx >> 6, e = idx & 63, ns = e >> 1;
        float cwr = scfr[ns] * wr[n + 1][ns] - scfi[ns] * wi[n + 1][ns];
        float cwi = scfr[ns] * wi[n + 1][ns] + scfi[ns] * wr[n + 1][ns];
        float v = (e & 1) ? -cwi : cwr;
        size_t o = ((size_t)h * CL + n) * 192 + 128 + e;
        bsplit(v, g_T2hi + o, g_T2mid + o);
    }
    // B1 end-state matrix [e][j]: s_end = sum_j w^{CL-1-j} u_j
    for (int idx = t; idx < 64 * CL; idx += 256) {
        int e = idx >> 7, j = idx & 127, ns = e >> 1;
        int d = CL - 1 - j;
        float v = (e & 1) ? wi[d][ns] : wr[d][ns];
        size_t o = ((size_t)h * 64 + e) * CL + j;
        bsplit(v, g_T1hi + o, g_T1mid + o);
    }
}

// =====================================================================
// gemm_end: per h, S_end[NINST x 64] = U[NINST x 128] @ B1^T. bf16 split-3.
// grid (2 mtiles, 512 h), 256 thr, tile 128x64, K=128.
// =====================================================================
#define E_PLANE 6144u
#define E_BOFF  12288u
#define E_BPLANE 3072u
#define E_STAGE 18432u
#define E_DSMEM (3 * E_STAGE)   /* 55296 */

__global__ __launch_bounds__(256, 2) void gemm_end()
{
    extern __shared__ __align__(16) char dsmE[];
    int tid = threadIdx.x;
    int warp = tid >> 5, lane = tid & 31;
    int grp = lane >> 2, tq = lane & 3;
    int mt = blockIdx.x, h = blockIdx.y;
    int wm = (warp >> 1) * 32, wn = (warp & 1) * 32;
    int lrow8 = (lane & 7) + (lane & 8);
    int khalf = (lane >> 4) * 16;

    int mloc = tid >> 1, ch = tid & 1;
    int m = mt * 128 + mloc;
    int bb = m >> 5, cc = m & 31;
    const __nv_bfloat16* aUh = g_Uhi  + ((size_t)(bb * H + h)) * LSEQ + cc * CL;
    const __nv_bfloat16* aUm = g_Umid + ((size_t)(bb * H + h)) * LSEQ + cc * CL;
    int frB = (tid & 127) >> 1, chB = tid & 1;
    const __nv_bfloat16* bTh = g_T1hi  + (size_t)h * 64 * CL;
    const __nv_bfloat16* bTm = g_T1mid + (size_t)h * 64 * CL;

    float acc[2][4][4];
#pragma unroll
    for (int mi = 0; mi < 2; mi++)
#pragma unroll
        for (int ni = 0; ni < 4; ni++)
#pragma unroll
            for (int r = 0; r < 4; r++) acc[mi][ni][r] = 0.0f;

#define LOAD_E(KT, S)                                                            \
    do {                                                                         \
        char* sb = dsmE + (unsigned)(S) * E_STAGE;                               \
        int k0 = (KT) * 16 + ch * 8;                                             \
        char* pa = sb + (unsigned)(mloc * 48 + ch * 16);                         \
        cpa16(pa,           aUh + k0);                                           \
        cpa16(pa + E_PLANE, aUm + k0);                                           \
        if (tid < 128) {                                                         \
            int kb = (KT) * 16 + chB * 8;                                        \
            char* pb = sb + E_BOFF + (unsigned)(frB * 48 + chB * 16);            \
            cpa16(pb,            bTh + (size_t)frB * CL + kb);                   \
            cpa16(pb + E_BPLANE, bTm + (size_t)frB * CL + kb);                   \
        }                                                                        \
        asm volatile("cp.async.commit_group;" ::: "memory");                     \
    } while (0)

    LOAD_E(0, 0);
    LOAD_E(1, 1);
    const int NKT = 8;
    for (int kt = 0; kt < NKT; kt++) {
        int s = kt - (kt / 3) * 3;
        if (kt + 2 < NKT) asm volatile("cp.async.wait_group 1;" ::: "memory");
        else              asm volatile("cp.async.wait_group 0;" ::: "memory");
        __syncthreads();
        if (kt + 2 < NKT) {
            int s2 = (kt + 2) - ((kt + 2) / 3) * 3;
            LOAD_E(kt + 2, s2);
        }
        const char* sb = dsmE + (unsigned)s * E_STAGE;
        uint32_t ah[2][4], am[2][4];
#pragma unroll
        for (int mi = 0; mi < 2; mi++) {
            const char* pa = sb + (unsigned)((wm + mi * 16 + lrow8) * 48) + khalf;
            ldsm4(ah[mi][0], ah[mi][1], ah[mi][2], ah[mi][3], pa);
            ldsm4(am[mi][0], am[mi][1], am[mi][2], am[mi][3], pa + E_PLANE);
        }
        uint32_t bh[4][2], bm[4][2];
#pragma unroll
        for (int p = 0; p < 2; p++) {
            const char* pb = sb + E_BOFF + (unsigned)((wn + p * 16 + lrow8) * 48) + khalf;
            ldsm4(bh[2 * p][0], bh[2 * p + 1][0], bh[2 * p][1], bh[2 * p + 1][1], pb);
            ldsm4(bm[2 * p][0], bm[2 * p + 1][0], bm[2 * p][1], bm[2 * p + 1][1],
                  pb + E_BPLANE);
        }
#pragma unroll
        for (int ni = 0; ni < 4; ni++)
#pragma unroll
            for (int mi = 0; mi < 2; mi++) {
                mma_bf16(acc[mi][ni], ah[mi], bh[ni][0], bh[ni][1]);
                mma_bf16(acc[mi][ni], am[mi], bh[ni][0], bh[ni][1]);
                mma_bf16(acc[mi][ni], ah[mi], bm[ni][0], bm[ni][1]);
            }
    }
#pragma unroll
    for (int mi = 0; mi < 2; mi++)
#pragma unroll
        for (int ni = 0; ni < 4; ni++) {
            int r = mt * 128 + wm + mi * 16 + grp;
            int n = wn + ni * 8 + tq * 2;
            float2 v0 = {acc[mi][ni][0], acc[mi][ni][1]};
            float2 v1 = {acc[mi][ni][2], acc[mi][ni][3]};
            *(float2*)&g_E2[((size_t)h * NINST + r) * 64 + n] = v0;
            *(float2*)&g_E2[((size_t)h * NINST + r + 8) * 64 + n] = v1;
        }
}

// =====================================================================
// prefix: combine chunk end states -> per-chunk init states (bf16 split)
// =====================================================================
__global__ __launch_bounds__(256) void ssm_prefix2(
    const float* __restrict__ log_dt, const float* __restrict__ A_imag,
    const float* __restrict__ log_A_real, int layer)
{
    int idx = blockIdx.x * 256 + threadIdx.x;   // 32768 = H*BSZ*8
    int li = idx & 7;
    int b  = (idx >> 3) & 7;
    int h  = idx >> 6;

    float Are[4], Aim[4], dt;
    scan_coeffs(log_dt, A_imag, log_A_real, layer, h, li, Are, Aim, &dt);
    float Wr[4], Wi[4];
#pragma unroll
    for (int j = 0; j < 4; j++) {                  // w^CL = exp(dA*CL)
        float e = expf(Are[j] * dt * (float)CL);
        Wr[j] = e * cosf(Aim[j] * dt * (float)CL);
        Wi[j] = e * sinf(Aim[j] * dt * (float)CL);
    }
    float Ire[4] = {0, 0, 0, 0}, Iim[4] = {0, 0, 0, 0};
    for (int c = 0; c < NC; c++) {
        size_t off = ((size_t)h * NINST + b * NC + c) * 64 + li * 8;
#pragma unroll
        for (int j = 0; j < 4; j++) {
            bsplit(Ire[j], g_Shi + off + 2 * j,     g_Smid + off + 2 * j);
            bsplit(Iim[j], g_Shi + off + 2 * j + 1, g_Smid + off + 2 * j + 1);
        }
        float4 e0 = *(const float4*)(g_E2 + off);
        float4 e1 = *(const float4*)(g_E2 + off + 4);
        float er[4] = {e0.x, e0.z, e1.x, e1.z};
        float ei[4] = {e0.y, e0.w, e1.y, e1.w};
#pragma unroll
        for (int j = 0; j < 4; j++) {
            float nr = fmaf(Wr[j], Ire[j], fmaf(-Wi[j], Iim[j], er[j]));
            float ni = fmaf(Wi[j], Ire[j], fmaf( Wr[j], Iim[j], ei[j]));
            Ire[j] = nr; Iim[j] = ni;
        }
    }
}

// =====================================================================
// gemm_toep: per h, Y[NINST x 128] = [U|Sinit][NINST x 192] @ B2^T.
// grid (2 mtiles, 512 h), 256 thr, tile 128x128, K=192 (12 ktiles).
// =====================================================================
#define PLANE 6144u
#define BOFF  12288u
#define STAGE 24576u
#define T_DSMEM (3 * STAGE)

__global__ __launch_bounds__(256, 2) void gemm_toep()
{
    extern __shared__ __align__(16) char dsmT[];
    int tid = threadIdx.x;
    int warp = tid >> 5, lane = tid & 31;
    int grp = lane >> 2, tq = lane & 3;
    int mt = blockIdx.x, h = blockIdx.y;
    int wm = (warp >> 1) * 32, wn = (warp & 1) * 64;
    int lrow8 = (lane & 7) + (lane & 8);
    int khalf = (lane >> 4) * 16;

    int mloc = tid >> 1, ch = tid & 1;
    int m = mt * 128 + mloc;
    int bb = m >> 5, cc = m & 31;
    const __nv_bfloat16* aUh = g_Uhi  + ((size_t)(bb * H + h)) * LSEQ + cc * CL;
    const __nv_bfloat16* aUm = g_Umid + ((size_t)(bb * H + h)) * LSEQ + cc * CL;
    const __nv_bfloat16* aSh = g_Shi  + ((size_t)h * NINST + m) * 64;
    const __nv_bfloat16* aSm = g_Smid + ((size_t)h * NINST + m) * 64;
    const __nv_bfloat16* bTh = g_T2hi  + (size_t)h * CL * 192;
    const __nv_bfloat16* bTm = g_T2mid + (size_t)h * CL * 192;

    float acc[2][8][4];
#pragma unroll
    for (int mi = 0; mi < 2; mi++)
#pragma unroll
        for (int ni = 0; ni < 8; ni++)
#pragma unroll
            for (int r = 0; r < 4; r++) acc[mi][ni][r] = 0.0f;

#define LOAD_T(KT, S)                                                            \
    do {                                                                         \
        char* sb = dsmT + (unsigned)(S) * STAGE;                                 \
        int k0 = (KT) * 16 + ch * 8;                                             \
        const __nv_bfloat16* sh = (k0 < 128) ? aUh + k0 : aSh + (k0 - 128);      \
        const __nv_bfloat16* sm = (k0 < 128) ? aUm + k0 : aSm + (k0 - 128);      \
        char* pa = sb + (unsigned)(mloc * 48 + ch * 16);                         \
        cpa16(pa,         sh);                                                   \
        cpa16(pa + PLANE, sm);                                                   \
        char* pb = sb + BOFF + (unsigned)(mloc * 48 + ch * 16);                  \
        cpa16(pb,         bTh + (size_t)mloc * 192 + k0);                        \
        cpa16(pb + PLANE, bTm + (size_t)mloc * 192 + k0);                        \
        asm volatile("cp.async.commit_group;" ::: "memory");                     \
    } while (0)

    LOAD_T(0, 0);
    LOAD_T(1, 1);
    const int NKT = 12;
    for (int kt = 0; kt < NKT; kt++) {
        int s = kt - (kt / 3) * 3;
        if (kt + 2 < NKT) asm volatile("cp.async.wait_group 1;" ::: "memory");
        else              asm volatile("cp.async.wait_group 0;" ::: "memory");
        __syncthreads();
        if (kt + 2 < NKT) {
            int s2 = (kt + 2) - ((kt + 2) / 3) * 3;
            LOAD_T(kt + 2, s2);
        }
        const char* sb = dsmT + (unsigned)s * STAGE;
        uint32_t ah[2][4], am[2][4];
#pragma unroll
        for (int mi = 0; mi < 2; mi++) {
            const char* pa = sb + (unsigned)((wm + mi * 16 + lrow8) * 48) + khalf;
            ldsm4(ah[mi][0], ah[mi][1], ah[mi][2], ah[mi][3], pa);
            ldsm4(am[mi][0], am[mi][1], am[mi][2], am[mi][3], pa + PLANE);
        }
        uint32_t bh[8][2], bm[8][2];
#pragma unroll
        for (int p = 0; p < 4; p++) {
            const char* pb = sb + BOFF + (unsigned)((wn + p * 16 + lrow8) * 48) + khalf;
            ldsm4(bh[2 * p][0], bh[2 * p + 1][0], bh[2 * p][1], bh[2 * p + 1][1], pb);
            ldsm4(bm[2 * p][0], bm[2 * p + 1][0], bm[2 * p][1], bm[2 * p + 1][1],
                  pb + PLANE);
        }
#pragma unroll
        for (int ni = 0; ni < 8; ni++)
#pragma unroll
            for (int mi = 0; mi < 2; mi++) {
                mma_bf16(acc[mi][ni], ah[mi], bh[ni][0], bh[ni][1]);
                mma_bf16(acc[mi][ni], am[mi], bh[ni][0], bh[ni][1]);
                mma_bf16(acc[mi][ni], ah[mi], bm[ni][0], bm[ni][1]);
            }
    }
    // store raw y (B,H,L)
#pragma unroll
    for (int mi = 0; mi < 2; mi++) {
        int r = mt * 128 + wm + mi * 16 + grp;
        int b0 = r >> 5, c0 = r & 31;
        int r1 = r + 8;
        int b1 = r1 >> 5, c1 = r1 & 31;
        float* y0 = g_Yt + ((size_t)(b0 * H + h)) * LSEQ + c0 * CL;
        float* y1 = g_Yt + ((size_t)(b1 * H + h)) * LSEQ + c1 * CL;
#pragma unroll
        for (int ni = 0; ni < 8; ni++) {
            int n = wn + ni * 8 + tq * 2;
            *(float2*)(y0 + n) = make_float2(acc[mi][ni][0], acc[mi][ni][1]);
            *(float2*)(y1 + n) = make_float2(acc[mi][ni][2], acc[mi][ni][3]);
        }
    }
}

// =====================================================================
// ytrans: (B,H,L) fp32 raw y -> GELU -> (B,L,H) bf16 hi/mid
// =====================================================================
__global__ __launch_bounds__(256) void ytrans() {
    __shared__ float tile[32][33];
    int b = blockIdx.z, h0 = blockIdx.y * 32, l0 = blockIdx.x * 32;
    int tx = threadIdx.x, ty = threadIdx.y;
#pragma unroll
    for (int j = 0; j < 32; j += 8)
        tile[ty + j][tx] = g_Yt[((size_t)(b * H + h0 + ty + j)) * LSEQ + l0 + tx];
    __syncthreads();
#pragma unroll
    for (int j = 0; j < 32; j += 8) {
        float v = tile[tx][ty + j];
        v = 0.5f * v * (1.0f + erff(v * 0.70710678118654752f));
        size_t o = ((size_t)b * LSEQ + l0 + ty + j) * H + h0 + tx;
        bsplit(v, g_Yhi + o, g_Ymid + o);
    }
}

// =====================================================================
// W prep: interleave rows (2i <- a-row i, 2i+1 <- g-row i+H), bf16 split.
// =====================================================================
__global__ __launch_bounds__(256) void w_prep(const float* __restrict__ W,
                                              const float* __restrict__ bp) {
    size_t i = (size_t)blockIdx.x * 256 + threadIdx.x;
    int col = (int)(i % H);
    int k   = (int)((i / H) % (2 * H));
    int l   = (int)(i / ((size_t)H * 2 * H));
    int orig = (k >> 1) + (k & 1) * H;
    float v = W[((size_t)l * 2 * H + orig) * H + col];
    bsplit(v, g_Whi + i, g_Wmid + i);
    if (i < NLAY * 2 * H) {
        int kk = (int)(i % (2 * H));
        int ll = (int)(i / (2 * H));
        int og = (kk >> 1) + (kk & 1) * H;
        g_bint[i] = bp[ll * 2 * H + og];
    }
}

// =====================================================================
// conv GEMM + fused GLU (unchanged from R8, validated)
// =====================================================================
__global__ __launch_bounds__(256, 2) void conv_gemm(int layer)
{
    extern __shared__ __align__(16) char dsm[];
    int tid = threadIdx.x;
    int warp = tid >> 5, lane = tid & 31;
    int grp = lane >> 2, tq = lane & 3;
    int n0 = blockIdx.x * 128, m0 = blockIdx.y * 128;

    const __nv_bfloat16* Wh = g_Whi  + (size_t)layer * 2 * H * H;
    const __nv_bfloat16* Wm = g_Wmid + (size_t)layer * 2 * H * H;

    int wm = (warp >> 1) * 32, wn = (warp & 1) * 64;
    int lrow8 = (lane & 7) + (lane & 8);
    int khalf = (lane >> 4) * 16;

    float acc[2][8][4];
#pragma unroll
    for (int mi = 0; mi < 2; mi++)
#pragma unroll
        for (int ni = 0; ni < 8; ni++)
#pragma unroll
            for (int r = 0; r < 4; r++) acc[mi][ni][r] = 0.0f;

    int fr = tid >> 1, fch = tid & 1;

#define LOAD_C(KT, S)                                                            \
    do {                                                                         \
        char* sb = dsm + (unsigned)(S) * STAGE + (unsigned)(fr * 48 + fch * 16); \
        size_t soA = (size_t)(m0 + fr) * H + (KT) * 16 + fch * 8;                \
        size_t soB = (size_t)(n0 + fr) * H + (KT) * 16 + fch * 8;                \
        cpa16(sb,                g_Yhi + soA);                                   \
        cpa16(sb + PLANE,        g_Ymid + soA);                                  \
        cpa16(sb + BOFF,         Wh + soB);                                      \
        cpa16(sb + BOFF + PLANE, Wm + soB);                                      \
        asm volatile("cp.async.commit_group;" ::: "memory");                     \
    } while (0)

    LOAD_C(0, 0);
    LOAD_C(1, 1);

    const int NKT = H / 16;   // 32
    for (int kt = 0; kt < NKT; kt++) {
        int s = kt - (kt / 3) * 3;
        if (kt + 2 < NKT) asm volatile("cp.async.wait_group 1;" ::: "memory");
        else              asm volatile("cp.async.wait_group 0;" ::: "memory");
        __syncthreads();
        if (kt + 2 < NKT) {
            int s2 = (kt + 2) - ((kt + 2) / 3) * 3;
            LOAD_C(kt + 2, s2);
        }
        const char* sb = dsm + (unsigned)s * STAGE;
        uint32_t ah[2][4], am[2][4];
#pragma unroll
        for (int mi = 0; mi < 2; mi++) {
            const char* pa = sb + (unsigned)((wm + mi * 16 + lrow8) * 48) + khalf;
            ldsm4(ah[mi][0], ah[mi][1], ah[mi][2], ah[mi][3], pa);
            ldsm4(am[mi][0], am[mi][1], am[mi][2], am[mi][3], pa + PLANE);
        }
        uint32_t bh[8][2], bm[8][2];
#pragma unroll
        for (int p = 0; p < 4; p++) {
            const char* pb = sb + BOFF + (unsigned)((wn + p * 16 + lrow8) * 48) + khalf;
            ldsm4(bh[2 * p][0], bh[2 * p + 1][0], bh[2 * p][1], bh[2 * p + 1][1], pb);
            ldsm4(bm[2 * p][0], bm[2 * p + 1][0], bm[2 * p][1], bm[2 * p + 1][1],
                  pb + PLANE);
        }
#pragma unroll
        for (int ni = 0; ni < 8; ni++)
#pragma unroll
            for (int mi = 0; mi < 2; mi++) {
                mma_bf16(acc[mi][ni], ah[mi], bh[ni][0], bh[ni][1]);
                mma_bf16(acc[mi][ni], am[mi], bh[ni][0], bh[ni][1]);
                mma_bf16(acc[mi][ni], ah[mi], bm[ni][0], bm[ni][1]);
            }
    }
#pragma unroll
    for (int mi = 0; mi < 2; mi++)
#pragma unroll
        for (int ni = 0; ni < 8; ni++) {
            int r  = m0 + wm + mi * 16 + grp;
            int cb = wn + ni * 8 + tq * 2;
            float ba = g_bint[layer * 2 * H + n0 + cb];
            float bg = g_bint[layer * 2 * H + n0 + cb + 1];
            float a0 = acc[mi][ni][0] + ba, gg0 = acc[mi][ni][1] + bg;
            float a1 = acc[mi][ni][2] + ba, gg1 = acc[mi][ni][3] + bg;
            int hidx = (n0 + cb) >> 1;
            g_Z[(size_t)r * H + hidx]       = a0 / (1.0f + expf(-gg0));
            g_Z[(size_t)(r + 8) * H + hidx] = a1 / (1.0f + expf(-gg1));
        }
}

// =====================================================================
// Residual + LayerNorm. warp per row.
// =====================================================================
__global__ __launch_bounds__(128) void res_ln(
    const float* __restrict__ xin, float* __restrict__ xout,
    const float* __restrict__ gamma, const float* __restrict__ beta, int layer)
{
    int row  = blockIdx.x * 4 + (threadIdx.x >> 5);
    int lane = threadIdx.x & 31;
    const float4* z4 = (const float4*)(g_Z + (size_t)row * H);
    const float4* x4 = (const float4*)(xin + (size_t)row * H);
    float4* o4       = (float4*)(xout + (size_t)row * H);
    const float4* g4 = (const float4*)(gamma + layer * H);
    const float4* e4 = (const float4*)(beta + layer * H);

    float4 v[4];
    float s = 0.0f, s2 = 0.0f;
#pragma unroll
    for (int j = 0; j < 4; j++) {
        float4 zz = z4[j * 32 + lane];
        float4 xv = x4[j * 32 + lane];
        float4 vv;
        vv.x = zz.x + xv.x; vv.y = zz.y + xv.y;
        vv.z = zz.z + xv.z; vv.w = zz.w + xv.w;
        v[j] = vv;
        s += vv.x + vv.y + vv.z + vv.w;
        s2 = fmaf(vv.x, vv.x, s2); s2 = fmaf(vv.y, vv.y, s2);
        s2 = fmaf(vv.z, vv.z, s2); s2 = fmaf(vv.w, vv.w, s2);
    }
#pragma unroll
    for (int o = 16; o; o >>= 1) {
        s  += __shfl_xor_sync(0xffffffffu, s, o);
        s2 += __shfl_xor_sync(0xffffffffu, s2, o);
    }
    float mu = s * (1.0f / H);
    float rs = rsqrtf(s2 * (1.0f / H) - mu * mu + LN_EPS);
#pragma unroll
    for (int j = 0; j < 4; j++) {
        float4 ga = g4[j * 32 + lane];
        float4 be = e4[j * 32 + lane];
        float4 vv = v[j], o;
        o.x = (vv.x - mu) * rs * ga.x + be.x;
        o.y = (vv.y - mu) * rs * ga.y + be.y;
        o.z = (vv.z - mu) * rs * ga.z + be.z;
        o.w = (vv.w - mu) * rs * ga.w + be.w;
        o4[j * 32 + lane] = o;
    }
}

// ================= launcher =================
extern "C" void kernel_launch(void* const* d_in, const int* in_sizes, int n_in,
                              void* d_out, int out_size)
{
    const float* x          = (const float*)d_in[0];
    const float* log_dt     = (const float*)d_in[1];
    const float* A_imag     = (const float*)d_in[2];
    const float* log_A_real = (const float*)d_in[3];
    const float* C          = (const float*)d_in[4];
    const float* D          = (const float*)d_in[5];
    const float* W          = (const float*)d_in[6];
    const float* bconv      = (const float*)d_in[7];
    const float* gamma      = (const float*)d_in[8];
    const float* beta       = (const float*)d_in[9];
    float* out = (float*)d_out;

    cudaFuncSetAttribute(conv_gemm, cudaFuncAttributeMaxDynamicSharedMemorySize,
                         T_DSMEM);
    cudaFuncSetAttribute(gemm_toep, cudaFuncAttributeMaxDynamicSharedMemorySize,
                         T_DSMEM);
    cudaFuncSetAttribute(gemm_end, cudaFuncAttributeMaxDynamicSharedMemorySize,
                         E_DSMEM);

    float* pA; cudaGetSymbolAddress((void**)&pA, g_xA);
    float* pB; cudaGetSymbolAddress((void**)&pB, g_xB);
    const float* xin[NLAY]  = {x,  pA, pB, pA};
    float*       xout[NLAY] = {pA, pB, pA, out};

    w_prep<<<(NLAY * 2 * H * H) / 256, 256>>>(W, bconv);

    dim3 tb(32, 8);
    for (int i = 0; i < NLAY; i++) {
        xsplit<<<dim3(H / 32, LSEQ / 32, BSZ), tb>>>(xin[i]);
        tbuild<<<H, 256>>>(log_dt, A_imag, log_A_real, C, D, i);
        gemm_end<<<dim3(2, H), 256, E_DSMEM>>>();
        ssm_prefix2<<<(H * BSZ * 8) / 256, 256>>>(log_dt, A_imag, log_A_real, i);
        gemm_toep<<<dim3(2, H), 256, T_DSMEM>>>();
        ytrans<<<dim3(LSEQ / 32, H / 32, BSZ), tb>>>();
        conv_gemm<<<dim3(2 * H / 128, MROWS / 128), 256, T_DSMEM>>>(i);
        res_ln<<<MROWS / 4, 128>>>(xin[i], xout[i], gamma, beta, i);
    }
}

// round 10
// speedup vs baseline: 1.2729x; 1.1915x over previous
#include <cuda_runtime.h>
#include <cuda_fp16.h>
#include <cstdint>

#define H     512
#define NLAY  4
#define N2    32
#define BSZ   8
#define LSEQ  4096
#define MROWS (BSZ * LSEQ)      /* 32768 */
#define NC    32                /* chunks per sequence */
#define CL    (LSEQ / NC)       /* 128 */
#define NINST (BSZ * NC)        /* 256 instances per h */
#define LN_EPS 1e-5f

// ---- static scratch. activations (B,L,H) row-major unless noted ----
__device__ __align__(256) float g_xA[(size_t)MROWS * H];
__device__ __align__(256) float g_xB[(size_t)MROWS * H];
__device__ __align__(256) __half g_Uhi [(size_t)MROWS * H];   // u (B,H,L)
__device__ __align__(256) __half g_Umid[(size_t)MROWS * H];
__device__ __align__(256) __half g_Yhi [(size_t)MROWS * H];   // gelu(y) (B,L,H)
__device__ __align__(256) __half g_Ymid[(size_t)MROWS * H];
__device__ __align__(256) float g_Yt[(size_t)MROWS * H];      // raw y (B,H,L)
__device__ __align__(256) __half g_Whi[(size_t)NLAY * 2 * H * H];
__device__ __align__(256) float g_bint[NLAY * 2 * H];
__device__ __align__(256) float g_Z[(size_t)MROWS * H];       // GLU out (B,L,H)
// Toeplitz machinery (per-layer rebuilt)
__device__ __align__(256) __half g_T2hi [(size_t)H * CL * 192];  // B2 [h][n=l][k]
__device__ __align__(256) __half g_T2mid[(size_t)H * CL * 192];
__device__ __align__(256) __half g_T1hi [(size_t)H * 64 * CL];   // B1 [h][e][j]
__device__ __align__(256) __half g_T1mid[(size_t)H * 64 * CL];
__device__ __align__(256) float g_E2[(size_t)H * NINST * 64];    // end states
__device__ __align__(256) __half g_Shi [(size_t)H * NINST * 64]; // init states
__device__ __align__(256) __half g_Smid[(size_t)H * NINST * 64];

// ---------------- helpers ----------------
__device__ __forceinline__ void cpa16(void* dst, const void* src) {
    unsigned d = (unsigned)__cvta_generic_to_shared(dst);
    asm volatile("cp.async.cg.shared.global [%0], [%1], 16;" :: "r"(d), "l"(src));
}
__device__ __forceinline__ void ldsm4(uint32_t& r0, uint32_t& r1, uint32_t& r2,
                                      uint32_t& r3, const void* p) {
    uint32_t a = (uint32_t)__cvta_generic_to_shared(p);
    asm volatile("ldmatrix.sync.aligned.m8n8.x4.shared.b16 {%0,%1,%2,%3}, [%4];"
                 : "=r"(r0), "=r"(r1), "=r"(r2), "=r"(r3) : "r"(a));
}
__device__ __forceinline__ void mma_f16(float* d, const uint32_t* a,
                                        uint32_t b0, uint32_t b1) {
    asm volatile(
        "mma.sync.aligned.m16n8k16.row.col.f32.f16.f16.f32 "
        "{%0,%1,%2,%3}, {%4,%5,%6,%7}, {%8,%9}, {%0,%1,%2,%3};"
        : "+f"(d[0]), "+f"(d[1]), "+f"(d[2]), "+f"(d[3])
        : "r"(a[0]), "r"(a[1]), "r"(a[2]), "r"(a[3]), "r"(b0), "r"(b1));
}
__device__ __forceinline__ void hsplit(float v, __half* hi_p, __half* mid_p) {
    __half hi = __float2half_rn(v);
    *hi_p = hi;
    *mid_p = __float2half_rn(v - __half2float(hi));
}

__device__ __forceinline__ void scan_coeffs(
    const float* log_dt, const float* A_imag, const float* log_A_real,
    int layer, int h, int li, float* Are_o, float* Aim_o, float* dt_o)
{
    float dt = expf(log_dt[layer * H + h]);
    int pbase = (layer * H + h) * N2 + li * 4;
    float4 aim = *(const float4*)(A_imag + pbase);
    float4 lar = *(const float4*)(log_A_real + pbase);
    float aimv[4] = {aim.x, aim.y, aim.z, aim.w};
    float larv[4] = {lar.x, lar.y, lar.z, lar.w};
#pragma unroll
    for (int j = 0; j < 4; j++) {
        Are_o[j] = -expf(larv[j]);
        Aim_o[j] = aimv[j];
    }
    *dt_o = dt;
}

// =====================================================================
// xsplit: (B,L,H) fp32 -> (B,H,L) fp16 hi/mid
// =====================================================================
__global__ __launch_bounds__(256) void xsplit(const float* __restrict__ x) {
    __shared__ float tile[32][33];
    int b = blockIdx.z, h0 = blockIdx.x * 32, l0 = blockIdx.y * 32;
    int tx = threadIdx.x, ty = threadIdx.y;
#pragma unroll
    for (int j = 0; j < 32; j += 8)
        tile[ty + j][tx] = x[((size_t)b * LSEQ + l0 + ty + j) * H + h0 + tx];
    __syncthreads();
#pragma unroll
    for (int j = 0; j < 32; j += 8) {
        float v = tile[tx][ty + j];
        size_t o = ((size_t)(b * H + h0 + ty + j)) * LSEQ + l0 + tx;
        hsplit(v, g_Uhi + o, g_Umid + o);
    }
}

// =====================================================================
// tbuild: per-h Toeplitz kernel k[d], correction matrix V, end-state E.
// =====================================================================
__global__ __launch_bounds__(256) void tbuild(
    const float* __restrict__ log_dt, const float* __restrict__ A_imag,
    const float* __restrict__ log_A_real, const float* __restrict__ Cp,
    const float* __restrict__ Dp, int layer)
{
    __shared__ float wr[CL + 1][32], wi[CL + 1][32];
    __shared__ float scfr[32], scfi[32], skern[CL];
    __shared__ float sD;
    int h = blockIdx.x;
    int t = threadIdx.x;
    if (t == 0) sD = Dp[layer * H + h];
    if (t < 32) {
        int n = t;
        float dt = expf(log_dt[layer * H + h]);
        float Are = -expf(log_A_real[(layer * H + h) * N2 + n]);
        float Aim = A_imag[(layer * H + h) * N2 + n];
        float e1 = expf(Are * dt);
        float w1r = e1 * cosf(Aim * dt), w1i = e1 * sinf(Aim * dt);
        float nr = w1r - 1.0f, ni = w1i;
        float cr = Cp[((layer * H + h) * N2 + n) * 2 + 0];
        float ci = Cp[((layer * H + h) * N2 + n) * 2 + 1];
        float tr = cr * nr - ci * ni;
        float ti = cr * ni + ci * nr;
        float inv = 2.0f / (Are * Are + Aim * Aim);
        scfr[n] = (tr * Are + ti * Aim) * inv;
        scfi[n] = (ti * Are - tr * Aim) * inv;
        float pr = 1.0f, pi = 0.0f;
        for (int d = 0; d <= CL; d++) {
            wr[d][n] = pr; wi[d][n] = pi;
            float npr = pr * w1r - pi * w1i;
            float npi = pr * w1i + pi * w1r;
            pr = npr; pi = npi;
        }
    }
    __syncthreads();
    if (t < CL) {
        float acc = (t == 0) ? sD : 0.0f;
#pragma unroll 8
        for (int n = 0; n < 32; n++)
            acc += scfr[n] * wr[t][n] - scfi[n] * wi[t][n];
        skern[t] = acc;
    }
    __syncthreads();
    for (int idx = t; idx < CL * CL; idx += 256) {
        int n = idx >> 7, k = idx & 127;
        float v = (k <= n) ? skern[n - k] : 0.0f;
        size_t o = ((size_t)h * CL + n) * 192 + k;
        hsplit(v, g_T2hi + o, g_T2mid + o);
    }
    for (int idx = t; idx < CL * 64; idx += 256) {
        int n = idx >> 6, e = idx & 63, ns = e >> 1;
        float cwr = scfr[ns] * wr[n + 1][ns] - scfi[ns] * wi[n + 1][ns];
        float cwi = scfr[ns] * wi[n + 1][ns] + scfi[ns] * wr[n + 1][ns];
        float v = (e & 1) ? -cwi : cwr;
        size_t o = ((size_t)h * CL + n) * 192 + 128 + e;
        hsplit(v, g_T2hi + o, g_T2mid + o);
    }
    for (int idx = t; idx < 64 * CL; idx += 256) {
        int e = idx >> 7, j = idx & 127, ns = e >> 1;
        int d = CL - 1 - j;
        float v = (e & 1) ? wi[d][ns] : wr[d][ns];
        size_t o = ((size_t)h * 64 + e) * CL + j;
        hsplit(v, g_T1hi + o, g_T1mid + o);
    }
}

// =====================================================================
// gemm_end: per h, S_end[NINST x 64] = U[NINST x 128] @ B1^T. fp16 3-term.
// =====================================================================
#define E_PLANE 6144u
#define E_BOFF  12288u
#define E_BPLANE 3072u
#define E_STAGE 18432u
#define E_DSMEM (3 * E_STAGE)

__global__ __launch_bounds__(256, 2) void gemm_end()
{
    extern __shared__ __align__(16) char dsmE[];
    int tid = threadIdx.x;
    int warp = tid >> 5, lane = tid & 31;
    int grp = lane >> 2, tq = lane & 3;
    int mt = blockIdx.x, h = blockIdx.y;
    int wm = (warp >> 1) * 32, wn = (warp & 1) * 32;
    int lrow8 = (lane & 7) + (lane & 8);
    int khalf = (lane >> 4) * 16;

    int mloc = tid >> 1, ch = tid & 1;
    int m = mt * 128 + mloc;
    int bb = m >> 5, cc = m & 31;
    const __half* aUh = g_Uhi  + ((size_t)(bb * H + h)) * LSEQ + cc * CL;
    const __half* aUm = g_Umid + ((size_t)(bb * H + h)) * LSEQ + cc * CL;
    int frB = (tid & 127) >> 1, chB = tid & 1;
    const __half* bTh = g_T1hi  + (size_t)h * 64 * CL;
    const __half* bTm = g_T1mid + (size_t)h * 64 * CL;

    float acc[2][4][4];
#pragma unroll
    for (int mi = 0; mi < 2; mi++)
#pragma unroll
        for (int ni = 0; ni < 4; ni++)
#pragma unroll
            for (int r = 0; r < 4; r++) acc[mi][ni][r] = 0.0f;

#define LOAD_E(KT, S)                                                            \
    do {                                                                         \
        char* sb = dsmE + (unsigned)(S) * E_STAGE;                               \
        int k0 = (KT) * 16 + ch * 8;                                             \
        char* pa = sb + (unsigned)(mloc * 48 + ch * 16);                         \
        cpa16(pa,           aUh + k0);                                           \
        cpa16(pa + E_PLANE, aUm + k0);                                           \
        if (tid < 128) {                                                         \
            int kb = (KT) * 16 + chB * 8;                                        \
            char* pb = sb + E_BOFF + (unsigned)(frB * 48 + chB * 16);            \
            cpa16(pb,            bTh + (size_t)frB * CL + kb);                   \
            cpa16(pb + E_BPLANE, bTm + (size_t)frB * CL + kb);                   \
        }                                                                        \
        asm volatile("cp.async.commit_group;" ::: "memory");                     \
    } while (0)

    LOAD_E(0, 0);
    LOAD_E(1, 1);
    const int NKT = 8;
    for (int kt = 0; kt < NKT; kt++) {
        int s = kt - (kt / 3) * 3;
        if (kt + 2 < NKT) asm volatile("cp.async.wait_group 1;" ::: "memory");
        else              asm volatile("cp.async.wait_group 0;" ::: "memory");
        __syncthreads();
        if (kt + 2 < NKT) {
            int s2 = (kt + 2) - ((kt + 2) / 3) * 3;
            LOAD_E(kt + 2, s2);
        }
        const char* sb = dsmE + (unsigned)s * E_STAGE;
        uint32_t ah[2][4], am[2][4];
#pragma unroll
        for (int mi = 0; mi < 2; mi++) {
            const char* pa = sb + (unsigned)((wm + mi * 16 + lrow8) * 48) + khalf;
            ldsm4(ah[mi][0], ah[mi][1], ah[mi][2], ah[mi][3], pa);
            ldsm4(am[mi][0], am[mi][1], am[mi][2], am[mi][3], pa + E_PLANE);
        }
        uint32_t bh[4][2], bm[4][2];
#pragma unroll
        for (int p = 0; p < 2; p++) {
            const char* pb = sb + E_BOFF + (unsigned)((wn + p * 16 + lrow8) * 48) + khalf;
            ldsm4(bh[2 * p][0], bh[2 * p + 1][0], bh[2 * p][1], bh[2 * p + 1][1], pb);
            ldsm4(bm[2 * p][0], bm[2 * p + 1][0], bm[2 * p][1], bm[2 * p + 1][1],
                  pb + E_BPLANE);
        }
#pragma unroll
        for (int ni = 0; ni < 4; ni++)
#pragma unroll
            for (int mi = 0; mi < 2; mi++) {
                mma_f16(acc[mi][ni], ah[mi], bh[ni][0], bh[ni][1]);
                mma_f16(acc[mi][ni], am[mi], bh[ni][0], bh[ni][1]);
                mma_f16(acc[mi][ni], ah[mi], bm[ni][0], bm[ni][1]);
            }
    }
#pragma unroll
    for (int mi = 0; mi < 2; mi++)
#pragma unroll
        for (int ni = 0; ni < 4; ni++) {
            int r = mt * 128 + wm + mi * 16 + grp;
            int n = wn + ni * 8 + tq * 2;
            float2 v0 = {acc[mi][ni][0], acc[mi][ni][1]};
            float2 v1 = {acc[mi][ni][2], acc[mi][ni][3]};
            *(float2*)&g_E2[((size_t)h * NINST + r) * 64 + n] = v0;
            *(float2*)&g_E2[((size_t)h * NINST + r + 8) * 64 + n] = v1;
        }
}

// =====================================================================
// prefix: combine chunk end states -> per-chunk init states (fp16 split)
// =====================================================================
__global__ __launch_bounds__(256) void ssm_prefix2(
    const float* __restrict__ log_dt, const float* __restrict__ A_imag,
    const float* __restrict__ log_A_real, int layer)
{
    int idx = blockIdx.x * 256 + threadIdx.x;
    int li = idx & 7;
    int b  = (idx >> 3) & 7;
    int h  = idx >> 6;

    float Are[4], Aim[4], dt;
    scan_coeffs(log_dt, A_imag, log_A_real, layer, h, li, Are, Aim, &dt);
    float Wr[4], Wi[4];
#pragma unroll
    for (int j = 0; j < 4; j++) {
        float e = expf(Are[j] * dt * (float)CL);
        Wr[j] = e * cosf(Aim[j] * dt * (float)CL);
        Wi[j] = e * sinf(Aim[j] * dt * (float)CL);
    }
    float Ire[4] = {0, 0, 0, 0}, Iim[4] = {0, 0, 0, 0};
    for (int c = 0; c < NC; c++) {
        size_t off = ((size_t)h * NINST + b * NC + c) * 64 + li * 8;
#pragma unroll
        for (int j = 0; j < 4; j++) {
            hsplit(Ire[j], g_Shi + off + 2 * j,     g_Smid + off + 2 * j);
            hsplit(Iim[j], g_Shi + off + 2 * j + 1, g_Smid + off + 2 * j + 1);
        }
        float4 e0 = *(const float4*)(g_E2 + off);
        float4 e1 = *(const float4*)(g_E2 + off + 4);
        float er[4] = {e0.x, e0.z, e1.x, e1.z};
        float ei[4] = {e0.y, e0.w, e1.y, e1.w};
#pragma unroll
        for (int j = 0; j < 4; j++) {
            float nr = fmaf(Wr[j], Ire[j], fmaf(-Wi[j], Iim[j], er[j]));
            float ni = fmaf(Wi[j], Ire[j], fmaf( Wr[j], Iim[j], ei[j]));
            Ire[j] = nr; Iim[j] = ni;
        }
    }
}

// =====================================================================
// gemm_toep: per h, Y[NINST x 128] = [U|Sinit][NINST x 192] @ B2^T.
// fp16 3-term. grid (2, 512), tile 128x128, K=192 (12 ktiles).
// =====================================================================
#define PLANE 6144u
#define BOFF  12288u
#define STAGE 24576u
#define T_DSMEM (3 * STAGE)

__global__ __launch_bounds__(256, 2) void gemm_toep()
{
    extern __shared__ __align__(16) char dsmT[];
    int tid = threadIdx.x;
    int warp = tid >> 5, lane = tid & 31;
    int grp = lane >> 2, tq = lane & 3;
    int mt = blockIdx.x, h = blockIdx.y;
    int wm = (warp >> 1) * 32, wn = (warp & 1) * 64;
    int lrow8 = (lane & 7) + (lane & 8);
    int khalf = (lane >> 4) * 16;

    int mloc = tid >> 1, ch = tid & 1;
    int m = mt * 128 + mloc;
    int bb = m >> 5, cc = m & 31;
    const __half* aUh = g_Uhi  + ((size_t)(bb * H + h)) * LSEQ + cc * CL;
    const __half* aUm = g_Umid + ((size_t)(bb * H + h)) * LSEQ + cc * CL;
    const __half* aSh = g_Shi  + ((size_t)h * NINST + m) * 64;
    const __half* aSm = g_Smid + ((size_t)h * NINST + m) * 64;
    const __half* bTh = g_T2hi  + (size_t)h * CL * 192;
    const __half* bTm = g_T2mid + (size_t)h * CL * 192;

    float acc[2][8][4];
#pragma unroll
    for (int mi = 0; mi < 2; mi++)
#pragma unroll
        for (int ni = 0; ni < 8; ni++)
#pragma unroll
            for (int r = 0; r < 4; r++) acc[mi][ni][r] = 0.0f;

#define LOAD_T(KT, S)                                                            \
    do {                                                                         \
        char* sb = dsmT + (unsigned)(S) * STAGE;                                 \
        int k0 = (KT) * 16 + ch * 8;                                             \
        const __half* sh = (k0 < 128) ? aUh + k0 : aSh + (k0 - 128);             \
        const __half* sm = (k0 < 128) ? aUm + k0 : aSm + (k0 - 128);             \
        char* pa = sb + (unsigned)(mloc * 48 + ch * 16);                         \
        cpa16(pa,         sh);                                                   \
        cpa16(pa + PLANE, sm);                                                   \
        char* pb = sb + BOFF + (unsigned)(mloc * 48 + ch * 16);                  \
        cpa16(pb,         bTh + (size_t)mloc * 192 + k0);                        \
        cpa16(pb + PLANE, bTm + (size_t)mloc * 192 + k0);                        \
        asm volatile("cp.async.commit_group;" ::: "memory");                     \
    } while (0)

    LOAD_T(0, 0);
    LOAD_T(1, 1);
    const int NKT = 12;
    for (int kt = 0; kt < NKT; kt++) {
        int s = kt - (kt / 3) * 3;
        if (kt + 2 < NKT) asm volatile("cp.async.wait_group 1;" ::: "memory");
        else              asm volatile("cp.async.wait_group 0;" ::: "memory");
        __syncthreads();
        if (kt + 2 < NKT) {
            int s2 = (kt + 2) - ((kt + 2) / 3) * 3;
            LOAD_T(kt + 2, s2);
        }
        const char* sb = dsmT + (unsigned)s * STAGE;
        uint32_t ah[2][4], am[2][4];
#pragma unroll
        for (int mi = 0; mi < 2; mi++) {
            const char* pa = sb + (unsigned)((wm + mi * 16 + lrow8) * 48) + khalf;
            ldsm4(ah[mi][0], ah[mi][1], ah[mi][2], ah[mi][3], pa);
            ldsm4(am[mi][0], am[mi][1], am[mi][2], am[mi][3], pa + PLANE);
        }
        uint32_t bh[8][2], bm[8][2];
#pragma unroll
        for (int p = 0; p < 4; p++) {
            const char* pb = sb + BOFF + (unsigned)((wn + p * 16 + lrow8) * 48) + khalf;
            ldsm4(bh[2 * p][0], bh[2 * p + 1][0], bh[2 * p][1], bh[2 * p + 1][1], pb);
            ldsm4(bm[2 * p][0], bm[2 * p + 1][0], bm[2 * p][1], bm[2 * p + 1][1],
                  pb + PLANE);
        }
#pragma unroll
        for (int ni = 0; ni < 8; ni++)
#pragma unroll
            for (int mi = 0; mi < 2; mi++) {
                mma_f16(acc[mi][ni], ah[mi], bh[ni][0], bh[ni][1]);
                mma_f16(acc[mi][ni], am[mi], bh[ni][0], bh[ni][1]);
                mma_f16(acc[mi][ni], ah[mi], bm[ni][0], bm[ni][1]);
            }
    }
#pragma unroll
    for (int mi = 0; mi < 2; mi++) {
        int r = mt * 128 + wm + mi * 16 + grp;
        int b0 = r >> 5, c0 = r & 31;
        int r1 = r + 8;
        int b1 = r1 >> 5, c1 = r1 & 31;
        float* y0 = g_Yt + ((size_t)(b0 * H + h)) * LSEQ + c0 * CL;
        float* y1 = g_Yt + ((size_t)(b1 * H + h)) * LSEQ + c1 * CL;
#pragma unroll
        for (int ni = 0; ni < 8; ni++) {
            int n = wn + ni * 8 + tq * 2;
            *(float2*)(y0 + n) = make_float2(acc[mi][ni][0], acc[mi][ni][1]);
            *(float2*)(y1 + n) = make_float2(acc[mi][ni][2], acc[mi][ni][3]);
        }
    }
}

// =====================================================================
// ytrans: (B,H,L) fp32 raw y -> GELU -> (B,L,H) fp16 hi/mid
// =====================================================================
__global__ __launch_bounds__(256) void ytrans() {
    __shared__ float tile[32][33];
    int b = blockIdx.z, h0 = blockIdx.y * 32, l0 = blockIdx.x * 32;
    int tx = threadIdx.x, ty = threadIdx.y;
#pragma unroll
    for (int j = 0; j < 32; j += 8)
        tile[ty + j][tx] = g_Yt[((size_t)(b * H + h0 + ty + j)) * LSEQ + l0 + tx];
    __syncthreads();
#pragma unroll
    for (int j = 0; j < 32; j += 8) {
        float v = tile[tx][ty + j];
        v = 0.5f * v * (1.0f + erff(v * 0.70710678118654752f));
        size_t o = ((size_t)b * LSEQ + l0 + ty + j) * H + h0 + tx;
        hsplit(v, g_Yhi + o, g_Ymid + o);
    }
}

// =====================================================================
// W prep: interleave rows (2i <- a-row i, 2i+1 <- g-row i+H), fp16 hi only.
// =====================================================================
__global__ __launch_bounds__(256) void w_prep(const float* __restrict__ W,
                                              const float* __restrict__ bp) {
    size_t i = (size_t)blockIdx.x * 256 + threadIdx.x;
    int col = (int)(i % H);
    int k   = (int)((i / H) % (2 * H));
    int l   = (int)(i / ((size_t)H * 2 * H));
    int orig = (k >> 1) + (k & 1) * H;
    float v = W[((size_t)l * 2 * H + orig) * H + col];
    g_Whi[i] = __float2half_rn(v);
    if (i < NLAY * 2 * H) {
        int kk = (int)(i % (2 * H));
        int ll = (int)(i / (2 * H));
        int og = (kk >> 1) + (kk & 1) * H;
        g_bint[i] = bp[ll * 2 * H + og];
    }
}

// =====================================================================
// conv GEMM + fused GLU: fp16 2-TERM split (Yhi*Whi + Ymid*Whi).
// CTA tile 128x128, K-tile 16, 3-stage, stage = 18432B.
// =====================================================================
#define C_PLANE 6144u
#define C_BOFF  12288u
#define C_STAGE 18432u
#define C_DSMEM (3 * C_STAGE)   /* 55296 */

__global__ __launch_bounds__(256, 2) void conv_gemm(int layer)
{
    extern __shared__ __align__(16) char dsm[];
    int tid = threadIdx.x;
    int warp = tid >> 5, lane = tid & 31;
    int grp = lane >> 2, tq = lane & 3;
    int n0 = blockIdx.x * 128, m0 = blockIdx.y * 128;

    const __half* Wh = g_Whi + (size_t)layer * 2 * H * H;

    int wm = (warp >> 1) * 32, wn = (warp & 1) * 64;
    int lrow8 = (lane & 7) + (lane & 8);
    int khalf = (lane >> 4) * 16;

    float acc[2][8][4];
#pragma unroll
    for (int mi = 0; mi < 2; mi++)
#pragma unroll
        for (int ni = 0; ni < 8; ni++)
#pragma unroll
            for (int r = 0; r < 4; r++) acc[mi][ni][r] = 0.0f;

    int fr = tid >> 1, fch = tid & 1;

#define LOAD_C(KT, S)                                                              \
    do {                                                                           \
        char* sb = dsm + (unsigned)(S) * C_STAGE + (unsigned)(fr * 48 + fch * 16); \
        size_t soA = (size_t)(m0 + fr) * H + (KT) * 16 + fch * 8;                  \
        size_t soB = (size_t)(n0 + fr) * H + (KT) * 16 + fch * 8;                  \
        cpa16(sb,           g_Yhi + soA);                                          \
        cpa16(sb + C_PLANE, g_Ymid + soA);                                         \
        cpa16(sb + C_BOFF,  Wh + soB);                                             \
        asm volatile("cp.async.commit_group;" ::: "memory");                       \
    } while (0)

    LOAD_C(0, 0);
    LOAD_C(1, 1);

    const int NKT = H / 16;   // 32
    for (int kt = 0; kt < NKT; kt++) {
        int s = kt - (kt / 3) * 3;
        if (kt + 2 < NKT) asm volatile("cp.async.wait_group 1;" ::: "memory");
        else              asm volatile("cp.async.wait_group 0;" ::: "memory");
        __syncthreads();
        if (kt + 2 < NKT) {
            int s2 = (kt + 2) - ((kt + 2) / 3) * 3;
            LOAD_C(kt + 2, s2);
        }
        const char* sb = dsm + (unsigned)s * C_STAGE;
        uint32_t ah[2][4], am[2][4];
#pragma unroll
        for (int mi = 0; mi < 2; mi++) {
            const char* pa = sb + (unsigned)((wm + mi * 16 + lrow8) * 48) + khalf;
            ldsm4(ah[mi][0], ah[mi][1], ah[mi][2], ah[mi][3], pa);
            ldsm4(am[mi][0], am[mi][1], am[mi][2], am[mi][3], pa + C_PLANE);
        }
        uint32_t bh[8][2];
#pragma unroll
        for (int p = 0; p < 4; p++) {
            const char* pb = sb + C_BOFF + (unsigned)((wn + p * 16 + lrow8) * 48) + khalf;
            ldsm4(bh[2 * p][0], bh[2 * p + 1][0], bh[2 * p][1], bh[2 * p + 1][1], pb);
        }
#pragma unroll
        for (int ni = 0; ni < 8; ni++)
#pragma unroll
            for (int mi = 0; mi < 2; mi++) {
                mma_f16(acc[mi][ni], ah[mi], bh[ni][0], bh[ni][1]);
                mma_f16(acc[mi][ni], am[mi], bh[ni][0], bh[ni][1]);
            }
    }
#pragma unroll
    for (int mi = 0; mi < 2; mi++)
#pragma unroll
        for (int ni = 0; ni < 8; ni++) {
            int r  = m0 + wm + mi * 16 + grp;
            int cb = wn + ni * 8 + tq * 2;
            float ba = g_bint[layer * 2 * H + n0 + cb];
            float bg = g_bint[layer * 2 * H + n0 + cb + 1];
            float a0 = acc[mi][ni][0] + ba, gg0 = acc[mi][ni][1] + bg;
            float a1 = acc[mi][ni][2] + ba, gg1 = acc[mi][ni][3] + bg;
            int hidx = (n0 + cb) >> 1;
            g_Z[(size_t)r * H + hidx]       = a0 / (1.0f + expf(-gg0));
            g_Z[(size_t)(r + 8) * H + hidx] = a1 / (1.0f + expf(-gg1));
        }
}

// =====================================================================
// Residual + LayerNorm. warp per row.
// =====================================================================
__global__ __launch_bounds__(128) void res_ln(
    const float* __restrict__ xin, float* __restrict__ xout,
    const float* __restrict__ gamma, const float* __restrict__ beta, int layer)
{
    int row  = blockIdx.x * 4 + (threadIdx.x >> 5);
    int lane = threadIdx.x & 31;
    const float4* z4 = (const float4*)(g_Z + (size_t)row * H);
    const float4* x4 = (const float4*)(xin + (size_t)row * H);
    float4* o4       = (float4*)(xout + (size_t)row * H);
    const float4* g4 = (const float4*)(gamma + layer * H);
    const float4* e4 = (const float4*)(beta + layer * H);

    float4 v[4];
    float s = 0.0f, s2 = 0.0f;
#pragma unroll
    for (int j = 0; j < 4; j++) {
        float4 zz = z4[j * 32 + lane];
        float4 xv = x4[j * 32 + lane];
        float4 vv;
        vv.x = zz.x + xv.x; vv.y = zz.y + xv.y;
        vv.z = zz.z + xv.z; vv.w = zz.w + xv.w;
        v[j] = vv;
        s += vv.x + vv.y + vv.z + vv.w;
        s2 = fmaf(vv.x, vv.x, s2); s2 = fmaf(vv.y, vv.y, s2);
        s2 = fmaf(vv.z, vv.z, s2); s2 = fmaf(vv.w, vv.w, s2);
    }
#pragma unroll
    for (int o = 16; o; o >>= 1) {
        s  += __shfl_xor_sync(0xffffffffu, s, o);
        s2 += __shfl_xor_sync(0xffffffffu, s2, o);
    }
    float mu = s * (1.0f / H);
    float rs = rsqrtf(s2 * (1.0f / H) - mu * mu + LN_EPS);
#pragma unroll
    for (int j = 0; j < 4; j++) {
        float4 ga = g4[j * 32 + lane];
        float4 be = e4[j * 32 + lane];
        float4 vv = v[j], o;
        o.x = (vv.x - mu) * rs * ga.x + be.x;
        o.y = (vv.y - mu) * rs * ga.y + be.y;
        o.z = (vv.z - mu) * rs * ga.z + be.z;
        o.w = (vv.w - mu) * rs * ga.w + be.w;
        o4[j * 32 + lane] = o;
    }
}

// ================= launcher =================
extern "C" void kernel_launch(void* const* d_in, const int* in_sizes, int n_in,
                              void* d_out, int out_size)
{
    const float* x          = (const float*)d_in[0];
    const float* log_dt     = (const float*)d_in[1];
    const float* A_imag     = (const float*)d_in[2];
    const float* log_A_real = (const float*)d_in[3];
    const float* C          = (const float*)d_in[4];
    const float* D          = (const float*)d_in[5];
    const float* W          = (const float*)d_in[6];
    const float* bconv      = (const float*)d_in[7];
    const float* gamma      = (const float*)d_in[8];
    const float* beta       = (const float*)d_in[9];
    float* out = (float*)d_out;

    cudaFuncSetAttribute(conv_gemm, cudaFuncAttributeMaxDynamicSharedMemorySize,
                         C_DSMEM);
    cudaFuncSetAttribute(gemm_toep, cudaFuncAttributeMaxDynamicSharedMemorySize,
                         T_DSMEM);
    cudaFuncSetAttribute(gemm_end, cudaFuncAttributeMaxDynamicSharedMemorySize,
                         E_DSMEM);

    float* pA; cudaGetSymbolAddress((void**)&pA, g_xA);
    float* pB; cudaGetSymbolAddress((void**)&pB, g_xB);
    const float* xin[NLAY]  = {x,  pA, pB, pA};
    float*       xout[NLAY] = {pA, pB, pA, out};

    w_prep<<<(NLAY * 2 * H * H) / 256, 256>>>(W, bconv);

    dim3 tb(32, 8);
    for (int i = 0; i < NLAY; i++) {
        xsplit<<<dim3(H / 32, LSEQ / 32, BSZ), tb>>>(xin[i]);
        tbuild<<<H, 256>>>(log_dt, A_imag, log_A_real, C, D, i);
        gemm_end<<<dim3(2, H), 256, E_DSMEM>>>();
        ssm_prefix2<<<(H * BSZ * 8) / 256, 256>>>(log_dt, A_imag, log_A_real, i);
        gemm_toep<<<dim3(2, H), 256, T_DSMEM>>>();
        ytrans<<<dim3(LSEQ / 32, H / 32, BSZ), tb>>>();
        conv_gemm<<<dim3(2 * H / 128, MROWS / 128), 256, C_DSMEM>>>(i);
        res_ln<<<MROWS / 4, 128>>>(xin[i], xout[i], gamma, beta, i);
    }
}

// round 11
// speedup vs baseline: 1.7702x; 1.3907x over previous
#include <cuda_runtime.h>
#include <cuda_fp16.h>
#include <cstdint>

#define H     512
#define NLAY  4
#define N2    32
#define BSZ   8
#define LSEQ  4096
#define MROWS (BSZ * LSEQ)      /* 32768 */
#define NC    32                /* chunks per sequence */
#define CL    (LSEQ / NC)       /* 128 */
#define NINST (BSZ * NC)        /* 256 instances per h */
#define LN_EPS 1e-5f

// ---- static scratch. activations (B,L,H) row-major unless noted ----
__device__ __align__(256) float g_xA[(size_t)MROWS * H];
__device__ __align__(256) float g_xB[(size_t)MROWS * H];
__device__ __align__(256) __half g_Uhi [(size_t)MROWS * H];   // u (B,H,L)
__device__ __align__(256) __half g_Umid[(size_t)MROWS * H];
__device__ __align__(256) __half g_Yhi [(size_t)MROWS * H];   // gelu(y) (B,L,H)
__device__ __align__(256) float g_Yt[(size_t)MROWS * H];      // raw y (B,H,L)
__device__ __align__(256) __half g_Whi[(size_t)NLAY * 2 * H * H];
__device__ __align__(256) float g_bint[NLAY * 2 * H];
__device__ __align__(256) float g_Z[(size_t)MROWS * H];       // GLU out (B,L,H)
// Toeplitz machinery (per-layer rebuilt)
__device__ __align__(256) __half g_T2hi [(size_t)H * CL * 192];  // B2 [h][n=l][k]
__device__ __align__(256) __half g_T2mid[(size_t)H * CL * 192];
__device__ __align__(256) __half g_T1hi [(size_t)H * 64 * CL];   // B1 [h][e][j]
__device__ __align__(256) float g_E2[(size_t)H * NINST * 64];    // end states
__device__ __align__(256) __half g_Shi [(size_t)H * NINST * 64]; // init states
__device__ __align__(256) __half g_Smid[(size_t)H * NINST * 64];

// ---------------- helpers ----------------
__device__ __forceinline__ void cpa16(void* dst, const void* src) {
    unsigned d = (unsigned)__cvta_generic_to_shared(dst);
    asm volatile("cp.async.cg.shared.global [%0], [%1], 16;" :: "r"(d), "l"(src));
}
__device__ __forceinline__ void ldsm4(uint32_t& r0, uint32_t& r1, uint32_t& r2,
                                      uint32_t& r3, const void* p) {
    uint32_t a = (uint32_t)__cvta_generic_to_shared(p);
    asm volatile("ldmatrix.sync.aligned.m8n8.x4.shared.b16 {%0,%1,%2,%3}, [%4];"
                 : "=r"(r0), "=r"(r1), "=r"(r2), "=r"(r3) : "r"(a));
}
__device__ __forceinline__ void mma_f16(float* d, const uint32_t* a,
                                        uint32_t b0, uint32_t b1) {
    asm volatile(
        "mma.sync.aligned.m16n8k16.row.col.f32.f16.f16.f32 "
        "{%0,%1,%2,%3}, {%4,%5,%6,%7}, {%8,%9}, {%0,%1,%2,%3};"
        : "+f"(d[0]), "+f"(d[1]), "+f"(d[2]), "+f"(d[3])
        : "r"(a[0]), "r"(a[1]), "r"(a[2]), "r"(a[3]), "r"(b0), "r"(b1));
}
__device__ __forceinline__ void hsplit(float v, __half* hi_p, __half* mid_p) {
    __half hi = __float2half_rn(v);
    *hi_p = hi;
    *mid_p = __float2half_rn(v - __half2float(hi));
}

__device__ __forceinline__ void scan_coeffs(
    const float* log_dt, const float* A_imag, const float* log_A_real,
    int layer, int h, int li, float* Are_o, float* Aim_o, float* dt_o)
{
    float dt = expf(log_dt[layer * H + h]);
    int pbase = (layer * H + h) * N2 + li * 4;
    float4 aim = *(const float4*)(A_imag + pbase);
    float4 lar = *(const float4*)(log_A_real + pbase);
    float aimv[4] = {aim.x, aim.y, aim.z, aim.w};
    float larv[4] = {lar.x, lar.y, lar.z, lar.w};
#pragma unroll
    for (int j = 0; j < 4; j++) {
        Are_o[j] = -expf(larv[j]);
        Aim_o[j] = aimv[j];
    }
    *dt_o = dt;
}

// =====================================================================
// xsplit: (B,L,H) fp32 -> (B,H,L) fp16 hi/mid
// =====================================================================
__global__ __launch_bounds__(256) void xsplit(const float* __restrict__ x) {
    __shared__ float tile[32][33];
    int b = blockIdx.z, h0 = blockIdx.x * 32, l0 = blockIdx.y * 32;
    int tx = threadIdx.x, ty = threadIdx.y;
#pragma unroll
    for (int j = 0; j < 32; j += 8)
        tile[ty + j][tx] = x[((size_t)b * LSEQ + l0 + ty + j) * H + h0 + tx];
    __syncthreads();
#pragma unroll
    for (int j = 0; j < 32; j += 8) {
        float v = tile[tx][ty + j];
        size_t o = ((size_t)(b * H + h0 + ty + j)) * LSEQ + l0 + tx;
        hsplit(v, g_Uhi + o, g_Umid + o);
    }
}

// =====================================================================
// tbuild: per-h Toeplitz kernel k[d], correction matrix V, end-state E.
// =====================================================================
__global__ __launch_bounds__(256) void tbuild(
    const float* __restrict__ log_dt, const float* __restrict__ A_imag,
    const float* __restrict__ log_A_real, const float* __restrict__ Cp,
    const float* __restrict__ Dp, int layer)
{
    __shared__ float wr[CL + 1][32], wi[CL + 1][32];
    __shared__ float scfr[32], scfi[32], skern[CL];
    __shared__ float sD;
    int h = blockIdx.x;
    int t = threadIdx.x;
    if (t == 0) sD = Dp[layer * H + h];
    if (t < 32) {
        int n = t;
        float dt = expf(log_dt[layer * H + h]);
        float Are = -expf(log_A_real[(layer * H + h) * N2 + n]);
        float Aim = A_imag[(layer * H + h) * N2 + n];
        float e1 = expf(Are * dt);
        float w1r = e1 * cosf(Aim * dt), w1i = e1 * sinf(Aim * dt);
        float nr = w1r - 1.0f, ni = w1i;
        float cr = Cp[((layer * H + h) * N2 + n) * 2 + 0];
        float ci = Cp[((layer * H + h) * N2 + n) * 2 + 1];
        float tr = cr * nr - ci * ni;
        float ti = cr * ni + ci * nr;
        float inv = 2.0f / (Are * Are + Aim * Aim);
        scfr[n] = (tr * Are + ti * Aim) * inv;
        scfi[n] = (ti * Are - tr * Aim) * inv;
        float pr = 1.0f, pi = 0.0f;
        for (int d = 0; d <= CL; d++) {
            wr[d][n] = pr; wi[d][n] = pi;
            float npr = pr * w1r - pi * w1i;
            float npi = pr * w1i + pi * w1r;
            pr = npr; pi = npi;
        }
    }
    __syncthreads();
    if (t < CL) {
        float acc = (t == 0) ? sD : 0.0f;
#pragma unroll 8
        for (int n = 0; n < 32; n++)
            acc += scfr[n] * wr[t][n] - scfi[n] * wi[t][n];
        skern[t] = acc;
    }
    __syncthreads();
    for (int idx = t; idx < CL * CL; idx += 256) {
        int n = idx >> 7, k = idx & 127;
        float v = (k <= n) ? skern[n - k] : 0.0f;
        size_t o = ((size_t)h * CL + n) * 192 + k;
        hsplit(v, g_T2hi + o, g_T2mid + o);
    }
    for (int idx = t; idx < CL * 64; idx += 256) {
        int n = idx >> 6, e = idx & 63, ns = e >> 1;
        float cwr = scfr[ns] * wr[n + 1][ns] - scfi[ns] * wi[n + 1][ns];
        float cwi = scfr[ns] * wi[n + 1][ns] + scfi[ns] * wr[n + 1][ns];
        float v = (e & 1) ? -cwi : cwr;
        size_t o = ((size_t)h * CL + n) * 192 + 128 + e;
        hsplit(v, g_T2hi + o, g_T2mid + o);
    }
    // B1 end-state matrix: hi plane only (2-term gemm_end)
    for (int idx = t; idx < 64 * CL; idx += 256) {
        int e = idx >> 7, j = idx & 127, ns = e >> 1;
        int d = CL - 1 - j;
        float v = (e & 1) ? wi[d][ns] : wr[d][ns];
        g_T1hi[((size_t)h * 64 + e) * CL + j] = __float2half_rn(v);
    }
}

// =====================================================================
// gemm_end: per h, S_end[NINST x 64] = U[NINST x 128] @ B1^T.
// 2-term: (Uhi + Umid) * B1hi.
// =====================================================================
#define E_PLANE 6144u
#define E_BOFF  12288u
#define E_STAGE 15360u
#define E_DSMEM (3 * E_STAGE)   /* 46080 */

__global__ __launch_bounds__(256, 2) void gemm_end()
{
    extern __shared__ __align__(16) char dsmE[];
    int tid = threadIdx.x;
    int warp = tid >> 5, lane = tid & 31;
    int grp = lane >> 2, tq = lane & 3;
    int mt = blockIdx.x, h = blockIdx.y;
    int wm = (warp >> 1) * 32, wn = (warp & 1) * 32;
    int lrow8 = (lane & 7) + (lane & 8);
    int khalf = (lane >> 4) * 16;

    int mloc = tid >> 1, ch = tid & 1;
    int m = mt * 128 + mloc;
    int bb = m >> 5, cc = m & 31;
    const __half* aUh = g_Uhi  + ((size_t)(bb * H + h)) * LSEQ + cc * CL;
    const __half* aUm = g_Umid + ((size_t)(bb * H + h)) * LSEQ + cc * CL;
    int frB = (tid & 127) >> 1, chB = tid & 1;
    const __half* bTh = g_T1hi + (size_t)h * 64 * CL;

    float acc[2][4][4];
#pragma unroll
    for (int mi = 0; mi < 2; mi++)
#pragma unroll
        for (int ni = 0; ni < 4; ni++)
#pragma unroll
            for (int r = 0; r < 4; r++) acc[mi][ni][r] = 0.0f;

#define LOAD_E(KT, S)                                                            \
    do {                                                                         \
        char* sb = dsmE + (unsigned)(S) * E_STAGE;                               \
        int k0 = (KT) * 16 + ch * 8;                                             \
        char* pa = sb + (unsigned)(mloc * 48 + ch * 16);                         \
        cpa16(pa,           aUh + k0);                                           \
        cpa16(pa + E_PLANE, aUm + k0);                                           \
        if (tid < 128) {                                                         \
            int kb = (KT) * 16 + chB * 8;                                        \
            char* pb = sb + E_BOFF + (unsigned)(frB * 48 + chB * 16);            \
            cpa16(pb, bTh + (size_t)frB * CL + kb);                              \
        }                                                                        \
        asm volatile("cp.async.commit_group;" ::: "memory");                     \
    } while (0)

    LOAD_E(0, 0);
    LOAD_E(1, 1);
    const int NKT = 8;
    for (int kt = 0; kt < NKT; kt++) {
        int s = kt - (kt / 3) * 3;
        if (kt + 2 < NKT) asm volatile("cp.async.wait_group 1;" ::: "memory");
        else              asm volatile("cp.async.wait_group 0;" ::: "memory");
        __syncthreads();
        if (kt + 2 < NKT) {
            int s2 = (kt + 2) - ((kt + 2) / 3) * 3;
            LOAD_E(kt + 2, s2);
        }
        const char* sb = dsmE + (unsigned)s * E_STAGE;
        uint32_t ah[2][4], am[2][4];
#pragma unroll
        for (int mi = 0; mi < 2; mi++) {
            const char* pa = sb + (unsigned)((wm + mi * 16 + lrow8) * 48) + khalf;
            ldsm4(ah[mi][0], ah[mi][1], ah[mi][2], ah[mi][3], pa);
            ldsm4(am[mi][0], am[mi][1], am[mi][2], am[mi][3], pa + E_PLANE);
        }
        uint32_t bh[4][2];
#pragma unroll
        for (int p = 0; p < 2; p++) {
            const char* pb = sb + E_BOFF + (unsigned)((wn + p * 16 + lrow8) * 48) + khalf;
            ldsm4(bh[2 * p][0], bh[2 * p + 1][0], bh[2 * p][1], bh[2 * p + 1][1], pb);
        }
#pragma unroll
        for (int ni = 0; ni < 4; ni++)
#pragma unroll
            for (int mi = 0; mi < 2; mi++) {
                mma_f16(acc[mi][ni], ah[mi], bh[ni][0], bh[ni][1]);
                mma_f16(acc[mi][ni], am[mi], bh[ni][0], bh[ni][1]);
            }
    }
#pragma unroll
    for (int mi = 0; mi < 2; mi++)
#pragma unroll
        for (int ni = 0; ni < 4; ni++) {
            int r = mt * 128 + wm + mi * 16 + grp;
            int n = wn + ni * 8 + tq * 2;
            float2 v0 = {acc[mi][ni][0], acc[mi][ni][1]};
            float2 v1 = {acc[mi][ni][2], acc[mi][ni][3]};
            *(float2*)&g_E2[((size_t)h * NINST + r) * 64 + n] = v0;
            *(float2*)&g_E2[((size_t)h * NINST + r + 8) * 64 + n] = v1;
        }
}

// =====================================================================
// prefix: combine chunk end states -> per-chunk init states (fp16 split)
// =====================================================================
__global__ __launch_bounds__(256) void ssm_prefix2(
    const float* __restrict__ log_dt, const float* __restrict__ A_imag,
    const float* __restrict__ log_A_real, int layer)
{
    int idx = blockIdx.x * 256 + threadIdx.x;
    int li = idx & 7;
    int b  = (idx >> 3) & 7;
    int h  = idx >> 6;

    float Are[4], Aim[4], dt;
    scan_coeffs(log_dt, A_imag, log_A_real, layer, h, li, Are, Aim, &dt);
    float Wr[4], Wi[4];
#pragma unroll
    for (int j = 0; j < 4; j++) {
        float e = expf(Are[j] * dt * (float)CL);
        Wr[j] = e * cosf(Aim[j] * dt * (float)CL);
        Wi[j] = e * sinf(Aim[j] * dt * (float)CL);
    }
    float Ire[4] = {0, 0, 0, 0}, Iim[4] = {0, 0, 0, 0};
    for (int c = 0; c < NC; c++) {
        size_t off = ((size_t)h * NINST + b * NC + c) * 64 + li * 8;
#pragma unroll
        for (int j = 0; j < 4; j++) {
            hsplit(Ire[j], g_Shi + off + 2 * j,     g_Smid + off + 2 * j);
            hsplit(Iim[j], g_Shi + off + 2 * j + 1, g_Smid + off + 2 * j + 1);
        }
        float4 e0 = *(const float4*)(g_E2 + off);
        float4 e1 = *(const float4*)(g_E2 + off + 4);
        float er[4] = {e0.x, e0.z, e1.x, e1.z};
        float ei[4] = {e0.y, e0.w, e1.y, e1.w};
#pragma unroll
        for (int j = 0; j < 4; j++) {
            float nr = fmaf(Wr[j], Ire[j], fmaf(-Wi[j], Iim[j], er[j]));
            float ni = fmaf(Wi[j], Ire[j], fmaf( Wr[j], Iim[j], ei[j]));
            Ire[j] = nr; Iim[j] = ni;
        }
    }
}

// =====================================================================
// gemm_toep: per h, Y[NINST x 128] = [U|Sinit][NINST x 192] @ B2^T.
// fp16 3-term. grid (2, 512), tile 128x128, K=192 (12 ktiles).
// =====================================================================
#define PLANE 6144u
#define BOFF  12288u
#define STAGE 24576u
#define T_DSMEM (3 * STAGE)

__global__ __launch_bounds__(256, 2) void gemm_toep()
{
    extern __shared__ __align__(16) char dsmT[];
    int tid = threadIdx.x;
    int warp = tid >> 5, lane = tid & 31;
    int grp = lane >> 2, tq = lane & 3;
    int mt = blockIdx.x, h = blockIdx.y;
    int wm = (warp >> 1) * 32, wn = (warp & 1) * 64;
    int lrow8 = (lane & 7) + (lane & 8);
    int khalf = (lane >> 4) * 16;

    int mloc = tid >> 1, ch = tid & 1;
    int m = mt * 128 + mloc;
    int bb = m >> 5, cc = m & 31;
    const __half* aUh = g_Uhi  + ((size_t)(bb * H + h)) * LSEQ + cc * CL;
    const __half* aUm = g_Umid + ((size_t)(bb * H + h)) * LSEQ + cc * CL;
    const __half* aSh = g_Shi  + ((size_t)h * NINST + m) * 64;
    const __half* aSm = g_Smid + ((size_t)h * NINST + m) * 64;
    const __half* bTh = g_T2hi  + (size_t)h * CL * 192;
    const __half* bTm = g_T2mid + (size_t)h * CL * 192;

    float acc[2][8][4];
#pragma unroll
    for (int mi = 0; mi < 2; mi++)
#pragma unroll
        for (int ni = 0; ni < 8; ni++)
#pragma unroll
            for (int r = 0; r < 4; r++) acc[mi][ni][r] = 0.0f;

#define LOAD_T(KT, S)                                                            \
    do {                                                                         \
        char* sb = dsmT + (unsigned)(S) * STAGE;                                 \
        int k0 = (KT) * 16 + ch * 8;                                             \
        const __half* sh = (k0 < 128) ? aUh + k0 : aSh + (k0 - 128);             \
        const __half* sm = (k0 < 128) ? aUm + k0 : aSm + (k0 - 128);             \
        char* pa = sb + (unsigned)(mloc * 48 + ch * 16);                         \
        cpa16(pa,         sh);                                                   \
        cpa16(pa + PLANE, sm);                                                   \
        char* pb = sb + BOFF + (unsigned)(mloc * 48 + ch * 16);                  \
        cpa16(pb,         bTh + (size_t)mloc * 192 + k0);                        \
        cpa16(pb + PLANE, bTm + (size_t)mloc * 192 + k0);                        \
        asm volatile("cp.async.commit_group;" ::: "memory");                     \
    } while (0)

    LOAD_T(0, 0);
    LOAD_T(1, 1);
    const int NKT = 12;
    for (int kt = 0; kt < NKT; kt++) {
        int s = kt - (kt / 3) * 3;
        if (kt + 2 < NKT) asm volatile("cp.async.wait_group 1;" ::: "memory");
        else              asm volatile("cp.async.wait_group 0;" ::: "memory");
        __syncthreads();
        if (kt + 2 < NKT) {
            int s2 = (kt + 2) - ((kt + 2) / 3) * 3;
            LOAD_T(kt + 2, s2);
        }
        const char* sb = dsmT + (unsigned)s * STAGE;
        uint32_t ah[2][4], am[2][4];
#pragma unroll
        for (int mi = 0; mi < 2; mi++) {
            const char* pa = sb + (unsigned)((wm + mi * 16 + lrow8) * 48) + khalf;
            ldsm4(ah[mi][0], ah[mi][1], ah[mi][2], ah[mi][3], pa);
            ldsm4(am[mi][0], am[mi][1], am[mi][2], am[mi][3], pa + PLANE);
        }
        uint32_t bh[8][2], bm[8][2];
#pragma unroll
        for (int p = 0; p < 4; p++) {
            const char* pb = sb + BOFF + (unsigned)((wn + p * 16 + lrow8) * 48) + khalf;
            ldsm4(bh[2 * p][0], bh[2 * p + 1][0], bh[2 * p][1], bh[2 * p + 1][1], pb);
            ldsm4(bm[2 * p][0], bm[2 * p + 1][0], bm[2 * p][1], bm[2 * p + 1][1],
                  pb + PLANE);
        }
#pragma unroll
        for (int ni = 0; ni < 8; ni++)
#pragma unroll
            for (int mi = 0; mi < 2; mi++) {
                mma_f16(acc[mi][ni], ah[mi], bh[ni][0], bh[ni][1]);
                mma_f16(acc[mi][ni], am[mi], bh[ni][0], bh[ni][1]);
                mma_f16(acc[mi][ni], ah[mi], bm[ni][0], bm[ni][1]);
            }
    }
#pragma unroll
    for (int mi = 0; mi < 2; mi++) {
        int r = mt * 128 + wm + mi * 16 + grp;
        int b0 = r >> 5, c0 = r & 31;
        int r1 = r + 8;
        int b1 = r1 >> 5, c1 = r1 & 31;
        float* y0 = g_Yt + ((size_t)(b0 * H + h)) * LSEQ + c0 * CL;
        float* y1 = g_Yt + ((size_t)(b1 * H + h)) * LSEQ + c1 * CL;
#pragma unroll
        for (int ni = 0; ni < 8; ni++) {
            int n = wn + ni * 8 + tq * 2;
            *(float2*)(y0 + n) = make_float2(acc[mi][ni][0], acc[mi][ni][1]);
            *(float2*)(y1 + n) = make_float2(acc[mi][ni][2], acc[mi][ni][3]);
        }
    }
}

// =====================================================================
// ytrans: (B,H,L) fp32 raw y -> GELU -> (B,L,H) fp16 hi (single plane)
// =====================================================================
__global__ __launch_bounds__(256) void ytrans() {
    __shared__ float tile[32][33];
    int b = blockIdx.z, h0 = blockIdx.y * 32, l0 = blockIdx.x * 32;
    int tx = threadIdx.x, ty = threadIdx.y;
#pragma unroll
    for (int j = 0; j < 32; j += 8)
        tile[ty + j][tx] = g_Yt[((size_t)(b * H + h0 + ty + j)) * LSEQ + l0 + tx];
    __syncthreads();
#pragma unroll
    for (int j = 0; j < 32; j += 8) {
        float v = tile[tx][ty + j];
        v = 0.5f * v * (1.0f + erff(v * 0.70710678118654752f));
        size_t o = ((size_t)b * LSEQ + l0 + ty + j) * H + h0 + tx;
        g_Yhi[o] = __float2half_rn(v);
    }
}

// =====================================================================
// W prep: interleave rows (2i <- a-row i, 2i+1 <- g-row i+H), fp16 hi only.
// =====================================================================
__global__ __launch_bounds__(256) void w_prep(const float* __restrict__ W,
                                              const float* __restrict__ bp) {
    size_t i = (size_t)blockIdx.x * 256 + threadIdx.x;
    int col = (int)(i % H);
    int k   = (int)((i / H) % (2 * H));
    int l   = (int)(i / ((size_t)H * 2 * H));
    int orig = (k >> 1) + (k & 1) * H;
    float v = W[((size_t)l * 2 * H + orig) * H + col];
    g_Whi[i] = __float2half_rn(v);
    if (i < NLAY * 2 * H) {
        int kk = (int)(i % (2 * H));
        int ll = (int)(i / (2 * H));
        int og = (kk >> 1) + (kk & 1) * H;
        g_bint[i] = bp[ll * 2 * H + og];
    }
}

// =====================================================================
// conv GEMM + fused GLU: fp16 1-TERM (Yhi * Whi).
// CTA tile 128x128, K-tile 16, 3-stage, stage = 12288B.
// =====================================================================
#define C_BOFF  6144u
#define C_STAGE 12288u
#define C_DSMEM (3 * C_STAGE)   /* 36864 */

__global__ __launch_bounds__(256, 2) void conv_gemm(int layer)
{
    extern __shared__ __align__(16) char dsm[];
    int tid = threadIdx.x;
    int warp = tid >> 5, lane = tid & 31;
    int grp = lane >> 2, tq = lane & 3;
    int n0 = blockIdx.x * 128, m0 = blockIdx.y * 128;

    const __half* Wh = g_Whi + (size_t)layer * 2 * H * H;

    int wm = (warp >> 1) * 32, wn = (warp & 1) * 64;
    int lrow8 = (lane & 7) + (lane & 8);
    int khalf = (lane >> 4) * 16;

    float acc[2][8][4];
#pragma unroll
    for (int mi = 0; mi < 2; mi++)
#pragma unroll
        for (int ni = 0; ni < 8; ni++)
#pragma unroll
            for (int r = 0; r < 4; r++) acc[mi][ni][r] = 0.0f;

    int fr = tid >> 1, fch = tid & 1;

#define LOAD_C(KT, S)                                                              \
    do {                                                                           \
        char* sb = dsm + (unsigned)(S) * C_STAGE + (unsigned)(fr * 48 + fch * 16); \
        size_t soA = (size_t)(m0 + fr) * H + (KT) * 16 + fch * 8;                  \
        size_t soB = (size_t)(n0 + fr) * H + (KT) * 16 + fch * 8;                  \
        cpa16(sb,          g_Yhi + soA);                                           \
        cpa16(sb + C_BOFF, Wh + soB);                                              \
        asm volatile("cp.async.commit_group;" ::: "memory");                       \
    } while (0)

    LOAD_C(0, 0);
    LOAD_C(1, 1);

    const int NKT = H / 16;   // 32
    for (int kt = 0; kt < NKT; kt++) {
        int s = kt - (kt / 3) * 3;
        if (kt + 2 < NKT) asm volatile("cp.async.wait_group 1;" ::: "memory");
        else              asm volatile("cp.async.wait_group 0;" ::: "memory");
        __syncthreads();
        if (kt + 2 < NKT) {
            int s2 = (kt + 2) - ((kt + 2) / 3) * 3;
            LOAD_C(kt + 2, s2);
        }
        const char* sb = dsm + (unsigned)s * C_STAGE;
        uint32_t ah[2][4];
#pragma unroll
        for (int mi = 0; mi < 2; mi++) {
            const char* pa = sb + (unsigned)((wm + mi * 16 + lrow8) * 48) + khalf;
            ldsm4(ah[mi][0], ah[mi][1], ah[mi][2], ah[mi][3], pa);
        }
        uint32_t bh[8][2];
#pragma unroll
        for (int p = 0; p < 4; p++) {
            const char* pb = sb + C_BOFF + (unsigned)((wn + p * 16 + lrow8) * 48) + khalf;
            ldsm4(bh[2 * p][0], bh[2 * p + 1][0], bh[2 * p][1], bh[2 * p + 1][1], pb);
        }
#pragma unroll
        for (int ni = 0; ni < 8; ni++)
#pragma unroll
            for (int mi = 0; mi < 2; mi++)
                mma_f16(acc[mi][ni], ah[mi], bh[ni][0], bh[ni][1]);
    }
#pragma unroll
    for (int mi = 0; mi < 2; mi++)
#pragma unroll
        for (int ni = 0; ni < 8; ni++) {
            int r  = m0 + wm + mi * 16 + grp;
            int cb = wn + ni * 8 + tq * 2;
            float ba = g_bint[layer * 2 * H + n0 + cb];
            float bg = g_bint[layer * 2 * H + n0 + cb + 1];
            float a0 = acc[mi][ni][0] + ba, gg0 = acc[mi][ni][1] + bg;
            float a1 = acc[mi][ni][2] + ba, gg1 = acc[mi][ni][3] + bg;
            int hidx = (n0 + cb) >> 1;
            g_Z[(size_t)r * H + hidx]       = a0 / (1.0f + expf(-gg0));
            g_Z[(size_t)(r + 8) * H + hidx] = a1 / (1.0f + expf(-gg1));
        }
}

// =====================================================================
// Residual + LayerNorm. warp per row.
// =====================================================================
__global__ __launch_bounds__(128) void res_ln(
    const float* __restrict__ xin, float* __restrict__ xout,
    const float* __restrict__ gamma, const float* __restrict__ beta, int layer)
{
    int row  = blockIdx.x * 4 + (threadIdx.x >> 5);
    int lane = threadIdx.x & 31;
    const float4* z4 = (const float4*)(g_Z + (size_t)row * H);
    const float4* x4 = (const float4*)(xin + (size_t)row * H);
    float4* o4       = (float4*)(xout + (size_t)row * H);
    const float4* g4 = (const float4*)(gamma + layer * H);
    const float4* e4 = (const float4*)(beta + layer * H);

    float4 v[4];
    float s = 0.0f, s2 = 0.0f;
#pragma unroll
    for (int j = 0; j < 4; j++) {
        float4 zz = z4[j * 32 + lane];
        float4 xv = x4[j * 32 + lane];
        float4 vv;
        vv.x = zz.x + xv.x; vv.y = zz.y + xv.y;
        vv.z = zz.z + xv.z; vv.w = zz.w + xv.w;
        v[j] = vv;
        s += vv.x + vv.y + vv.z + vv.w;
        s2 = fmaf(vv.x, vv.x, s2); s2 = fmaf(vv.y, vv.y, s2);
        s2 = fmaf(vv.z, vv.z, s2); s2 = fmaf(vv.w, vv.w, s2);
    }
#pragma unroll
    for (int o = 16; o; o >>= 1) {
        s  += __shfl_xor_sync(0xffffffffu, s, o);
        s2 += __shfl_xor_sync(0xffffffffu, s2, o);
    }
    float mu = s * (1.0f / H);
    float rs = rsqrtf(s2 * (1.0f / H) - mu * mu + LN_EPS);
#pragma unroll
    for (int j = 0; j < 4; j++) {
        float4 ga = g4[j * 32 + lane];
        float4 be = e4[j * 32 + lane];
        float4 vv = v[j], o;
        o.x = (vv.x - mu) * rs * ga.x + be.x;
        o.y = (vv.y - mu) * rs * ga.y + be.y;
        o.z = (vv.z - mu) * rs * ga.z + be.z;
        o.w = (vv.w - mu) * rs * ga.w + be.w;
        o4[j * 32 + lane] = o;
    }
}

// ================= launcher =================
extern "C" void kernel_launch(void* const* d_in, const int* in_sizes, int n_in,
                              void* d_out, int out_size)
{
    const float* x          = (const float*)d_in[0];
    const float* log_dt     = (const float*)d_in[1];
    const float* A_imag     = (const float*)d_in[2];
    const float* log_A_real = (const float*)d_in[3];
    const float* C          = (const float*)d_in[4];
    const float* D          = (const float*)d_in[5];
    const float* W          = (const float*)d_in[6];
    const float* bconv      = (const float*)d_in[7];
    const float* gamma      = (const float*)d_in[8];
    const float* beta       = (const float*)d_in[9];
    float* out = (float*)d_out;

    cudaFuncSetAttribute(conv_gemm, cudaFuncAttributeMaxDynamicSharedMemorySize,
                         C_DSMEM);
    cudaFuncSetAttribute(gemm_toep, cudaFuncAttributeMaxDynamicSharedMemorySize,
                         T_DSMEM);
    cudaFuncSetAttribute(gemm_end, cudaFuncAttributeMaxDynamicSharedMemorySize,
                         E_DSMEM);

    float* pA; cudaGetSymbolAddress((void**)&pA, g_xA);
    float* pB; cudaGetSymbolAddress((void**)&pB, g_xB);
    const float* xin[NLAY]  = {x,  pA, pB, pA};
    float*       xout[NLAY] = {pA, pB, pA, out};

    w_prep<<<(NLAY * 2 * H * H) / 256, 256>>>(W, bconv);

    dim3 tb(32, 8);
    for (int i = 0; i < NLAY; i++) {
        xsplit<<<dim3(H / 32, LSEQ / 32, BSZ), tb>>>(xin[i]);
        tbuild<<<H, 256>>>(log_dt, A_imag, log_A_real, C, D, i);
        gemm_end<<<dim3(2, H), 256, E_DSMEM>>>();
        ssm_prefix2<<<(H * BSZ * 8) / 256, 256>>>(log_dt, A_imag, log_A_real, i);
        gemm_toep<<<dim3(2, H), 256, T_DSMEM>>>();
        ytrans<<<dim3(LSEQ / 32, H / 32, BSZ), tb>>>();
        conv_gemm<<<dim3(2 * H / 128, MROWS / 128), 256, C_DSMEM>>>(i);
        res_ln<<<MROWS / 4, 128>>>(xin[i], xout[i], gamma, beta, i);
    }
}

// round 12
// speedup vs baseline: 1.9079x; 1.0778x over previous
#include <cuda_runtime.h>
#include <cuda_fp16.h>
#include <cstdint>

#define H     512
#define NLAY  4
#define N2    32
#define BSZ   8
#define LSEQ  4096
#define MROWS (BSZ * LSEQ)      /* 32768 */
#define NC    32                /* chunks per sequence */
#define CL    (LSEQ / NC)       /* 128 */
#define NINST (BSZ * NC)        /* 256 instances per h */
#define LN_EPS 1e-5f

// ---- static scratch. activations (B,L,H) row-major unless noted ----
__device__ __align__(256) float g_xA[(size_t)MROWS * H];
__device__ __align__(256) float g_xB[(size_t)MROWS * H];
__device__ __align__(256) __half g_Uhi [(size_t)MROWS * H];   // u (B,H,L)
__device__ __align__(256) __half g_Umid[(size_t)MROWS * H];
__device__ __align__(256) __half g_Yhi [(size_t)MROWS * H];   // gelu(y) (B,L,H)
__device__ __align__(256) __half g_Yt16[(size_t)MROWS * H];   // gelu(y) (B,H,L)
__device__ __align__(256) __half g_Whi[(size_t)NLAY * 2 * H * H];
__device__ __align__(256) float g_bint[NLAY * 2 * H];
__device__ __align__(256) float g_Z[(size_t)MROWS * H];       // GLU out (B,L,H)
// Toeplitz machinery (per-layer rebuilt)
__device__ __align__(256) __half g_T2hi[(size_t)H * CL * 192];  // B2 [h][n=l][k]
__device__ __align__(256) __half g_T1hi[(size_t)H * 64 * CL];   // B1 [h][e][j]
__device__ __align__(256) float g_E2[(size_t)H * NINST * 64];    // end states
__device__ __align__(256) __half g_Shi [(size_t)H * NINST * 64]; // init states
__device__ __align__(256) __half g_Smid[(size_t)H * NINST * 64];

// ---------------- helpers ----------------
__device__ __forceinline__ void cpa16(void* dst, const void* src) {
    unsigned d = (unsigned)__cvta_generic_to_shared(dst);
    asm volatile("cp.async.cg.shared.global [%0], [%1], 16;" :: "r"(d), "l"(src));
}
__device__ __forceinline__ void ldsm4(uint32_t& r0, uint32_t& r1, uint32_t& r2,
                                      uint32_t& r3, const void* p) {
    uint32_t a = (uint32_t)__cvta_generic_to_shared(p);
    asm volatile("ldmatrix.sync.aligned.m8n8.x4.shared.b16 {%0,%1,%2,%3}, [%4];"
                 : "=r"(r0), "=r"(r1), "=r"(r2), "=r"(r3) : "r"(a));
}
__device__ __forceinline__ void mma_f16(float* d, const uint32_t* a,
                                        uint32_t b0, uint32_t b1) {
    asm volatile(
        "mma.sync.aligned.m16n8k16.row.col.f32.f16.f16.f32 "
        "{%0,%1,%2,%3}, {%4,%5,%6,%7}, {%8,%9}, {%0,%1,%2,%3};"
        : "+f"(d[0]), "+f"(d[1]), "+f"(d[2]), "+f"(d[3])
        : "r"(a[0]), "r"(a[1]), "r"(a[2]), "r"(a[3]), "r"(b0), "r"(b1));
}
__device__ __forceinline__ void hsplit(float v, __half* hi_p, __half* mid_p) {
    __half hi = __float2half_rn(v);
    *hi_p = hi;
    *mid_p = __float2half_rn(v - __half2float(hi));
}
__device__ __forceinline__ float gelu_f(float v) {
    return 0.5f * v * (1.0f + erff(v * 0.70710678118654752f));
}

__device__ __forceinline__ void scan_coeffs(
    const float* log_dt, const float* A_imag, const float* log_A_real,
    int layer, int h, int li, float* Are_o, float* Aim_o, float* dt_o)
{
    float dt = expf(log_dt[layer * H + h]);
    int pbase = (layer * H + h) * N2 + li * 4;
    float4 aim = *(const float4*)(A_imag + pbase);
    float4 lar = *(const float4*)(log_A_real + pbase);
    float aimv[4] = {aim.x, aim.y, aim.z, aim.w};
    float larv[4] = {lar.x, lar.y, lar.z, lar.w};
#pragma unroll
    for (int j = 0; j < 4; j++) {
        Are_o[j] = -expf(larv[j]);
        Aim_o[j] = aimv[j];
    }
    *dt_o = dt;
}

// =====================================================================
// xsplit: (B,L,H) fp32 -> (B,H,L) fp16 hi/mid
// =====================================================================
__global__ __launch_bounds__(256) void xsplit(const float* __restrict__ x) {
    __shared__ float tile[32][33];
    int b = blockIdx.z, h0 = blockIdx.x * 32, l0 = blockIdx.y * 32;
    int tx = threadIdx.x, ty = threadIdx.y;
#pragma unroll
    for (int j = 0; j < 32; j += 8)
        tile[ty + j][tx] = x[((size_t)b * LSEQ + l0 + ty + j) * H + h0 + tx];
    __syncthreads();
#pragma unroll
    for (int j = 0; j < 32; j += 8) {
        float v = tile[tx][ty + j];
        size_t o = ((size_t)(b * H + h0 + ty + j)) * LSEQ + l0 + tx;
        hsplit(v, g_Uhi + o, g_Umid + o);
    }
}

// =====================================================================
// tbuild: per-h Toeplitz kernel k[d], correction matrix V, end-state E.
// hi planes only.
// =====================================================================
__global__ __launch_bounds__(256) void tbuild(
    const float* __restrict__ log_dt, const float* __restrict__ A_imag,
    const float* __restrict__ log_A_real, const float* __restrict__ Cp,
    const float* __restrict__ Dp, int layer)
{
    __shared__ float wr[CL + 1][32], wi[CL + 1][32];
    __shared__ float scfr[32], scfi[32], skern[CL];
    __shared__ float sD;
    int h = blockIdx.x;
    int t = threadIdx.x;
    if (t == 0) sD = Dp[layer * H + h];
    if (t < 32) {
        int n = t;
        float dt = expf(log_dt[layer * H + h]);
        float Are = -expf(log_A_real[(layer * H + h) * N2 + n]);
        float Aim = A_imag[(layer * H + h) * N2 + n];
        float e1 = expf(Are * dt);
        float w1r = e1 * cosf(Aim * dt), w1i = e1 * sinf(Aim * dt);
        float nr = w1r - 1.0f, ni = w1i;
        float cr = Cp[((layer * H + h) * N2 + n) * 2 + 0];
        float ci = Cp[((layer * H + h) * N2 + n) * 2 + 1];
        float tr = cr * nr - ci * ni;
        float ti = cr * ni + ci * nr;
        float inv = 2.0f / (Are * Are + Aim * Aim);
        scfr[n] = (tr * Are + ti * Aim) * inv;
        scfi[n] = (ti * Are - tr * Aim) * inv;
        float pr = 1.0f, pi = 0.0f;
        for (int d = 0; d <= CL; d++) {
            wr[d][n] = pr; wi[d][n] = pi;
            float npr = pr * w1r - pi * w1i;
            float npi = pr * w1i + pi * w1r;
            pr = npr; pi = npi;
        }
    }
    __syncthreads();
    if (t < CL) {
        float acc = (t == 0) ? sD : 0.0f;
#pragma unroll 8
        for (int n = 0; n < 32; n++)
            acc += scfr[n] * wr[t][n] - scfi[n] * wi[t][n];
        skern[t] = acc;
    }
    __syncthreads();
    for (int idx = t; idx < CL * CL; idx += 256) {
        int n = idx >> 7, k = idx & 127;
        float v = (k <= n) ? skern[n - k] : 0.0f;
        g_T2hi[((size_t)h * CL + n) * 192 + k] = __float2half_rn(v);
    }
    for (int idx = t; idx < CL * 64; idx += 256) {
        int n = idx >> 6, e = idx & 63, ns = e >> 1;
        float cwr = scfr[ns] * wr[n + 1][ns] - scfi[ns] * wi[n + 1][ns];
        float cwi = scfr[ns] * wi[n + 1][ns] + scfi[ns] * wr[n + 1][ns];
        float v = (e & 1) ? -cwi : cwr;
        g_T2hi[((size_t)h * CL + n) * 192 + 128 + e] = __float2half_rn(v);
    }
    for (int idx = t; idx < 64 * CL; idx += 256) {
        int e = idx >> 7, j = idx & 127, ns = e >> 1;
        int d = CL - 1 - j;
        float v = (e & 1) ? wi[d][ns] : wr[d][ns];
        g_T1hi[((size_t)h * 64 + e) * CL + j] = __float2half_rn(v);
    }
}

// =====================================================================
// gemm_end: per h, S_end[NINST x 64] = U[NINST x 128] @ B1^T.
// 1-term: Uhi * B1hi.
// =====================================================================
#define E_BOFF  6144u
#define E_STAGE 9216u
#define E_DSMEM (3 * E_STAGE)   /* 27648 */

__global__ __launch_bounds__(256, 2) void gemm_end()
{
    extern __shared__ __align__(16) char dsmE[];
    int tid = threadIdx.x;
    int warp = tid >> 5, lane = tid & 31;
    int grp = lane >> 2, tq = lane & 3;
    int mt = blockIdx.x, h = blockIdx.y;
    int wm = (warp >> 1) * 32, wn = (warp & 1) * 32;
    int lrow8 = (lane & 7) + (lane & 8);
    int khalf = (lane >> 4) * 16;

    int mloc = tid >> 1, ch = tid & 1;
    int m = mt * 128 + mloc;
    int bb = m >> 5, cc = m & 31;
    const __half* aUh = g_Uhi + ((size_t)(bb * H + h)) * LSEQ + cc * CL;
    int frB = (tid & 127) >> 1, chB = tid & 1;
    const __half* bTh = g_T1hi + (size_t)h * 64 * CL;

    float acc[2][4][4];
#pragma unroll
    for (int mi = 0; mi < 2; mi++)
#pragma unroll
        for (int ni = 0; ni < 4; ni++)
#pragma unroll
            for (int r = 0; r < 4; r++) acc[mi][ni][r] = 0.0f;

#define LOAD_E(KT, S)                                                            \
    do {                                                                         \
        char* sb = dsmE + (unsigned)(S) * E_STAGE;                               \
        int k0 = (KT) * 16 + ch * 8;                                             \
        cpa16(sb + (unsigned)(mloc * 48 + ch * 16), aUh + k0);                   \
        if (tid < 128) {                                                         \
            int kb = (KT) * 16 + chB * 8;                                        \
            cpa16(sb + E_BOFF + (unsigned)(frB * 48 + chB * 16),                 \
                  bTh + (size_t)frB * CL + kb);                                  \
        }                                                                        \
        asm volatile("cp.async.commit_group;" ::: "memory");                     \
    } while (0)

    LOAD_E(0, 0);
    LOAD_E(1, 1);
    const int NKT = 8;
    for (int kt = 0; kt < NKT; kt++) {
        int s = kt - (kt / 3) * 3;
        if (kt + 2 < NKT) asm volatile("cp.async.wait_group 1;" ::: "memory");
        else              asm volatile("cp.async.wait_group 0;" ::: "memory");
        __syncthreads();
        if (kt + 2 < NKT) {
            int s2 = (kt + 2) - ((kt + 2) / 3) * 3;
            LOAD_E(kt + 2, s2);
        }
        const char* sb = dsmE + (unsigned)s * E_STAGE;
        uint32_t ah[2][4];
#pragma unroll
        for (int mi = 0; mi < 2; mi++) {
            const char* pa = sb + (unsigned)((wm + mi * 16 + lrow8) * 48) + khalf;
            ldsm4(ah[mi][0], ah[mi][1], ah[mi][2], ah[mi][3], pa);
        }
        uint32_t bh[4][2];
#pragma unroll
        for (int p = 0; p < 2; p++) {
            const char* pb = sb + E_BOFF + (unsigned)((wn + p * 16 + lrow8) * 48) + khalf;
            ldsm4(bh[2 * p][0], bh[2 * p + 1][0], bh[2 * p][1], bh[2 * p + 1][1], pb);
        }
#pragma unroll
        for (int ni = 0; ni < 4; ni++)
#pragma unroll
            for (int mi = 0; mi < 2; mi++)
                mma_f16(acc[mi][ni], ah[mi], bh[ni][0], bh[ni][1]);
    }
#pragma unroll
    for (int mi = 0; mi < 2; mi++)
#pragma unroll
        for (int ni = 0; ni < 4; ni++) {
            int r = mt * 128 + wm + mi * 16 + grp;
            int n = wn + ni * 8 + tq * 2;
            float2 v0 = {acc[mi][ni][0], acc[mi][ni][1]};
            float2 v1 = {acc[mi][ni][2], acc[mi][ni][3]};
            *(float2*)&g_E2[((size_t)h * NINST + r) * 64 + n] = v0;
            *(float2*)&g_E2[((size_t)h * NINST + r + 8) * 64 + n] = v1;
        }
}

// =====================================================================
// prefix: combine chunk end states -> per-chunk init states (fp16 split)
// =====================================================================
__global__ __launch_bounds__(256) void ssm_prefix2(
    const float* __restrict__ log_dt, const float* __restrict__ A_imag,
    const float* __restrict__ log_A_real, int layer)
{
    int idx = blockIdx.x * 256 + threadIdx.x;
    int li = idx & 7;
    int b  = (idx >> 3) & 7;
    int h  = idx >> 6;

    float Are[4], Aim[4], dt;
    scan_coeffs(log_dt, A_imag, log_A_real, layer, h, li, Are, Aim, &dt);
    float Wr[4], Wi[4];
#pragma unroll
    for (int j = 0; j < 4; j++) {
        float e = expf(Are[j] * dt * (float)CL);
        Wr[j] = e * cosf(Aim[j] * dt * (float)CL);
        Wi[j] = e * sinf(Aim[j] * dt * (float)CL);
    }
    float Ire[4] = {0, 0, 0, 0}, Iim[4] = {0, 0, 0, 0};
    for (int c = 0; c < NC; c++) {
        size_t off = ((size_t)h * NINST + b * NC + c) * 64 + li * 8;
#pragma unroll
        for (int j = 0; j < 4; j++) {
            hsplit(Ire[j], g_Shi + off + 2 * j,     g_Smid + off + 2 * j);
            hsplit(Iim[j], g_Shi + off + 2 * j + 1, g_Smid + off + 2 * j + 1);
        }
        float4 e0 = *(const float4*)(g_E2 + off);
        float4 e1 = *(const float4*)(g_E2 + off + 4);
        float er[4] = {e0.x, e0.z, e1.x, e1.z};
        float ei[4] = {e0.y, e0.w, e1.y, e1.w};
#pragma unroll
        for (int j = 0; j < 4; j++) {
            float nr = fmaf(Wr[j], Ire[j], fmaf(-Wi[j], Iim[j], er[j]));
            float ni = fmaf(Wi[j], Ire[j], fmaf( Wr[j], Iim[j], ei[j]));
            Ire[j] = nr; Iim[j] = ni;
        }
    }
}

// =====================================================================
// gemm_toep: per h, Y[NINST x 128] = [U|Sinit][NINST x 192] @ B2hi^T.
// 2-term: (Ahi + Amid) * Bhi. Epilogue: GELU + fp16 store (B,H,L).
// =====================================================================
#define PLANE 6144u
#define BOFF  12288u
#define STAGE 18432u
#define T_DSMEM (3 * STAGE)     /* 55296 */

__global__ __launch_bounds__(256, 2) void gemm_toep()
{
    extern __shared__ __align__(16) char dsmT[];
    int tid = threadIdx.x;
    int warp = tid >> 5, lane = tid & 31;
    int grp = lane >> 2, tq = lane & 3;
    int mt = blockIdx.x, h = blockIdx.y;
    int wm = (warp >> 1) * 32, wn = (warp & 1) * 64;
    int lrow8 = (lane & 7) + (lane & 8);
    int khalf = (lane >> 4) * 16;

    int mloc = tid >> 1, ch = tid & 1;
    int m = mt * 128 + mloc;
    int bb = m >> 5, cc = m & 31;
    const __half* aUh = g_Uhi  + ((size_t)(bb * H + h)) * LSEQ + cc * CL;
    const __half* aUm = g_Umid + ((size_t)(bb * H + h)) * LSEQ + cc * CL;
    const __half* aSh = g_Shi  + ((size_t)h * NINST + m) * 64;
    const __half* aSm = g_Smid + ((size_t)h * NINST + m) * 64;
    const __half* bTh = g_T2hi + (size_t)h * CL * 192;

    float acc[2][8][4];
#pragma unroll
    for (int mi = 0; mi < 2; mi++)
#pragma unroll
        for (int ni = 0; ni < 8; ni++)
#pragma unroll
            for (int r = 0; r < 4; r++) acc[mi][ni][r] = 0.0f;

#define LOAD_T(KT, S)                                                            \
    do {                                                                         \
        char* sb = dsmT + (unsigned)(S) * STAGE;                                 \
        int k0 = (KT) * 16 + ch * 8;                                             \
        const __half* sh = (k0 < 128) ? aUh + k0 : aSh + (k0 - 128);             \
        const __half* sm = (k0 < 128) ? aUm + k0 : aSm + (k0 - 128);             \
        char* pa = sb + (unsigned)(mloc * 48 + ch * 16);                         \
        cpa16(pa,         sh);                                                   \
        cpa16(pa + PLANE, sm);                                                   \
        cpa16(sb + BOFF + (unsigned)(mloc * 48 + ch * 16),                       \
              bTh + (size_t)mloc * 192 + k0);                                    \
        asm volatile("cp.async.commit_group;" ::: "memory");                     \
    } while (0)

    LOAD_T(0, 0);
    LOAD_T(1, 1);
    const int NKT = 12;
    for (int kt = 0; kt < NKT; kt++) {
        int s = kt - (kt / 3) * 3;
        if (kt + 2 < NKT) asm volatile("cp.async.wait_group 1;" ::: "memory");
        else              asm volatile("cp.async.wait_group 0;" ::: "memory");
        __syncthreads();
        if (kt + 2 < NKT) {
            int s2 = (kt + 2) - ((kt + 2) / 3) * 3;
            LOAD_T(kt + 2, s2);
        }
        const char* sb = dsmT + (unsigned)s * STAGE;
        uint32_t ah[2][4], am[2][4];
#pragma unroll
        for (int mi = 0; mi < 2; mi++) {
            const char* pa = sb + (unsigned)((wm + mi * 16 + lrow8) * 48) + khalf;
            ldsm4(ah[mi][0], ah[mi][1], ah[mi][2], ah[mi][3], pa);
            ldsm4(am[mi][0], am[mi][1], am[mi][2], am[mi][3], pa + PLANE);
        }
        uint32_t bh[8][2];
#pragma unroll
        for (int p = 0; p < 4; p++) {
            const char* pb = sb + BOFF + (unsigned)((wn + p * 16 + lrow8) * 48) + khalf;
            ldsm4(bh[2 * p][0], bh[2 * p + 1][0], bh[2 * p][1], bh[2 * p + 1][1], pb);
        }
#pragma unroll
        for (int ni = 0; ni < 8; ni++)
#pragma unroll
            for (int mi = 0; mi < 2; mi++) {
                mma_f16(acc[mi][ni], ah[mi], bh[ni][0], bh[ni][1]);
                mma_f16(acc[mi][ni], am[mi], bh[ni][0], bh[ni][1]);
            }
    }
    // epilogue: GELU + fp16 store to (B,H,L)
#pragma unroll
    for (int mi = 0; mi < 2; mi++) {
        int r = mt * 128 + wm + mi * 16 + grp;
        int b0 = r >> 5, c0 = r & 31;
        int r1 = r + 8;
        int b1 = r1 >> 5, c1 = r1 & 31;
        __half* y0 = g_Yt16 + ((size_t)(b0 * H + h)) * LSEQ + c0 * CL;
        __half* y1 = g_Yt16 + ((size_t)(b1 * H + h)) * LSEQ + c1 * CL;
#pragma unroll
        for (int ni = 0; ni < 8; ni++) {
            int n = wn + ni * 8 + tq * 2;
            __half2 v0 = __floats2half2_rn(gelu_f(acc[mi][ni][0]),
                                           gelu_f(acc[mi][ni][1]));
            __half2 v1 = __floats2half2_rn(gelu_f(acc[mi][ni][2]),
                                           gelu_f(acc[mi][ni][3]));
            *(__half2*)(y0 + n) = v0;
            *(__half2*)(y1 + n) = v1;
        }
    }
}

// =====================================================================
// ytrans: (B,H,L) fp16 -> (B,L,H) fp16 (pure transpose)
// =====================================================================
__global__ __launch_bounds__(256) void ytrans() {
    __shared__ __half tile[32][40];
    int b = blockIdx.z, h0 = blockIdx.y * 32, l0 = blockIdx.x * 32;
    int tx = threadIdx.x, ty = threadIdx.y;
#pragma unroll
    for (int j = 0; j < 32; j += 8)
        tile[ty + j][tx] = g_Yt16[((size_t)(b * H + h0 + ty + j)) * LSEQ + l0 + tx];
    __syncthreads();
#pragma unroll
    for (int j = 0; j < 32; j += 8)
        g_Yhi[((size_t)b * LSEQ + l0 + ty + j) * H + h0 + tx] = tile[tx][ty + j];
}

// =====================================================================
// W prep: interleave rows (2i <- a-row i, 2i+1 <- g-row i+H), fp16 hi only.
// =====================================================================
__global__ __launch_bounds__(256) void w_prep(const float* __restrict__ W,
                                              const float* __restrict__ bp) {
    size_t i = (size_t)blockIdx.x * 256 + threadIdx.x;
    int col = (int)(i % H);
    int k   = (int)((i / H) % (2 * H));
    int l   = (int)(i / ((size_t)H * 2 * H));
    int orig = (k >> 1) + (k & 1) * H;
    float v = W[((size_t)l * 2 * H + orig) * H + col];
    g_Whi[i] = __float2half_rn(v);
    if (i < NLAY * 2 * H) {
        int kk = (int)(i % (2 * H));
        int ll = (int)(i / (2 * H));
        int og = (kk >> 1) + (kk & 1) * H;
        g_bint[i] = bp[ll * 2 * H + og];
    }
}

// =====================================================================
// conv GEMM + fused GLU: fp16 1-TERM (Yhi * Whi).
// =====================================================================
#define C_BOFF  6144u
#define C_STAGE 12288u
#define C_DSMEM (3 * C_STAGE)   /* 36864 */

__global__ __launch_bounds__(256, 2) void conv_gemm(int layer)
{
    extern __shared__ __align__(16) char dsm[];
    int tid = threadIdx.x;
    int warp = tid >> 5, lane = tid & 31;
    int grp = lane >> 2, tq = lane & 3;
    int n0 = blockIdx.x * 128, m0 = blockIdx.y * 128;

    const __half* Wh = g_Whi + (size_t)layer * 2 * H * H;

    int wm = (warp >> 1) * 32, wn = (warp & 1) * 64;
    int lrow8 = (lane & 7) + (lane & 8);
    int khalf = (lane >> 4) * 16;

    float acc[2][8][4];
#pragma unroll
    for (int mi = 0; mi < 2; mi++)
#pragma unroll
        for (int ni = 0; ni < 8; ni++)
#pragma unroll
            for (int r = 0; r < 4; r++) acc[mi][ni][r] = 0.0f;

    int fr = tid >> 1, fch = tid & 1;

#define LOAD_C(KT, S)                                                              \
    do {                                                                           \
        char* sb = dsm + (unsigned)(S) * C_STAGE + (unsigned)(fr * 48 + fch * 16); \
        size_t soA = (size_t)(m0 + fr) * H + (KT) * 16 + fch * 8;                  \
        size_t soB = (size_t)(n0 + fr) * H + (KT) * 16 + fch * 8;                  \
        cpa16(sb,          g_Yhi + soA);                                           \
        cpa16(sb + C_BOFF, Wh + soB);                                              \
        asm volatile("cp.async.commit_group;" ::: "memory");                       \
    } while (0)

    LOAD_C(0, 0);
    LOAD_C(1, 1);

    const int NKT = H / 16;   // 32
    for (int kt = 0; kt < NKT; kt++) {
        int s = kt - (kt / 3) * 3;
        if (kt + 2 < NKT) asm volatile("cp.async.wait_group 1;" ::: "memory");
        else              asm volatile("cp.async.wait_group 0;" ::: "memory");
        __syncthreads();
        if (kt + 2 < NKT) {
            int s2 = (kt + 2) - ((kt + 2) / 3) * 3;
            LOAD_C(kt + 2, s2);
        }
        const char* sb = dsm + (unsigned)s * C_STAGE;
        uint32_t ah[2][4];
#pragma unroll
        for (int mi = 0; mi < 2; mi++) {
            const char* pa = sb + (unsigned)((wm + mi * 16 + lrow8) * 48) + khalf;
            ldsm4(ah[mi][0], ah[mi][1], ah[mi][2], ah[mi][3], pa);
        }
        uint32_t bh[8][2];
#pragma unroll
        for (int p = 0; p < 4; p++) {
            const char* pb = sb + C_BOFF + (unsigned)((wn + p * 16 + lrow8) * 48) + khalf;
            ldsm4(bh[2 * p][0], bh[2 * p + 1][0], bh[2 * p][1], bh[2 * p + 1][1], pb);
        }
#pragma unroll
        for (int ni = 0; ni < 8; ni++)
#pragma unroll
            for (int mi = 0; mi < 2; mi++)
                mma_f16(acc[mi][ni], ah[mi], bh[ni][0], bh[ni][1]);
    }
#pragma unroll
    for (int mi = 0; mi < 2; mi++)
#pragma unroll
        for (int ni = 0; ni < 8; ni++) {
            int r  = m0 + wm + mi * 16 + grp;
            int cb = wn + ni * 8 + tq * 2;
            float ba = g_bint[layer * 2 * H + n0 + cb];
            float bg = g_bint[layer * 2 * H + n0 + cb + 1];
            float a0 = acc[mi][ni][0] + ba, gg0 = acc[mi][ni][1] + bg;
            float a1 = acc[mi][ni][2] + ba, gg1 = acc[mi][ni][3] + bg;
            int hidx = (n0 + cb) >> 1;
            g_Z[(size_t)r * H + hidx]       = a0 / (1.0f + expf(-gg0));
            g_Z[(size_t)(r + 8) * H + hidx] = a1 / (1.0f + expf(-gg1));
        }
}

// =====================================================================
// Residual + LayerNorm. warp per row.
// =====================================================================
__global__ __launch_bounds__(128) void res_ln(
    const float* __restrict__ xin, float* __restrict__ xout,
    const float* __restrict__ gamma, const float* __restrict__ beta, int layer)
{
    int row  = blockIdx.x * 4 + (threadIdx.x >> 5);
    int lane = threadIdx.x & 31;
    const float4* z4 = (const float4*)(g_Z + (size_t)row * H);
    const float4* x4 = (const float4*)(xin + (size_t)row * H);
    float4* o4       = (float4*)(xout + (size_t)row * H);
    const float4* g4 = (const float4*)(gamma + layer * H);
    const float4* e4 = (const float4*)(beta + layer * H);

    float4 v[4];
    float s = 0.0f, s2 = 0.0f;
#pragma unroll
    for (int j = 0; j < 4; j++) {
        float4 zz = z4[j * 32 + lane];
        float4 xv = x4[j * 32 + lane];
        float4 vv;
        vv.x = zz.x + xv.x; vv.y = zz.y + xv.y;
        vv.z = zz.z + xv.z; vv.w = zz.w + xv.w;
        v[j] = vv;
        s += vv.x + vv.y + vv.z + vv.w;
        s2 = fmaf(vv.x, vv.x, s2); s2 = fmaf(vv.y, vv.y, s2);
        s2 = fmaf(vv.z, vv.z, s2); s2 = fmaf(vv.w, vv.w, s2);
    }
#pragma unroll
    for (int o = 16; o; o >>= 1) {
        s  += __shfl_xor_sync(0xffffffffu, s, o);
        s2 += __shfl_xor_sync(0xffffffffu, s2, o);
    }
    float mu = s * (1.0f / H);
    float rs = rsqrtf(s2 * (1.0f / H) - mu * mu + LN_EPS);
#pragma unroll
    for (int j = 0; j < 4; j++) {
        float4 ga = g4[j * 32 + lane];
        float4 be = e4[j * 32 + lane];
        float4 vv = v[j], o;
        o.x = (vv.x - mu) * rs * ga.x + be.x;
        o.y = (vv.y - mu) * rs * ga.y + be.y;
        o.z = (vv.z - mu) * rs * ga.z + be.z;
        o.w = (vv.w - mu) * rs * ga.w + be.w;
        o4[j * 32 + lane] = o;
    }
}

// ================= launcher =================
extern "C" void kernel_launch(void* const* d_in, const int* in_sizes, int n_in,
                              void* d_out, int out_size)
{
    const float* x          = (const float*)d_in[0];
    const float* log_dt     = (const float*)d_in[1];
    const float* A_imag     = (const float*)d_in[2];
    const float* log_A_real = (const float*)d_in[3];
    const float* C          = (const float*)d_in[4];
    const float* D          = (const float*)d_in[5];
    const float* W          = (const float*)d_in[6];
    const float* bconv      = (const float*)d_in[7];
    const float* gamma      = (const float*)d_in[8];
    const float* beta       = (const float*)d_in[9];
    float* out = (float*)d_out;

    cudaFuncSetAttribute(conv_gemm, cudaFuncAttributeMaxDynamicSharedMemorySize,
                         C_DSMEM);
    cudaFuncSetAttribute(gemm_toep, cudaFuncAttributeMaxDynamicSharedMemorySize,
                         T_DSMEM);
    cudaFuncSetAttribute(gemm_end, cudaFuncAttributeMaxDynamicSharedMemorySize,
                         E_DSMEM);

    float* pA; cudaGetSymbolAddress((void**)&pA, g_xA);
    float* pB; cudaGetSymbolAddress((void**)&pB, g_xB);
    const float* xin[NLAY]  = {x,  pA, pB, pA};
    float*       xout[NLAY] = {pA, pB, pA, out};

    w_prep<<<(NLAY * 2 * H * H) / 256, 256>>>(W, bconv);

    dim3 tb(32, 8);
    for (int i = 0; i < NLAY; i++) {
        xsplit<<<dim3(H / 32, LSEQ / 32, BSZ), tb>>>(xin[i]);
        tbuild<<<H, 256>>>(log_dt, A_imag, log_A_real, C, D, i);
        gemm_end<<<dim3(2, H), 256, E_DSMEM>>>();
        ssm_prefix2<<<(H * BSZ * 8) / 256, 256>>>(log_dt, A_imag, log_A_real, i);
        gemm_toep<<<dim3(2, H), 256, T_DSMEM>>>();
        ytrans<<<dim3(LSEQ / 32, H / 32, BSZ), tb>>>();
        conv_gemm<<<dim3(2 * H / 128, MROWS / 128), 256, C_DSMEM>>>(i);
        res_ln<<<MROWS / 4, 128>>>(xin[i], xout[i], gamma, beta, i);
    }
}

// round 13
// speedup vs baseline: 2.1446x; 1.1241x over previous
#include <cuda_runtime.h>
#include <cuda_fp16.h>
#include <cstdint>

#define H     512
#define NLAY  4
#define N2    32
#define BSZ   8
#define LSEQ  4096
#define MROWS (BSZ * LSEQ)      /* 32768 */
#define NC    32                /* chunks per sequence */
#define CL    (LSEQ / NC)       /* 128 */
#define NINST (BSZ * NC)        /* 256 instances per h */
#define LN_EPS 1e-5f

// ---- static scratch. activations (B,L,H) row-major unless noted ----
__device__ __align__(256) float g_xA[(size_t)MROWS * H];
__device__ __align__(256) float g_xB[(size_t)MROWS * H];
__device__ __align__(256) __half g_Uhi [(size_t)MROWS * H];   // u (B,H,L)
__device__ __align__(256) __half g_Yhi [(size_t)MROWS * H];   // gelu(y) (B,L,H)
__device__ __align__(256) __half g_Yt16[(size_t)MROWS * H];   // gelu(y) (B,H,L)
__device__ __align__(256) __half g_Whi[(size_t)NLAY * 2 * H * H];
__device__ __align__(256) float g_bint[NLAY * 2 * H];
__device__ __align__(256) float g_Z[(size_t)MROWS * H];       // GLU out (B,L,H)
// Toeplitz machinery (per-layer rebuilt)
__device__ __align__(256) __half g_T2hi[(size_t)H * CL * 192];  // B2 [h][n=l][k]
__device__ __align__(256) __half g_T1hi[(size_t)H * 64 * CL];   // B1 [h][e][j]
__device__ __align__(256) __half g_E2h[(size_t)H * NINST * 64]; // end states (fp16)
__device__ __align__(256) __half g_Shi[(size_t)H * NINST * 64]; // init states

// ---------------- helpers ----------------
__device__ __forceinline__ void cpa16(void* dst, const void* src) {
    unsigned d = (unsigned)__cvta_generic_to_shared(dst);
    asm volatile("cp.async.cg.shared.global [%0], [%1], 16;" :: "r"(d), "l"(src));
}
__device__ __forceinline__ void ldsm4(uint32_t& r0, uint32_t& r1, uint32_t& r2,
                                      uint32_t& r3, const void* p) {
    uint32_t a = (uint32_t)__cvta_generic_to_shared(p);
    asm volatile("ldmatrix.sync.aligned.m8n8.x4.shared.b16 {%0,%1,%2,%3}, [%4];"
                 : "=r"(r0), "=r"(r1), "=r"(r2), "=r"(r3) : "r"(a));
}
__device__ __forceinline__ void mma_f16(float* d, const uint32_t* a,
                                        uint32_t b0, uint32_t b1) {
    asm volatile(
        "mma.sync.aligned.m16n8k16.row.col.f32.f16.f16.f32 "
        "{%0,%1,%2,%3}, {%4,%5,%6,%7}, {%8,%9}, {%0,%1,%2,%3};"
        : "+f"(d[0]), "+f"(d[1]), "+f"(d[2]), "+f"(d[3])
        : "r"(a[0]), "r"(a[1]), "r"(a[2]), "r"(a[3]), "r"(b0), "r"(b1));
}
__device__ __forceinline__ float gelu_f(float v) {
    return 0.5f * v * (1.0f + erff(v * 0.70710678118654752f));
}

__device__ __forceinline__ void scan_coeffs(
    const float* log_dt, const float* A_imag, const float* log_A_real,
    int layer, int h, int li, float* Are_o, float* Aim_o, float* dt_o)
{
    float dt = expf(log_dt[layer * H + h]);
    int pbase = (layer * H + h) * N2 + li * 4;
    float4 aim = *(const float4*)(A_imag + pbase);
    float4 lar = *(const float4*)(log_A_real + pbase);
    float aimv[4] = {aim.x, aim.y, aim.z, aim.w};
    float larv[4] = {lar.x, lar.y, lar.z, lar.w};
#pragma unroll
    for (int j = 0; j < 4; j++) {
        Are_o[j] = -expf(larv[j]);
        Aim_o[j] = aimv[j];
    }
    *dt_o = dt;
}

// =====================================================================
// xsplit: (B,L,H) fp32 -> (B,H,L) fp16 (layer 0 only)
// =====================================================================
__global__ __launch_bounds__(256) void xsplit(const float* __restrict__ x) {
    __shared__ float tile[32][33];
    int b = blockIdx.z, h0 = blockIdx.x * 32, l0 = blockIdx.y * 32;
    int tx = threadIdx.x, ty = threadIdx.y;
#pragma unroll
    for (int j = 0; j < 32; j += 8)
        tile[ty + j][tx] = x[((size_t)b * LSEQ + l0 + ty + j) * H + h0 + tx];
    __syncthreads();
#pragma unroll
    for (int j = 0; j < 32; j += 8) {
        size_t o = ((size_t)(b * H + h0 + ty + j)) * LSEQ + l0 + tx;
        g_Uhi[o] = __float2half_rn(tile[tx][ty + j]);
    }
}

// =====================================================================
// tbuild: per-h Toeplitz kernel k[d], correction matrix V, end-state E.
// =====================================================================
__global__ __launch_bounds__(256) void tbuild(
    const float* __restrict__ log_dt, const float* __restrict__ A_imag,
    const float* __restrict__ log_A_real, const float* __restrict__ Cp,
    const float* __restrict__ Dp, int layer)
{
    __shared__ float wr[CL + 1][32], wi[CL + 1][32];
    __shared__ float scfr[32], scfi[32], skern[CL];
    __shared__ float sD;
    int h = blockIdx.x;
    int t = threadIdx.x;
    if (t == 0) sD = Dp[layer * H + h];
    if (t < 32) {
        int n = t;
        float dt = expf(log_dt[layer * H + h]);
        float Are = -expf(log_A_real[(layer * H + h) * N2 + n]);
        float Aim = A_imag[(layer * H + h) * N2 + n];
        float e1 = expf(Are * dt);
        float w1r = e1 * cosf(Aim * dt), w1i = e1 * sinf(Aim * dt);
        float nr = w1r - 1.0f, ni = w1i;
        float cr = Cp[((layer * H + h) * N2 + n) * 2 + 0];
        float ci = Cp[((layer * H + h) * N2 + n) * 2 + 1];
        float tr = cr * nr - ci * ni;
        float ti = cr * ni + ci * nr;
        float inv = 2.0f / (Are * Are + Aim * Aim);
        scfr[n] = (tr * Are + ti * Aim) * inv;
        scfi[n] = (ti * Are - tr * Aim) * inv;
        float pr = 1.0f, pi = 0.0f;
        for (int d = 0; d <= CL; d++) {
            wr[d][n] = pr; wi[d][n] = pi;
            float npr = pr * w1r - pi * w1i;
            float npi = pr * w1i + pi * w1r;
            pr = npr; pi = npi;
        }
    }
    __syncthreads();
    if (t < CL) {
        float acc = (t == 0) ? sD : 0.0f;
#pragma unroll 8
        for (int n = 0; n < 32; n++)
            acc += scfr[n] * wr[t][n] - scfi[n] * wi[t][n];
        skern[t] = acc;
    }
    __syncthreads();
    for (int idx = t; idx < CL * CL; idx += 256) {
        int n = idx >> 7, k = idx & 127;
        float v = (k <= n) ? skern[n - k] : 0.0f;
        g_T2hi[((size_t)h * CL + n) * 192 + k] = __float2half_rn(v);
    }
    for (int idx = t; idx < CL * 64; idx += 256) {
        int n = idx >> 6, e = idx & 63, ns = e >> 1;
        float cwr = scfr[ns] * wr[n + 1][ns] - scfi[ns] * wi[n + 1][ns];
        float cwi = scfr[ns] * wi[n + 1][ns] + scfi[ns] * wr[n + 1][ns];
        float v = (e & 1) ? -cwi : cwr;
        g_T2hi[((size_t)h * CL + n) * 192 + 128 + e] = __float2half_rn(v);
    }
    for (int idx = t; idx < 64 * CL; idx += 256) {
        int e = idx >> 7, j = idx & 127, ns = e >> 1;
        int d = CL - 1 - j;
        float v = (e & 1) ? wi[d][ns] : wr[d][ns];
        g_T1hi[((size_t)h * 64 + e) * CL + j] = __float2half_rn(v);
    }
}

// =====================================================================
// gemm_end: per h, S_end[NINST x 64] = Uhi[NINST x 128] @ B1hi^T. 1-term.
// =====================================================================
#define E_BOFF  6144u
#define E_STAGE 9216u
#define E_DSMEM (3 * E_STAGE)   /* 27648 */

__global__ __launch_bounds__(256, 2) void gemm_end()
{
    extern __shared__ __align__(16) char dsmE[];
    int tid = threadIdx.x;
    int warp = tid >> 5, lane = tid & 31;
    int grp = lane >> 2, tq = lane & 3;
    int mt = blockIdx.x, h = blockIdx.y;
    int wm = (warp >> 1) * 32, wn = (warp & 1) * 32;
    int lrow8 = (lane & 7) + (lane & 8);
    int khalf = (lane >> 4) * 16;

    int mloc = tid >> 1, ch = tid & 1;
    int m = mt * 128 + mloc;
    int bb = m >> 5, cc = m & 31;
    const __half* aUh = g_Uhi + ((size_t)(bb * H + h)) * LSEQ + cc * CL;
    int frB = (tid & 127) >> 1, chB = tid & 1;
    const __half* bTh = g_T1hi + (size_t)h * 64 * CL;

    float acc[2][4][4];
#pragma unroll
    for (int mi = 0; mi < 2; mi++)
#pragma unroll
        for (int ni = 0; ni < 4; ni++)
#pragma unroll
            for (int r = 0; r < 4; r++) acc[mi][ni][r] = 0.0f;

#define LOAD_E(KT, S)                                                            \
    do {                                                                         \
        char* sb = dsmE + (unsigned)(S) * E_STAGE;                               \
        int k0 = (KT) * 16 + ch * 8;                                             \
        cpa16(sb + (unsigned)(mloc * 48 + ch * 16), aUh + k0);                   \
        if (tid < 128) {                                                         \
            int kb = (KT) * 16 + chB * 8;                                        \
            cpa16(sb + E_BOFF + (unsigned)(frB * 48 + chB * 16),                 \
                  bTh + (size_t)frB * CL + kb);                                  \
        }                                                                        \
        asm volatile("cp.async.commit_group;" ::: "memory");                     \
    } while (0)

    LOAD_E(0, 0);
    LOAD_E(1, 1);
    const int NKT = 8;
    for (int kt = 0; kt < NKT; kt++) {
        int s = kt - (kt / 3) * 3;
        if (kt + 2 < NKT) asm volatile("cp.async.wait_group 1;" ::: "memory");
        else              asm volatile("cp.async.wait_group 0;" ::: "memory");
        __syncthreads();
        if (kt + 2 < NKT) {
            int s2 = (kt + 2) - ((kt + 2) / 3) * 3;
            LOAD_E(kt + 2, s2);
        }
        const char* sb = dsmE + (unsigned)s * E_STAGE;
        uint32_t ah[2][4];
#pragma unroll
        for (int mi = 0; mi < 2; mi++) {
            const char* pa = sb + (unsigned)((wm + mi * 16 + lrow8) * 48) + khalf;
            ldsm4(ah[mi][0], ah[mi][1], ah[mi][2], ah[mi][3], pa);
        }
        uint32_t bh[4][2];
#pragma unroll
        for (int p = 0; p < 2; p++) {
            const char* pb = sb + E_BOFF + (unsigned)((wn + p * 16 + lrow8) * 48) + khalf;
            ldsm4(bh[2 * p][0], bh[2 * p + 1][0], bh[2 * p][1], bh[2 * p + 1][1], pb);
        }
#pragma unroll
        for (int ni = 0; ni < 4; ni++)
#pragma unroll
            for (int mi = 0; mi < 2; mi++)
                mma_f16(acc[mi][ni], ah[mi], bh[ni][0], bh[ni][1]);
    }
#pragma unroll
    for (int mi = 0; mi < 2; mi++)
#pragma unroll
        for (int ni = 0; ni < 4; ni++) {
            int r = mt * 128 + wm + mi * 16 + grp;
            int n = wn + ni * 8 + tq * 2;
            __half2 v0 = __floats2half2_rn(acc[mi][ni][0], acc[mi][ni][1]);
            __half2 v1 = __floats2half2_rn(acc[mi][ni][2], acc[mi][ni][3]);
            *(__half2*)&g_E2h[((size_t)h * NINST + r) * 64 + n] = v0;
            *(__half2*)&g_E2h[((size_t)h * NINST + r + 8) * 64 + n] = v1;
        }
}

// =====================================================================
// prefix: combine chunk end states -> per-chunk init states (fp16)
// =====================================================================
__global__ __launch_bounds__(256) void ssm_prefix2(
    const float* __restrict__ log_dt, const float* __restrict__ A_imag,
    const float* __restrict__ log_A_real, int layer)
{
    int idx = blockIdx.x * 256 + threadIdx.x;
    int li = idx & 7;
    int b  = (idx >> 3) & 7;
    int h  = idx >> 6;

    float Are[4], Aim[4], dt;
    scan_coeffs(log_dt, A_imag, log_A_real, layer, h, li, Are, Aim, &dt);
    float Wr[4], Wi[4];
#pragma unroll
    for (int j = 0; j < 4; j++) {
        float e = expf(Are[j] * dt * (float)CL);
        Wr[j] = e * cosf(Aim[j] * dt * (float)CL);
        Wi[j] = e * sinf(Aim[j] * dt * (float)CL);
    }
    float Ire[4] = {0, 0, 0, 0}, Iim[4] = {0, 0, 0, 0};
    for (int c = 0; c < NC; c++) {
        size_t off = ((size_t)h * NINST + b * NC + c) * 64 + li * 8;
#pragma unroll
        for (int j = 0; j < 4; j++) {
            g_Shi[off + 2 * j]     = __float2half_rn(Ire[j]);
            g_Shi[off + 2 * j + 1] = __float2half_rn(Iim[j]);
        }
#pragma unroll
        for (int j = 0; j < 4; j++) {
            float er = __half2float(g_E2h[off + 2 * j]);
            float ei = __half2float(g_E2h[off + 2 * j + 1]);
            float nr = fmaf(Wr[j], Ire[j], fmaf(-Wi[j], Iim[j], er));
            float ni = fmaf(Wi[j], Ire[j], fmaf( Wr[j], Iim[j], ei));
            Ire[j] = nr; Iim[j] = ni;
        }
    }
}

// =====================================================================
// gemm_toep: per h, Y[NINST x 128] = [U|Sinit]hi @ B2hi^T. 1-term.
// Epilogue: GELU + fp16 store (B,H,L).
// =====================================================================
#define T_BOFF  6144u
#define T_STAGE 12288u
#define T_DSMEM (3 * T_STAGE)   /* 36864 */

__global__ __launch_bounds__(256, 2) void gemm_toep()
{
    extern __shared__ __align__(16) char dsmT[];
    int tid = threadIdx.x;
    int warp = tid >> 5, lane = tid & 31;
    int grp = lane >> 2, tq = lane & 3;
    int mt = blockIdx.x, h = blockIdx.y;
    int wm = (warp >> 1) * 32, wn = (warp & 1) * 64;
    int lrow8 = (lane & 7) + (lane & 8);
    int khalf = (lane >> 4) * 16;

    int mloc = tid >> 1, ch = tid & 1;
    int m = mt * 128 + mloc;
    int bb = m >> 5, cc = m & 31;
    const __half* aUh = g_Uhi + ((size_t)(bb * H + h)) * LSEQ + cc * CL;
    const __half* aSh = g_Shi + ((size_t)h * NINST + m) * 64;
    const __half* bTh = g_T2hi + (size_t)h * CL * 192;

    float acc[2][8][4];
#pragma unroll
    for (int mi = 0; mi < 2; mi++)
#pragma unroll
        for (int ni = 0; ni < 8; ni++)
#pragma unroll
            for (int r = 0; r < 4; r++) acc[mi][ni][r] = 0.0f;

#define LOAD_T(KT, S)                                                            \
    do {                                                                         \
        char* sb = dsmT + (unsigned)(S) * T_STAGE;                               \
        int k0 = (KT) * 16 + ch * 8;                                             \
        const __half* sh = (k0 < 128) ? aUh + k0 : aSh + (k0 - 128);             \
        cpa16(sb + (unsigned)(mloc * 48 + ch * 16), sh);                         \
        cpa16(sb + T_BOFF + (unsigned)(mloc * 48 + ch * 16),                     \
              bTh + (size_t)mloc * 192 + k0);                                    \
        asm volatile("cp.async.commit_group;" ::: "memory");                     \
    } while (0)

    LOAD_T(0, 0);
    LOAD_T(1, 1);
    const int NKT = 12;
    for (int kt = 0; kt < NKT; kt++) {
        int s = kt - (kt / 3) * 3;
        if (kt + 2 < NKT) asm volatile("cp.async.wait_group 1;" ::: "memory");
        else              asm volatile("cp.async.wait_group 0;" ::: "memory");
        __syncthreads();
        if (kt + 2 < NKT) {
            int s2 = (kt + 2) - ((kt + 2) / 3) * 3;
            LOAD_T(kt + 2, s2);
        }
        const char* sb = dsmT + (unsigned)s * T_STAGE;
        uint32_t ah[2][4];
#pragma unroll
        for (int mi = 0; mi < 2; mi++) {
            const char* pa = sb + (unsigned)((wm + mi * 16 + lrow8) * 48) + khalf;
            ldsm4(ah[mi][0], ah[mi][1], ah[mi][2], ah[mi][3], pa);
        }
        uint32_t bh[8][2];
#pragma unroll
        for (int p = 0; p < 4; p++) {
            const char* pb = sb + T_BOFF + (unsigned)((wn + p * 16 + lrow8) * 48) + khalf;
            ldsm4(bh[2 * p][0], bh[2 * p + 1][0], bh[2 * p][1], bh[2 * p + 1][1], pb);
        }
#pragma unroll
        for (int ni = 0; ni < 8; ni++)
#pragma unroll
            for (int mi = 0; mi < 2; mi++)
                mma_f16(acc[mi][ni], ah[mi], bh[ni][0], bh[ni][1]);
    }
    // epilogue: GELU + fp16 store to (B,H,L)
#pragma unroll
    for (int mi = 0; mi < 2; mi++) {
        int r = mt * 128 + wm + mi * 16 + grp;
        int b0 = r >> 5, c0 = r & 31;
        int r1 = r + 8;
        int b1 = r1 >> 5, c1 = r1 & 31;
        __half* y0 = g_Yt16 + ((size_t)(b0 * H + h)) * LSEQ + c0 * CL;
        __half* y1 = g_Yt16 + ((size_t)(b1 * H + h)) * LSEQ + c1 * CL;
#pragma unroll
        for (int ni = 0; ni < 8; ni++) {
            int n = wn + ni * 8 + tq * 2;
            __half2 v0 = __floats2half2_rn(gelu_f(acc[mi][ni][0]),
                                           gelu_f(acc[mi][ni][1]));
            __half2 v1 = __floats2half2_rn(gelu_f(acc[mi][ni][2]),
                                           gelu_f(acc[mi][ni][3]));
            *(__half2*)(y0 + n) = v0;
            *(__half2*)(y1 + n) = v1;
        }
    }
}

// =====================================================================
// ytrans: (B,H,L) fp16 -> (B,L,H) fp16 (pure transpose)
// =====================================================================
__global__ __launch_bounds__(256) void ytrans() {
    __shared__ __half tile[32][40];
    int b = blockIdx.z, h0 = blockIdx.y * 32, l0 = blockIdx.x * 32;
    int tx = threadIdx.x, ty = threadIdx.y;
#pragma unroll
    for (int j = 0; j < 32; j += 8)
        tile[ty + j][tx] = g_Yt16[((size_t)(b * H + h0 + ty + j)) * LSEQ + l0 + tx];
    __syncthreads();
#pragma unroll
    for (int j = 0; j < 32; j += 8)
        g_Yhi[((size_t)b * LSEQ + l0 + ty + j) * H + h0 + tx] = tile[tx][ty + j];
}

// =====================================================================
// W prep: interleave rows (2i <- a-row i, 2i+1 <- g-row i+H), fp16.
// =====================================================================
__global__ __launch_bounds__(256) void w_prep(const float* __restrict__ W,
                                              const float* __restrict__ bp) {
    size_t i = (size_t)blockIdx.x * 256 + threadIdx.x;
    int col = (int)(i % H);
    int k   = (int)((i / H) % (2 * H));
    int l   = (int)(i / ((size_t)H * 2 * H));
    int orig = (k >> 1) + (k & 1) * H;
    float v = W[((size_t)l * 2 * H + orig) * H + col];
    g_Whi[i] = __float2half_rn(v);
    if (i < NLAY * 2 * H) {
        int kk = (int)(i % (2 * H));
        int ll = (int)(i / (2 * H));
        int og = (kk >> 1) + (kk & 1) * H;
        g_bint[i] = bp[ll * 2 * H + og];
    }
}

// =====================================================================
// conv GEMM + fused GLU: fp16 1-TERM (Yhi * Whi).
// =====================================================================
#define C_BOFF  6144u
#define C_STAGE 12288u
#define C_DSMEM (3 * C_STAGE)   /* 36864 */

__global__ __launch_bounds__(256, 2) void conv_gemm(int layer)
{
    extern __shared__ __align__(16) char dsm[];
    int tid = threadIdx.x;
    int warp = tid >> 5, lane = tid & 31;
    int grp = lane >> 2, tq = lane & 3;
    int n0 = blockIdx.x * 128, m0 = blockIdx.y * 128;

    const __half* Wh = g_Whi + (size_t)layer * 2 * H * H;

    int wm = (warp >> 1) * 32, wn = (warp & 1) * 64;
    int lrow8 = (lane & 7) + (lane & 8);
    int khalf = (lane >> 4) * 16;

    float acc[2][8][4];
#pragma unroll
    for (int mi = 0; mi < 2; mi++)
#pragma unroll
        for (int ni = 0; ni < 8; ni++)
#pragma unroll
            for (int r = 0; r < 4; r++) acc[mi][ni][r] = 0.0f;

    int fr = tid >> 1, fch = tid & 1;

#define LOAD_C(KT, S)                                                              \
    do {                                                                           \
        char* sb = dsm + (unsigned)(S) * C_STAGE + (unsigned)(fr * 48 + fch * 16); \
        size_t soA = (size_t)(m0 + fr) * H + (KT) * 16 + fch * 8;                  \
        size_t soB = (size_t)(n0 + fr) * H + (KT) * 16 + fch * 8;                  \
        cpa16(sb,          g_Yhi + soA);                                           \
        cpa16(sb + C_BOFF, Wh + soB);                                              \
        asm volatile("cp.async.commit_group;" ::: "memory");                       \
    } while (0)

    LOAD_C(0, 0);
    LOAD_C(1, 1);

    const int NKT = H / 16;   // 32
    for (int kt = 0; kt < NKT; kt++) {
        int s = kt - (kt / 3) * 3;
        if (kt + 2 < NKT) asm volatile("cp.async.wait_group 1;" ::: "memory");
        else              asm volatile("cp.async.wait_group 0;" ::: "memory");
        __syncthreads();
        if (kt + 2 < NKT) {
            int s2 = (kt + 2) - ((kt + 2) / 3) * 3;
            LOAD_C(kt + 2, s2);
        }
        const char* sb = dsm + (unsigned)s * C_STAGE;
        uint32_t ah[2][4];
#pragma unroll
        for (int mi = 0; mi < 2; mi++) {
            const char* pa = sb + (unsigned)((wm + mi * 16 + lrow8) * 48) + khalf;
            ldsm4(ah[mi][0], ah[mi][1], ah[mi][2], ah[mi][3], pa);
        }
        uint32_t bh[8][2];
#pragma unroll
        for (int p = 0; p < 4; p++) {
            const char* pb = sb + C_BOFF + (unsigned)((wn + p * 16 + lrow8) * 48) + khalf;
            ldsm4(bh[2 * p][0], bh[2 * p + 1][0], bh[2 * p][1], bh[2 * p + 1][1], pb);
        }
#pragma unroll
        for (int ni = 0; ni < 8; ni++)
#pragma unroll
            for (int mi = 0; mi < 2; mi++)
                mma_f16(acc[mi][ni], ah[mi], bh[ni][0], bh[ni][1]);
    }
#pragma unroll
    for (int mi = 0; mi < 2; mi++)
#pragma unroll
        for (int ni = 0; ni < 8; ni++) {
            int r  = m0 + wm + mi * 16 + grp;
            int cb = wn + ni * 8 + tq * 2;
            float ba = g_bint[layer * 2 * H + n0 + cb];
            float bg = g_bint[layer * 2 * H + n0 + cb + 1];
            float a0 = acc[mi][ni][0] + ba, gg0 = acc[mi][ni][1] + bg;
            float a1 = acc[mi][ni][2] + ba, gg1 = acc[mi][ni][3] + bg;
            int hidx = (n0 + cb) >> 1;
            g_Z[(size_t)r * H + hidx]       = a0 / (1.0f + expf(-gg0));
            g_Z[(size_t)(r + 8) * H + hidx] = a1 / (1.0f + expf(-gg1));
        }
}

// =====================================================================
// res_ln (final layer): residual + LN, warp per row, writes fp32 out.
// =====================================================================
__global__ __launch_bounds__(128) void res_ln(
    const float* __restrict__ xin, float* __restrict__ xout,
    const float* __restrict__ gamma, const float* __restrict__ beta, int layer)
{
    int row  = blockIdx.x * 4 + (threadIdx.x >> 5);
    int lane = threadIdx.x & 31;
    const float4* z4 = (const float4*)(g_Z + (size_t)row * H);
    const float4* x4 = (const float4*)(xin + (size_t)row * H);
    float4* o4       = (float4*)(xout + (size_t)row * H);
    const float4* g4 = (const float4*)(gamma + layer * H);
    const float4* e4 = (const float4*)(beta + layer * H);

    float4 v[4];
    float s = 0.0f, s2 = 0.0f;
#pragma unroll
    for (int j = 0; j < 4; j++) {
        float4 zz = z4[j * 32 + lane];
        float4 xv = x4[j * 32 + lane];
        float4 vv;
        vv.x = zz.x + xv.x; vv.y = zz.y + xv.y;
        vv.z = zz.z + xv.z; vv.w = zz.w + xv.w;
        v[j] = vv;
        s += vv.x + vv.y + vv.z + vv.w;
        s2 = fmaf(vv.x, vv.x, s2); s2 = fmaf(vv.y, vv.y, s2);
        s2 = fmaf(vv.z, vv.z, s2); s2 = fmaf(vv.w, vv.w, s2);
    }
#pragma unroll
    for (int o = 16; o; o >>= 1) {
        s  += __shfl_xor_sync(0xffffffffu, s, o);
        s2 += __shfl_xor_sync(0xffffffffu, s2, o);
    }
    float mu = s * (1.0f / H);
    float rs = rsqrtf(s2 * (1.0f / H) - mu * mu + LN_EPS);
#pragma unroll
    for (int j = 0; j < 4; j++) {
        float4 ga = g4[j * 32 + lane];
        float4 be = e4[j * 32 + lane];
        float4 vv = v[j], o;
        o.x = (vv.x - mu) * rs * ga.x + be.x;
        o.y = (vv.y - mu) * rs * ga.y + be.y;
        o.z = (vv.z - mu) * rs * ga.z + be.z;
        o.w = (vv.w - mu) * rs * ga.w + be.w;
        o4[j * 32 + lane] = o;
    }
}

// =====================================================================
// res_lnT (layers 0..2): residual + LN + write fp32 xout AND transposed
// fp16 U plane (B,H,L) for the next layer. 32 rows x 512 h per block.
// =====================================================================
#define RL_SMEM (32 * 513 * 4)   /* 65664 */
__global__ __launch_bounds__(256) void res_lnT(
    const float* __restrict__ xin, float* __restrict__ xout,
    const float* __restrict__ gamma, const float* __restrict__ beta, int layer)
{
    extern __shared__ float sv[];    // [32][513]
    int warp = threadIdx.x >> 5, lane = threadIdx.x & 31;
    int row0 = blockIdx.x * 32;
    int b = row0 >> 12;              // row0 / LSEQ
    int l0 = row0 & (LSEQ - 1);
    const float4* g4 = (const float4*)(gamma + layer * H);
    const float4* e4 = (const float4*)(beta + layer * H);

#pragma unroll
    for (int i = 0; i < 4; i++) {
        int lr = warp * 4 + i;
        int row = row0 + lr;
        const float4* z4 = (const float4*)(g_Z + (size_t)row * H);
        const float4* x4 = (const float4*)(xin + (size_t)row * H);
        float4* o4 = (float4*)(xout + (size_t)row * H);
        float4 v[4];
        float s = 0.0f, s2 = 0.0f;
#pragma unroll
        for (int j = 0; j < 4; j++) {
            float4 zz = z4[j * 32 + lane];
            float4 xv = x4[j * 32 + lane];
            float4 vv;
            vv.x = zz.x + xv.x; vv.y = zz.y + xv.y;
            vv.z = zz.z + xv.z; vv.w = zz.w + xv.w;
            v[j] = vv;
            s += vv.x + vv.y + vv.z + vv.w;
            s2 = fmaf(vv.x, vv.x, s2); s2 = fmaf(vv.y, vv.y, s2);
            s2 = fmaf(vv.z, vv.z, s2); s2 = fmaf(vv.w, vv.w, s2);
        }
#pragma unroll
        for (int o = 16; o; o >>= 1) {
            s  += __shfl_xor_sync(0xffffffffu, s, o);
            s2 += __shfl_xor_sync(0xffffffffu, s2, o);
        }
        float mu = s * (1.0f / H);
        float rs = rsqrtf(s2 * (1.0f / H) - mu * mu + LN_EPS);
#pragma unroll
        for (int j = 0; j < 4; j++) {
            float4 ga = g4[j * 32 + lane];
            float4 be = e4[j * 32 + lane];
            float4 vv = v[j], o;
            o.x = (vv.x - mu) * rs * ga.x + be.x;
            o.y = (vv.y - mu) * rs * ga.y + be.y;
            o.z = (vv.z - mu) * rs * ga.z + be.z;
            o.w = (vv.w - mu) * rs * ga.w + be.w;
            o4[j * 32 + lane] = o;
            int hh = (j * 32 + lane) * 4;
            sv[lr * 513 + hh + 0] = o.x;
            sv[lr * 513 + hh + 1] = o.y;
            sv[lr * 513 + hh + 2] = o.z;
            sv[lr * 513 + hh + 3] = o.w;
        }
    }
    __syncthreads();
    // transposed fp16 write: warp w handles h = it*8 + w, lanes = l
#pragma unroll 4
    for (int it = 0; it < 64; it++) {
        int h = it * 8 + warp;
        float v = sv[lane * 513 + h];
        g_Uhi[((size_t)(b * H + h)) * LSEQ + l0 + lane] = __float2half_rn(v);
    }
}

// ================= launcher =================
extern "C" void kernel_launch(void* const* d_in, const int* in_sizes, int n_in,
                              void* d_out, int out_size)
{
    const float* x          = (const float*)d_in[0];
    const float* log_dt     = (const float*)d_in[1];
    const float* A_imag     = (const float*)d_in[2];
    const float* log_A_real = (const float*)d_in[3];
    const float* C          = (const float*)d_in[4];
    const float* D          = (const float*)d_in[5];
    const float* W          = (const float*)d_in[6];
    const float* bconv      = (const float*)d_in[7];
    const float* gamma      = (const float*)d_in[8];
    const float* beta       = (const float*)d_in[9];
    float* out = (float*)d_out;

    cudaFuncSetAttribute(conv_gemm, cudaFuncAttributeMaxDynamicSharedMemorySize,
                         C_DSMEM);
    cudaFuncSetAttribute(gemm_toep, cudaFuncAttributeMaxDynamicSharedMemorySize,
                         T_DSMEM);
    cudaFuncSetAttribute(gemm_end, cudaFuncAttributeMaxDynamicSharedMemorySize,
                         E_DSMEM);
    cudaFuncSetAttribute(res_lnT, cudaFuncAttributeMaxDynamicSharedMemorySize,
                         RL_SMEM);

    float* pA; cudaGetSymbolAddress((void**)&pA, g_xA);
    float* pB; cudaGetSymbolAddress((void**)&pB, g_xB);
    const float* xin[NLAY]  = {x,  pA, pB, pA};
    float*       xout[NLAY] = {pA, pB, pA, out};

    w_prep<<<(NLAY * 2 * H * H) / 256, 256>>>(W, bconv);

    dim3 tb(32, 8);
    xsplit<<<dim3(H / 32, LSEQ / 32, BSZ), tb>>>(x);   // layer-0 U plane

    for (int i = 0; i < NLAY; i++) {
        tbuild<<<H, 256>>>(log_dt, A_imag, log_A_real, C, D, i);
        gemm_end<<<dim3(2, H), 256, E_DSMEM>>>();
        ssm_prefix2<<<(H * BSZ * 8) / 256, 256>>>(log_dt, A_imag, log_A_real, i);
        gemm_toep<<<dim3(2, H), 256, T_DSMEM>>>();
        ytrans<<<dim3(LSEQ / 32, H / 32, BSZ), tb>>>();
        conv_gemm<<<dim3(2 * H / 128, MROWS / 128), 256, C_DSMEM>>>(i);
        if (i < NLAY - 1)
            res_lnT<<<MROWS / 32, 256, RL_SMEM>>>(xin[i], xout[i], gamma, beta, i);
        else
            res_ln<<<MROWS / 4, 128>>>(xin[i], xout[i], gamma, beta, i);
    }
}

// round 14
// speedup vs baseline: 2.4606x; 1.1473x over previous
#include <cuda_runtime.h>
#include <cuda_fp16.h>
#include <cstdint>

#define H     512
#define NLAY  4
#define N2    32
#define BSZ   8
#define LSEQ  4096
#define MROWS (BSZ * LSEQ)      /* 32768 */
#define NC    32                /* chunks per sequence */
#define CL    (LSEQ / NC)       /* 128 */
#define NINST (BSZ * NC)        /* 256 instances per h */
#define LN_EPS 1e-5f

// ---- static scratch. activations (B,L,H) row-major unless noted ----
__device__ __align__(256) float g_xA[(size_t)MROWS * H];
__device__ __align__(256) float g_xB[(size_t)MROWS * H];
__device__ __align__(256) __half g_Uhi [(size_t)MROWS * H];   // u (B,H,L)
__device__ __align__(256) __half g_Yt16[(size_t)MROWS * H];   // gelu(y) (B,H,L)
__device__ __align__(256) __half g_Whi[(size_t)NLAY * 2 * H * H];
__device__ __align__(256) float g_bint[NLAY * 2 * H];
__device__ __align__(256) __half g_Zh[(size_t)MROWS * H];     // GLU out (B,L,H) fp16
// Toeplitz machinery (ALL layers, built once)
__device__ __align__(256) __half g_T2hi[(size_t)NLAY * H * CL * 192];
__device__ __align__(256) __half g_T1hi[(size_t)NLAY * H * 64 * CL];
__device__ __align__(256) __half g_E2h[(size_t)H * NINST * 64]; // end states
__device__ __align__(256) __half g_Shi[(size_t)H * NINST * 64]; // init states

// ---------------- helpers ----------------
__device__ __forceinline__ void cpa16(void* dst, const void* src) {
    unsigned d = (unsigned)__cvta_generic_to_shared(dst);
    asm volatile("cp.async.cg.shared.global [%0], [%1], 16;" :: "r"(d), "l"(src));
}
__device__ __forceinline__ void ldsm4(uint32_t& r0, uint32_t& r1, uint32_t& r2,
                                      uint32_t& r3, const void* p) {
    uint32_t a = (uint32_t)__cvta_generic_to_shared(p);
    asm volatile("ldmatrix.sync.aligned.m8n8.x4.shared.b16 {%0,%1,%2,%3}, [%4];"
                 : "=r"(r0), "=r"(r1), "=r"(r2), "=r"(r3) : "r"(a));
}
__device__ __forceinline__ void ldsm4t(uint32_t& r0, uint32_t& r1, uint32_t& r2,
                                       uint32_t& r3, const void* p) {
    uint32_t a = (uint32_t)__cvta_generic_to_shared(p);
    asm volatile("ldmatrix.sync.aligned.m8n8.x4.trans.shared.b16 {%0,%1,%2,%3}, [%4];"
                 : "=r"(r0), "=r"(r1), "=r"(r2), "=r"(r3) : "r"(a));
}
__device__ __forceinline__ void mma_f16(float* d, const uint32_t* a,
                                        uint32_t b0, uint32_t b1) {
    asm volatile(
        "mma.sync.aligned.m16n8k16.row.col.f32.f16.f16.f32 "
        "{%0,%1,%2,%3}, {%4,%5,%6,%7}, {%8,%9}, {%0,%1,%2,%3};"
        : "+f"(d[0]), "+f"(d[1]), "+f"(d[2]), "+f"(d[3])
        : "r"(a[0]), "r"(a[1]), "r"(a[2]), "r"(a[3]), "r"(b0), "r"(b1));
}
__device__ __forceinline__ float gelu_f(float v) {
    return 0.5f * v * (1.0f + erff(v * 0.70710678118654752f));
}

__device__ __forceinline__ void scan_coeffs(
    const float* log_dt, const float* A_imag, const float* log_A_real,
    int layer, int h, int li, float* Are_o, float* Aim_o, float* dt_o)
{
    float dt = expf(log_dt[layer * H + h]);
    int pbase = (layer * H + h) * N2 + li * 4;
    float4 aim = *(const float4*)(A_imag + pbase);
    float4 lar = *(const float4*)(log_A_real + pbase);
    float aimv[4] = {aim.x, aim.y, aim.z, aim.w};
    float larv[4] = {lar.x, lar.y, lar.z, lar.w};
#pragma unroll
    for (int j = 0; j < 4; j++) {
        Are_o[j] = -expf(larv[j]);
        Aim_o[j] = aimv[j];
    }
    *dt_o = dt;
}

// =====================================================================
// xsplit: (B,L,H) fp32 -> (B,H,L) fp16 (layer 0 only)
// =====================================================================
__global__ __launch_bounds__(256) void xsplit(const float* __restrict__ x) {
    __shared__ float tile[32][33];
    int b = blockIdx.z, h0 = blockIdx.x * 32, l0 = blockIdx.y * 32;
    int tx = threadIdx.x, ty = threadIdx.y;
#pragma unroll
    for (int j = 0; j < 32; j += 8)
        tile[ty + j][tx] = x[((size_t)b * LSEQ + l0 + ty + j) * H + h0 + tx];
    __syncthreads();
#pragma unroll
    for (int j = 0; j < 32; j += 8) {
        size_t o = ((size_t)(b * H + h0 + ty + j)) * LSEQ + l0 + tx;
        g_Uhi[o] = __float2half_rn(tile[tx][ty + j]);
    }
}

// =====================================================================
// tbuild: per-(h,layer) Toeplitz kernel, correction V, end-state E.
// Run ONCE for all layers: grid (H, NLAY).
// =====================================================================
__global__ __launch_bounds__(256) void tbuild(
    const float* __restrict__ log_dt, const float* __restrict__ A_imag,
    const float* __restrict__ log_A_real, const float* __restrict__ Cp,
    const float* __restrict__ Dp)
{
    __shared__ float wr[CL + 1][32], wi[CL + 1][32];
    __shared__ float scfr[32], scfi[32], skern[CL];
    __shared__ float sD;
    int h = blockIdx.x;
    int layer = blockIdx.y;
    int t = threadIdx.x;
    __half* T2 = g_T2hi + (size_t)layer * H * CL * 192;
    __half* T1 = g_T1hi + (size_t)layer * H * 64 * CL;
    if (t == 0) sD = Dp[layer * H + h];
    if (t < 32) {
        int n = t;
        float dt = expf(log_dt[layer * H + h]);
        float Are = -expf(log_A_real[(layer * H + h) * N2 + n]);
        float Aim = A_imag[(layer * H + h) * N2 + n];
        float e1 = expf(Are * dt);
        float w1r = e1 * cosf(Aim * dt), w1i = e1 * sinf(Aim * dt);
        float nr = w1r - 1.0f, ni = w1i;
        float cr = Cp[((layer * H + h) * N2 + n) * 2 + 0];
        float ci = Cp[((layer * H + h) * N2 + n) * 2 + 1];
        float tr = cr * nr - ci * ni;
        float ti = cr * ni + ci * nr;
        float inv = 2.0f / (Are * Are + Aim * Aim);
        scfr[n] = (tr * Are + ti * Aim) * inv;
        scfi[n] = (ti * Are - tr * Aim) * inv;
        float pr = 1.0f, pi = 0.0f;
        for (int d = 0; d <= CL; d++) {
            wr[d][n] = pr; wi[d][n] = pi;
            float npr = pr * w1r - pi * w1i;
            float npi = pr * w1i + pi * w1r;
            pr = npr; pi = npi;
        }
    }
    __syncthreads();
    if (t < CL) {
        float acc = (t == 0) ? sD : 0.0f;
#pragma unroll 8
        for (int n = 0; n < 32; n++)
            acc += scfr[n] * wr[t][n] - scfi[n] * wi[t][n];
        skern[t] = acc;
    }
    __syncthreads();
    for (int idx = t; idx < CL * CL; idx += 256) {
        int n = idx >> 7, k = idx & 127;
        float v = (k <= n) ? skern[n - k] : 0.0f;
        T2[((size_t)h * CL + n) * 192 + k] = __float2half_rn(v);
    }
    for (int idx = t; idx < CL * 64; idx += 256) {
        int n = idx >> 6, e = idx & 63, ns = e >> 1;
        float cwr = scfr[ns] * wr[n + 1][ns] - scfi[ns] * wi[n + 1][ns];
        float cwi = scfr[ns] * wi[n + 1][ns] + scfi[ns] * wr[n + 1][ns];
        float v = (e & 1) ? -cwi : cwr;
        T2[((size_t)h * CL + n) * 192 + 128 + e] = __float2half_rn(v);
    }
    for (int idx = t; idx < 64 * CL; idx += 256) {
        int e = idx >> 7, j = idx & 127, ns = e >> 1;
        int d = CL - 1 - j;
        float v = (e & 1) ? wi[d][ns] : wr[d][ns];
        T1[((size_t)h * 64 + e) * CL + j] = __float2half_rn(v);
    }
}

// =====================================================================
// gemm_end: per h, S_end[NINST x 64] = Uhi[NINST x 128] @ B1hi^T. 1-term.
// =====================================================================
#define E_BOFF  6144u
#define E_STAGE 9216u
#define E_DSMEM (3 * E_STAGE)   /* 27648 */

__global__ __launch_bounds__(256, 2) void gemm_end(int layer)
{
    extern __shared__ __align__(16) char dsmE[];
    int tid = threadIdx.x;
    int warp = tid >> 5, lane = tid & 31;
    int grp = lane >> 2, tq = lane & 3;
    int mt = blockIdx.x, h = blockIdx.y;
    int wm = (warp >> 1) * 32, wn = (warp & 1) * 32;
    int lrow8 = (lane & 7) + (lane & 8);
    int khalf = (lane >> 4) * 16;

    int mloc = tid >> 1, ch = tid & 1;
    int m = mt * 128 + mloc;
    int bb = m >> 5, cc = m & 31;
    const __half* aUh = g_Uhi + ((size_t)(bb * H + h)) * LSEQ + cc * CL;
    int frB = (tid & 127) >> 1, chB = tid & 1;
    const __half* bTh = g_T1hi + ((size_t)layer * H + h) * 64 * CL;

    float acc[2][4][4];
#pragma unroll
    for (int mi = 0; mi < 2; mi++)
#pragma unroll
        for (int ni = 0; ni < 4; ni++)
#pragma unroll
            for (int r = 0; r < 4; r++) acc[mi][ni][r] = 0.0f;

#define LOAD_E(KT, S)                                                            \
    do {                                                                         \
        char* sb = dsmE + (unsigned)(S) * E_STAGE;                               \
        int k0 = (KT) * 16 + ch * 8;                                             \
        cpa16(sb + (unsigned)(mloc * 48 + ch * 16), aUh + k0);                   \
        if (tid < 128) {                                                         \
            int kb = (KT) * 16 + chB * 8;                                        \
            cpa16(sb + E_BOFF + (unsigned)(frB * 48 + chB * 16),                 \
                  bTh + (size_t)frB * CL + kb);                                  \
        }                                                                        \
        asm volatile("cp.async.commit_group;" ::: "memory");                     \
    } while (0)

    LOAD_E(0, 0);
    LOAD_E(1, 1);
    const int NKT = 8;
    for (int kt = 0; kt < NKT; kt++) {
        int s = kt - (kt / 3) * 3;
        if (kt + 2 < NKT) asm volatile("cp.async.wait_group 1;" ::: "memory");
        else              asm volatile("cp.async.wait_group 0;" ::: "memory");
        __syncthreads();
        if (kt + 2 < NKT) {
            int s2 = (kt + 2) - ((kt + 2) / 3) * 3;
            LOAD_E(kt + 2, s2);
        }
        const char* sb = dsmE + (unsigned)s * E_STAGE;
        uint32_t ah[2][4];
#pragma unroll
        for (int mi = 0; mi < 2; mi++) {
            const char* pa = sb + (unsigned)((wm + mi * 16 + lrow8) * 48) + khalf;
            ldsm4(ah[mi][0], ah[mi][1], ah[mi][2], ah[mi][3], pa);
        }
        uint32_t bh[4][2];
#pragma unroll
        for (int p = 0; p < 2; p++) {
            const char* pb = sb + E_BOFF + (unsigned)((wn + p * 16 + lrow8) * 48) + khalf;
            ldsm4(bh[2 * p][0], bh[2 * p + 1][0], bh[2 * p][1], bh[2 * p + 1][1], pb);
        }
#pragma unroll
        for (int ni = 0; ni < 4; ni++)
#pragma unroll
            for (int mi = 0; mi < 2; mi++)
                mma_f16(acc[mi][ni], ah[mi], bh[ni][0], bh[ni][1]);
    }
#pragma unroll
    for (int mi = 0; mi < 2; mi++)
#pragma unroll
        for (int ni = 0; ni < 4; ni++) {
            int r = mt * 128 + wm + mi * 16 + grp;
            int n = wn + ni * 8 + tq * 2;
            __half2 v0 = __floats2half2_rn(acc[mi][ni][0], acc[mi][ni][1]);
            __half2 v1 = __floats2half2_rn(acc[mi][ni][2], acc[mi][ni][3]);
            *(__half2*)&g_E2h[((size_t)h * NINST + r) * 64 + n] = v0;
            *(__half2*)&g_E2h[((size_t)h * NINST + r + 8) * 64 + n] = v1;
        }
}

// =====================================================================
// prefix: combine chunk end states -> per-chunk init states (fp16)
// =====================================================================
__global__ __launch_bounds__(256) void ssm_prefix2(
    const float* __restrict__ log_dt, const float* __restrict__ A_imag,
    const float* __restrict__ log_A_real, int layer)
{
    int idx = blockIdx.x * 256 + threadIdx.x;
    int li = idx & 7;
    int b  = (idx >> 3) & 7;
    int h  = idx >> 6;

    float Are[4], Aim[4], dt;
    scan_coeffs(log_dt, A_imag, log_A_real, layer, h, li, Are, Aim, &dt);
    float Wr[4], Wi[4];
#pragma unroll
    for (int j = 0; j < 4; j++) {
        float e = expf(Are[j] * dt * (float)CL);
        Wr[j] = e * cosf(Aim[j] * dt * (float)CL);
        Wi[j] = e * sinf(Aim[j] * dt * (float)CL);
    }
    float Ire[4] = {0, 0, 0, 0}, Iim[4] = {0, 0, 0, 0};
    for (int c = 0; c < NC; c++) {
        size_t off = ((size_t)h * NINST + b * NC + c) * 64 + li * 8;
#pragma unroll
        for (int j = 0; j < 4; j++) {
            g_Shi[off + 2 * j]     = __float2half_rn(Ire[j]);
            g_Shi[off + 2 * j + 1] = __float2half_rn(Iim[j]);
        }
#pragma unroll
        for (int j = 0; j < 4; j++) {
            float er = __half2float(g_E2h[off + 2 * j]);
            float ei = __half2float(g_E2h[off + 2 * j + 1]);
            float nr = fmaf(Wr[j], Ire[j], fmaf(-Wi[j], Iim[j], er));
            float ni = fmaf(Wi[j], Ire[j], fmaf( Wr[j], Iim[j], ei));
            Ire[j] = nr; Iim[j] = ni;
        }
    }
}

// =====================================================================
// gemm_toep: per h, Y[NINST x 128] = [U|Sinit]hi @ B2hi^T. 1-term.
// Epilogue: GELU + fp16 store (B,H,L).
// =====================================================================
#define T_BOFF  6144u
#define T_STAGE 12288u
#define T_DSMEM (3 * T_STAGE)   /* 36864 */

__global__ __launch_bounds__(256, 2) void gemm_toep(int layer)
{
    extern __shared__ __align__(16) char dsmT[];
    int tid = threadIdx.x;
    int warp = tid >> 5, lane = tid & 31;
    int grp = lane >> 2, tq = lane & 3;
    int mt = blockIdx.x, h = blockIdx.y;
    int wm = (warp >> 1) * 32, wn = (warp & 1) * 64;
    int lrow8 = (lane & 7) + (lane & 8);
    int khalf = (lane >> 4) * 16;

    int mloc = tid >> 1, ch = tid & 1;
    int m = mt * 128 + mloc;
    int bb = m >> 5, cc = m & 31;
    const __half* aUh = g_Uhi + ((size_t)(bb * H + h)) * LSEQ + cc * CL;
    const __half* aSh = g_Shi + ((size_t)h * NINST + m) * 64;
    const __half* bTh = g_T2hi + ((size_t)layer * H + h) * CL * 192;

    float acc[2][8][4];
#pragma unroll
    for (int mi = 0; mi < 2; mi++)
#pragma unroll
        for (int ni = 0; ni < 8; ni++)
#pragma unroll
            for (int r = 0; r < 4; r++) acc[mi][ni][r] = 0.0f;

#define LOAD_T(KT, S)                                                            \
    do {                                                                         \
        char* sb = dsmT + (unsigned)(S) * T_STAGE;                               \
        int k0 = (KT) * 16 + ch * 8;                                             \
        const __half* sh = (k0 < 128) ? aUh + k0 : aSh + (k0 - 128);             \
        cpa16(sb + (unsigned)(mloc * 48 + ch * 16), sh);                         \
        cpa16(sb + T_BOFF + (unsigned)(mloc * 48 + ch * 16),                     \
              bTh + (size_t)mloc * 192 + k0);                                    \
        asm volatile("cp.async.commit_group;" ::: "memory");                     \
    } while (0)

    LOAD_T(0, 0);
    LOAD_T(1, 1);
    const int NKT = 12;
    for (int kt = 0; kt < NKT; kt++) {
        int s = kt - (kt / 3) * 3;
        if (kt + 2 < NKT) asm volatile("cp.async.wait_group 1;" ::: "memory");
        else              asm volatile("cp.async.wait_group 0;" ::: "memory");
        __syncthreads();
        if (kt + 2 < NKT) {
            int s2 = (kt + 2) - ((kt + 2) / 3) * 3;
            LOAD_T(kt + 2, s2);
        }
        const char* sb = dsmT + (unsigned)s * T_STAGE;
        uint32_t ah[2][4];
#pragma unroll
        for (int mi = 0; mi < 2; mi++) {
            const char* pa = sb + (unsigned)((wm + mi * 16 + lrow8) * 48) + khalf;
            ldsm4(ah[mi][0], ah[mi][1], ah[mi][2], ah[mi][3], pa);
        }
        uint32_t bh[8][2];
#pragma unroll
        for (int p = 0; p < 4; p++) {
            const char* pb = sb + T_BOFF + (unsigned)((wn + p * 16 + lrow8) * 48) + khalf;
            ldsm4(bh[2 * p][0], bh[2 * p + 1][0], bh[2 * p][1], bh[2 * p + 1][1], pb);
        }
#pragma unroll
        for (int ni = 0; ni < 8; ni++)
#pragma unroll
            for (int mi = 0; mi < 2; mi++)
                mma_f16(acc[mi][ni], ah[mi], bh[ni][0], bh[ni][1]);
    }
    // epilogue: GELU + fp16 store to (B,H,L)
#pragma unroll
    for (int mi = 0; mi < 2; mi++) {
        int r = mt * 128 + wm + mi * 16 + grp;
        int b0 = r >> 5, c0 = r & 31;
        int r1 = r + 8;
        int b1 = r1 >> 5, c1 = r1 & 31;
        __half* y0 = g_Yt16 + ((size_t)(b0 * H + h)) * LSEQ + c0 * CL;
        __half* y1 = g_Yt16 + ((size_t)(b1 * H + h)) * LSEQ + c1 * CL;
#pragma unroll
        for (int ni = 0; ni < 8; ni++) {
            int n = wn + ni * 8 + tq * 2;
            __half2 v0 = __floats2half2_rn(gelu_f(acc[mi][ni][0]),
                                           gelu_f(acc[mi][ni][1]));
            __half2 v1 = __floats2half2_rn(gelu_f(acc[mi][ni][2]),
                                           gelu_f(acc[mi][ni][3]));
            *(__half2*)(y0 + n) = v0;
            *(__half2*)(y1 + n) = v1;
        }
    }
}

// =====================================================================
// W prep: interleave rows (2i <- a-row i, 2i+1 <- g-row i+H), fp16.
// =====================================================================
__global__ __launch_bounds__(256) void w_prep(const float* __restrict__ W,
                                              const float* __restrict__ bp) {
    size_t i = (size_t)blockIdx.x * 256 + threadIdx.x;
    int col = (int)(i % H);
    int k   = (int)((i / H) % (2 * H));
    int l   = (int)(i / ((size_t)H * 2 * H));
    int orig = (k >> 1) + (k & 1) * H;
    float v = W[((size_t)l * 2 * H + orig) * H + col];
    g_Whi[i] = __float2half_rn(v);
    if (i < NLAY * 2 * H) {
        int kk = (int)(i % (2 * H));
        int ll = (int)(i / (2 * H));
        int og = (kk >> 1) + (kk & 1) * H;
        g_bint[i] = bp[ll * 2 * H + og];
    }
}

// =====================================================================
// conv GEMM + fused GLU: fp16 1-TERM (Y * W), A read DIRECTLY from
// g_Yt16 (B,H,L) using ldmatrix.x4.trans (no ytrans kernel).
// A tile: 16 h-rows x 128 l, smem stride 272B (conflict-free).
// =====================================================================
#define C_BOFF  4608u           /* A region 16*272=4352, padded */
#define C_STAGE 10752u          /* 4608 + 6144 */
#define C_DSMEM (3 * C_STAGE)   /* 32256 */

__global__ __launch_bounds__(256, 2) void conv_gemm(int layer)
{
    extern __shared__ __align__(16) char dsm[];
    int tid = threadIdx.x;
    int warp = tid >> 5, lane = tid & 31;
    int grp = lane >> 2, tq = lane & 3;
    int n0 = blockIdx.x * 128, m0 = blockIdx.y * 128;
    int bB = m0 >> 12;           // batch  (m0 / LSEQ)
    int l0 = m0 & (LSEQ - 1);    // l offset

    const __half* Wh = g_Whi + (size_t)layer * 2 * H * H;

    int wm = (warp >> 1) * 32, wn = (warp & 1) * 64;
    int lrow8 = (lane & 7) + (lane & 8);
    int khalf = (lane >> 4) * 16;
    // trans A addressing: k-row and m-col-byte
    int ktr = ((lane >> 4) & 1) * 8 + (lane & 7);
    int mby = ((lane >> 3) & 1) * 16;

    float acc[2][8][4];
#pragma unroll
    for (int mi = 0; mi < 2; mi++)
#pragma unroll
        for (int ni = 0; ni < 8; ni++)
#pragma unroll
            for (int r = 0; r < 4; r++) acc[mi][ni][r] = 0.0f;

    int fa_r = tid >> 4, fa_c = tid & 15;   // A: 16 rows x 16 chunks
    int fb_r = tid >> 1, fb_c = tid & 1;    // B: 128 rows x 2 chunks

#define LOAD_C(KT, S)                                                            \
    do {                                                                         \
        char* sb = dsm + (unsigned)(S) * C_STAGE;                                \
        cpa16(sb + (unsigned)(fa_r * 272 + fa_c * 16),                           \
              g_Yt16 + ((size_t)(bB * H + (KT) * 16 + fa_r)) * LSEQ + l0 + fa_c * 8); \
        cpa16(sb + C_BOFF + (unsigned)(fb_r * 48 + fb_c * 16),                   \
              Wh + (size_t)(n0 + fb_r) * H + (KT) * 16 + fb_c * 8);              \
        asm volatile("cp.async.commit_group;" ::: "memory");                     \
    } while (0)

    LOAD_C(0, 0);
    LOAD_C(1, 1);

    const int NKT = H / 16;   // 32
    for (int kt = 0; kt < NKT; kt++) {
        int s = kt - (kt / 3) * 3;
        if (kt + 2 < NKT) asm volatile("cp.async.wait_group 1;" ::: "memory");
        else              asm volatile("cp.async.wait_group 0;" ::: "memory");
        __syncthreads();
        if (kt + 2 < NKT) {
            int s2 = (kt + 2) - ((kt + 2) / 3) * 3;
            LOAD_C(kt + 2, s2);
        }
        const char* sb = dsm + (unsigned)s * C_STAGE;
        uint32_t ah[2][4];
#pragma unroll
        for (int mi = 0; mi < 2; mi++) {
            const char* pa = sb + (unsigned)(ktr * 272 + (wm + mi * 16) * 2 + mby);
            ldsm4t(ah[mi][0], ah[mi][1], ah[mi][2], ah[mi][3], pa);
        }
        uint32_t bh[8][2];
#pragma unroll
        for (int p = 0; p < 4; p++) {
            const char* pb = sb + C_BOFF + (unsigned)((wn + p * 16 + lrow8) * 48) + khalf;
            ldsm4(bh[2 * p][0], bh[2 * p + 1][0], bh[2 * p][1], bh[2 * p + 1][1], pb);
        }
#pragma unroll
        for (int ni = 0; ni < 8; ni++)
#pragma unroll
            for (int mi = 0; mi < 2; mi++)
                mma_f16(acc[mi][ni], ah[mi], bh[ni][0], bh[ni][1]);
    }
#pragma unroll
    for (int mi = 0; mi < 2; mi++)
#pragma unroll
        for (int ni = 0; ni < 8; ni++) {
            int r  = m0 + wm + mi * 16 + grp;
            int cb = wn + ni * 8 + tq * 2;
            float ba = g_bint[layer * 2 * H + n0 + cb];
            float bg = g_bint[layer * 2 * H + n0 + cb + 1];
            float a0 = acc[mi][ni][0] + ba, gg0 = acc[mi][ni][1] + bg;
            float a1 = acc[mi][ni][2] + ba, gg1 = acc[mi][ni][3] + bg;
            int hidx = (n0 + cb) >> 1;
            g_Zh[(size_t)r * H + hidx]       = __float2half_rn(a0 / (1.0f + expf(-gg0)));
            g_Zh[(size_t)(r + 8) * H + hidx] = __float2half_rn(a1 / (1.0f + expf(-gg1)));
        }
}

// =====================================================================
// res_ln (final layer): residual + LN, warp per row, fp32 out.
// =====================================================================
__global__ __launch_bounds__(128) void res_ln(
    const float* __restrict__ xin, float* __restrict__ xout,
    const float* __restrict__ gamma, const float* __restrict__ beta, int layer)
{
    int row  = blockIdx.x * 4 + (threadIdx.x >> 5);
    int lane = threadIdx.x & 31;
    const __half2* zh = (const __half2*)(g_Zh + (size_t)row * H);
    const float4* x4 = (const float4*)(xin + (size_t)row * H);
    float4* o4       = (float4*)(xout + (size_t)row * H);
    const float4* g4 = (const float4*)(gamma + layer * H);
    const float4* e4 = (const float4*)(beta + layer * H);

    float4 v[4];
    float s = 0.0f, s2 = 0.0f;
#pragma unroll
    for (int j = 0; j < 4; j++) {
        __half2 p0 = zh[(j * 32 + lane) * 2];
        __half2 p1 = zh[(j * 32 + lane) * 2 + 1];
        float4 xv = x4[j * 32 + lane];
        float4 vv;
        vv.x = __low2float(p0)  + xv.x; vv.y = __high2float(p0) + xv.y;
        vv.z = __low2float(p1)  + xv.z; vv.w = __high2float(p1) + xv.w;
        v[j] = vv;
        s += vv.x + vv.y + vv.z + vv.w;
        s2 = fmaf(vv.x, vv.x, s2); s2 = fmaf(vv.y, vv.y, s2);
        s2 = fmaf(vv.z, vv.z, s2); s2 = fmaf(vv.w, vv.w, s2);
    }
#pragma unroll
    for (int o = 16; o; o >>= 1) {
        s  += __shfl_xor_sync(0xffffffffu, s, o);
        s2 += __shfl_xor_sync(0xffffffffu, s2, o);
    }
    float mu = s * (1.0f / H);
    float rs = rsqrtf(s2 * (1.0f / H) - mu * mu + LN_EPS);
#pragma unroll
    for (int j = 0; j < 4; j++) {
        float4 ga = g4[j * 32 + lane];
        float4 be = e4[j * 32 + lane];
        float4 vv = v[j], o;
        o.x = (vv.x - mu) * rs * ga.x + be.x;
        o.y = (vv.y - mu) * rs * ga.y + be.y;
        o.z = (vv.z - mu) * rs * ga.z + be.z;
        o.w = (vv.w - mu) * rs * ga.w + be.w;
        o4[j * 32 + lane] = o;
    }
}

// =====================================================================
// res_lnT (layers 0..2): residual + LN + fp32 xout AND transposed
// fp16 U plane (B,H,L). 32 rows x 512 h per block.
// =====================================================================
#define RL_SMEM (32 * 513 * 4)   /* 65664 */
__global__ __launch_bounds__(256) void res_lnT(
    const float* __restrict__ xin, float* __restrict__ xout,
    const float* __restrict__ gamma, const float* __restrict__ beta, int layer)
{
    extern __shared__ float sv[];    // [32][513]
    int warp = threadIdx.x >> 5, lane = threadIdx.x & 31;
    int row0 = blockIdx.x * 32;
    int b = row0 >> 12;
    int l0 = row0 & (LSEQ - 1);
    const float4* g4 = (const float4*)(gamma + layer * H);
    const float4* e4 = (const float4*)(beta + layer * H);

#pragma unroll
    for (int i = 0; i < 4; i++) {
        int lr = warp * 4 + i;
        int row = row0 + lr;
        const __half2* zh = (const __half2*)(g_Zh + (size_t)row * H);
        const float4* x4 = (const float4*)(xin + (size_t)row * H);
        float4* o4 = (float4*)(xout + (size_t)row * H);
        float4 v[4];
        float s = 0.0f, s2 = 0.0f;
#pragma unroll
        for (int j = 0; j < 4; j++) {
            __half2 p0 = zh[(j * 32 + lane) * 2];
            __half2 p1 = zh[(j * 32 + lane) * 2 + 1];
            float4 xv = x4[j * 32 + lane];
            float4 vv;
            vv.x = __low2float(p0)  + xv.x; vv.y = __high2float(p0) + xv.y;
            vv.z = __low2float(p1)  + xv.z; vv.w = __high2float(p1) + xv.w;
            v[j] = vv;
            s += vv.x + vv.y + vv.z + vv.w;
            s2 = fmaf(vv.x, vv.x, s2); s2 = fmaf(vv.y, vv.y, s2);
            s2 = fmaf(vv.z, vv.z, s2); s2 = fmaf(vv.w, vv.w, s2);
        }
#pragma unroll
        for (int o = 16; o; o >>= 1) {
            s  += __shfl_xor_sync(0xffffffffu, s, o);
            s2 += __shfl_xor_sync(0xffffffffu, s2, o);
        }
        float mu = s * (1.0f / H);
        float rs = rsqrtf(s2 * (1.0f / H) - mu * mu + LN_EPS);
#pragma unroll
        for (int j = 0; j < 4; j++) {
            float4 ga = g4[j * 32 + lane];
            float4 be = e4[j * 32 + lane];
            float4 vv = v[j], o;
            o.x = (vv.x - mu) * rs * ga.x + be.x;
            o.y = (vv.y - mu) * rs * ga.y + be.y;
            o.z = (vv.z - mu) * rs * ga.z + be.z;
            o.w = (vv.w - mu) * rs * ga.w + be.w;
            o4[j * 32 + lane] = o;
            int hh = (j * 32 + lane) * 4;
            sv[lr * 513 + hh + 0] = o.x;
            sv[lr * 513 + hh + 1] = o.y;
            sv[lr * 513 + hh + 2] = o.z;
            sv[lr * 513 + hh + 3] = o.w;
        }
    }
    __syncthreads();
#pragma unroll 4
    for (int it = 0; it < 64; it++) {
        int h = it * 8 + warp;
        float v = sv[lane * 513 + h];
        g_Uhi[((size_t)(b * H + h)) * LSEQ + l0 + lane] = __float2half_rn(v);
    }
}

// ================= launcher =================
extern "C" void kernel_launch(void* const* d_in, const int* in_sizes, int n_in,
                              void* d_out, int out_size)
{
    const float* x          = (const float*)d_in[0];
    const float* log_dt     = (const float*)d_in[1];
    const float* A_imag     = (const float*)d_in[2];
    const float* log_A_real = (const float*)d_in[3];
    const float* C          = (const float*)d_in[4];
    const float* D          = (const float*)d_in[5];
    const float* W          = (const float*)d_in[6];
    const float* bconv      = (const float*)d_in[7];
    const float* gamma      = (const float*)d_in[8];
    const float* beta       = (const float*)d_in[9];
    float* out = (float*)d_out;

    cudaFuncSetAttribute(conv_gemm, cudaFuncAttributeMaxDynamicSharedMemorySize,
                         C_DSMEM);
    cudaFuncSetAttribute(gemm_toep, cudaFuncAttributeMaxDynamicSharedMemorySize,
                         T_DSMEM);
    cudaFuncSetAttribute(gemm_end, cudaFuncAttributeMaxDynamicSharedMemorySize,
                         E_DSMEM);
    cudaFuncSetAttribute(res_lnT, cudaFuncAttributeMaxDynamicSharedMemorySize,
                         RL_SMEM);

    float* pA; cudaGetSymbolAddress((void**)&pA, g_xA);
    float* pB; cudaGetSymbolAddress((void**)&pB, g_xB);
    const float* xin[NLAY]  = {x,  pA, pB, pA};
    float*       xout[NLAY] = {pA, pB, pA, out};

    w_prep<<<(NLAY * 2 * H * H) / 256, 256>>>(W, bconv);
    tbuild<<<dim3(H, NLAY), 256>>>(log_dt, A_imag, log_A_real, C, D);

    dim3 tb(32, 8);
    xsplit<<<dim3(H / 32, LSEQ / 32, BSZ), tb>>>(x);   // layer-0 U plane

    for (int i = 0; i < NLAY; i++) {
        gemm_end<<<dim3(2, H), 256, E_DSMEM>>>(i);
        ssm_prefix2<<<(H * BSZ * 8) / 256, 256>>>(log_dt, A_imag, log_A_real, i);
        gemm_toep<<<dim3(2, H), 256, T_DSMEM>>>(i);
        conv_gemm<<<dim3(2 * H / 128, MROWS / 128), 256, C_DSMEM>>>(i);
        if (i < NLAY - 1)
            res_lnT<<<MROWS / 32, 256, RL_SMEM>>>(xin[i], xout[i], gamma, beta, i);
        else
            res_ln<<<MROWS / 4, 128>>>(xin[i], xout[i], gamma, beta, i);
    }
}

// round 15
// speedup vs baseline: 2.6938x; 1.0948x over previous
#include <cuda_runtime.h>
#include <cuda_fp16.h>
#include <cstdint>

#define H     512
#define NLAY  4
#define N2    32
#define BSZ   8
#define LSEQ  4096
#define MROWS (BSZ * LSEQ)      /* 32768 */
#define NC    32                /* chunks per sequence */
#define CL    (LSEQ / NC)       /* 128 */
#define NINST (BSZ * NC)        /* 256 instances per h */
#define LN_EPS 1e-5f

// ---- static scratch ----
__device__ __align__(256) __half g_x16A[(size_t)MROWS * H];   // residual fp16 ping
__device__ __align__(256) __half g_x16B[(size_t)MROWS * H];   // residual fp16 pong
__device__ __align__(256) __half g_Uhi [(size_t)MROWS * H];   // u (B,H,L)
__device__ __align__(256) __half g_Yt16[(size_t)MROWS * H];   // gelu(y) (B,H,L)
__device__ __align__(256) __half g_Whi[(size_t)NLAY * 2 * H * H];
__device__ __align__(256) float g_bint[NLAY * 2 * H];
__device__ __align__(256) __half g_Zh[(size_t)MROWS * H];     // GLU out (B,L,H)
// Toeplitz machinery (ALL layers, built once)
__device__ __align__(256) __half g_T2hi[(size_t)NLAY * H * CL * 192];
__device__ __align__(256) __half g_T1hi[(size_t)NLAY * H * 64 * CL];
__device__ __align__(256) __half g_Shi[(size_t)H * NINST * 64]; // init states

// ---------------- helpers ----------------
__device__ __forceinline__ void cpa16(void* dst, const void* src) {
    unsigned d = (unsigned)__cvta_generic_to_shared(dst);
    asm volatile("cp.async.cg.shared.global [%0], [%1], 16;" :: "r"(d), "l"(src));
}
__device__ __forceinline__ void ldsm4(uint32_t& r0, uint32_t& r1, uint32_t& r2,
                                      uint32_t& r3, const void* p) {
    uint32_t a = (uint32_t)__cvta_generic_to_shared(p);
    asm volatile("ldmatrix.sync.aligned.m8n8.x4.shared.b16 {%0,%1,%2,%3}, [%4];"
                 : "=r"(r0), "=r"(r1), "=r"(r2), "=r"(r3) : "r"(a));
}
__device__ __forceinline__ void ldsm4t(uint32_t& r0, uint32_t& r1, uint32_t& r2,
                                       uint32_t& r3, const void* p) {
    uint32_t a = (uint32_t)__cvta_generic_to_shared(p);
    asm volatile("ldmatrix.sync.aligned.m8n8.x4.trans.shared.b16 {%0,%1,%2,%3}, [%4];"
                 : "=r"(r0), "=r"(r1), "=r"(r2), "=r"(r3) : "r"(a));
}
__device__ __forceinline__ void mma_f16(float* d, const uint32_t* a,
                                        uint32_t b0, uint32_t b1) {
    asm volatile(
        "mma.sync.aligned.m16n8k16.row.col.f32.f16.f16.f32 "
        "{%0,%1,%2,%3}, {%4,%5,%6,%7}, {%8,%9}, {%0,%1,%2,%3};"
        : "+f"(d[0]), "+f"(d[1]), "+f"(d[2]), "+f"(d[3])
        : "r"(a[0]), "r"(a[1]), "r"(a[2]), "r"(a[3]), "r"(b0), "r"(b1));
}
__device__ __forceinline__ float gelu_f(float v) {
    return 0.5f * v * (1.0f + erff(v * 0.70710678118654752f));
}

// =====================================================================
// xsplit: (B,L,H) fp32 -> (B,H,L) fp16 (layer 0 only)
// =====================================================================
__global__ __launch_bounds__(256) void xsplit(const float* __restrict__ x) {
    __shared__ float tile[32][33];
    int b = blockIdx.z, h0 = blockIdx.x * 32, l0 = blockIdx.y * 32;
    int tx = threadIdx.x, ty = threadIdx.y;
#pragma unroll
    for (int j = 0; j < 32; j += 8)
        tile[ty + j][tx] = x[((size_t)b * LSEQ + l0 + ty + j) * H + h0 + tx];
    __syncthreads();
#pragma unroll
    for (int j = 0; j < 32; j += 8) {
        size_t o = ((size_t)(b * H + h0 + ty + j)) * LSEQ + l0 + tx;
        g_Uhi[o] = __float2half_rn(tile[tx][ty + j]);
    }
}

// =====================================================================
// tbuild: per-(h,layer) Toeplitz kernel, correction V, end-state E.
// =====================================================================
__global__ __launch_bounds__(256) void tbuild(
    const float* __restrict__ log_dt, const float* __restrict__ A_imag,
    const float* __restrict__ log_A_real, const float* __restrict__ Cp,
    const float* __restrict__ Dp)
{
    __shared__ float wr[CL + 1][32], wi[CL + 1][32];
    __shared__ float scfr[32], scfi[32], skern[CL];
    __shared__ float sD;
    int h = blockIdx.x;
    int layer = blockIdx.y;
    int t = threadIdx.x;
    __half* T2 = g_T2hi + (size_t)layer * H * CL * 192;
    __half* T1 = g_T1hi + (size_t)layer * H * 64 * CL;
    if (t == 0) sD = Dp[layer * H + h];
    if (t < 32) {
        int n = t;
        float dt = expf(log_dt[layer * H + h]);
        float Are = -expf(log_A_real[(layer * H + h) * N2 + n]);
        float Aim = A_imag[(layer * H + h) * N2 + n];
        float e1 = expf(Are * dt);
        float w1r = e1 * cosf(Aim * dt), w1i = e1 * sinf(Aim * dt);
        float nr = w1r - 1.0f, ni = w1i;
        float cr = Cp[((layer * H + h) * N2 + n) * 2 + 0];
        float ci = Cp[((layer * H + h) * N2 + n) * 2 + 1];
        float tr = cr * nr - ci * ni;
        float ti = cr * ni + ci * nr;
        float inv = 2.0f / (Are * Are + Aim * Aim);
        scfr[n] = (tr * Are + ti * Aim) * inv;
        scfi[n] = (ti * Are - tr * Aim) * inv;
        float pr = 1.0f, pi = 0.0f;
        for (int d = 0; d <= CL; d++) {
            wr[d][n] = pr; wi[d][n] = pi;
            float npr = pr * w1r - pi * w1i;
            float npi = pr * w1i + pi * w1r;
            pr = npr; pi = npi;
        }
    }
    __syncthreads();
    if (t < CL) {
        float acc = (t == 0) ? sD : 0.0f;
#pragma unroll 8
        for (int n = 0; n < 32; n++)
            acc += scfr[n] * wr[t][n] - scfi[n] * wi[t][n];
        skern[t] = acc;
    }
    __syncthreads();
    for (int idx = t; idx < CL * CL; idx += 256) {
        int n = idx >> 7, k = idx & 127;
        float v = (k <= n) ? skern[n - k] : 0.0f;
        T2[((size_t)h * CL + n) * 192 + k] = __float2half_rn(v);
    }
    for (int idx = t; idx < CL * 64; idx += 256) {
        int n = idx >> 6, e = idx & 63, ns = e >> 1;
        float cwr = scfr[ns] * wr[n + 1][ns] - scfi[ns] * wi[n + 1][ns];
        float cwi = scfr[ns] * wi[n + 1][ns] + scfi[ns] * wr[n + 1][ns];
        float v = (e & 1) ? -cwi : cwr;
        T2[((size_t)h * CL + n) * 192 + 128 + e] = __float2half_rn(v);
    }
    for (int idx = t; idx < 64 * CL; idx += 256) {
        int e = idx >> 7, j = idx & 127, ns = e >> 1;
        int d = CL - 1 - j;
        float v = (e & 1) ? wi[d][ns] : wr[d][ns];
        T1[((size_t)h * 64 + e) * CL + j] = __float2half_rn(v);
    }
}

// =====================================================================
// gemm_endpre: per h, S_end[256 x 64] = Uhi @ B1hi^T, then in-block
// prefix over chunks -> g_Shi. grid (H), 256 threads.
// Stages 3 x 15360B; E overlay 256x66 halves (33792B) unioned.
// =====================================================================
#define EP_BOFF  12288u
#define EP_STAGE 15360u
#define EP_DSMEM 46080u

__global__ __launch_bounds__(256, 2) void gemm_endpre(
    const float* __restrict__ log_dt, const float* __restrict__ A_imag,
    const float* __restrict__ log_A_real, int layer)
{
    extern __shared__ __align__(16) char dsmP[];
    int tid = threadIdx.x;
    int warp = tid >> 5, lane = tid & 31;
    int grp = lane >> 2, tq = lane & 3;
    int h = blockIdx.x;
    int wm = warp * 32;
    int lrow8 = (lane & 7) + (lane & 8);
    int khalf = (lane >> 4) * 16;

    int bb = tid >> 5, cc = tid & 31;   // A loader: row tid
    const __half* aU = g_Uhi + ((size_t)(bb * H + h)) * LSEQ + cc * CL;
    const __half* bTh = g_T1hi + ((size_t)layer * H + h) * 64 * CL;

    float acc[2][8][4];
#pragma unroll
    for (int mi = 0; mi < 2; mi++)
#pragma unroll
        for (int ni = 0; ni < 8; ni++)
#pragma unroll
            for (int r = 0; r < 4; r++) acc[mi][ni][r] = 0.0f;

#define LOAD_EP(KT, S)                                                           \
    do {                                                                         \
        char* sb = dsmP + (unsigned)(S) * EP_STAGE;                              \
        cpa16(sb + (unsigned)(tid * 48),      aU + (KT) * 16);                   \
        cpa16(sb + (unsigned)(tid * 48 + 16), aU + (KT) * 16 + 8);               \
        if (tid < 128)                                                           \
            cpa16(sb + EP_BOFF + (unsigned)((tid >> 1) * 48 + (tid & 1) * 16),   \
                  bTh + (size_t)(tid >> 1) * CL + (KT) * 16 + (tid & 1) * 8);    \
        asm volatile("cp.async.commit_group;" ::: "memory");                     \
    } while (0)

    LOAD_EP(0, 0);
    LOAD_EP(1, 1);
    const int NKT = 8;
    for (int kt = 0; kt < NKT; kt++) {
        int s = kt - (kt / 3) * 3;
        if (kt + 2 < NKT) asm volatile("cp.async.wait_group 1;" ::: "memory");
        else              asm volatile("cp.async.wait_group 0;" ::: "memory");
        __syncthreads();
        if (kt + 2 < NKT) {
            int s2 = (kt + 2) - ((kt + 2) / 3) * 3;
            LOAD_EP(kt + 2, s2);
        }
        const char* sb = dsmP + (unsigned)s * EP_STAGE;
        uint32_t ah[2][4];
#pragma unroll
        for (int mi = 0; mi < 2; mi++) {
            const char* pa = sb + (unsigned)((wm + mi * 16 + lrow8) * 48) + khalf;
            ldsm4(ah[mi][0], ah[mi][1], ah[mi][2], ah[mi][3], pa);
        }
        uint32_t bh[8][2];
#pragma unroll
        for (int p = 0; p < 4; p++) {
            const char* pb = sb + EP_BOFF + (unsigned)((p * 16 + lrow8) * 48) + khalf;
            ldsm4(bh[2 * p][0], bh[2 * p + 1][0], bh[2 * p][1], bh[2 * p + 1][1], pb);
        }
#pragma unroll
        for (int ni = 0; ni < 8; ni++)
#pragma unroll
            for (int mi = 0; mi < 2; mi++)
                mma_f16(acc[mi][ni], ah[mi], bh[ni][0], bh[ni][1]);
    }
    __syncthreads();   // done with pipeline smem; overlay E

    __half (*E)[66] = (__half(*)[66])dsmP;
#pragma unroll
    for (int mi = 0; mi < 2; mi++) {
        int r = wm + mi * 16 + grp;
#pragma unroll
        for (int ni = 0; ni < 8; ni++) {
            int cidx = ni * 8 + tq * 2;
            *(__half2*)&E[r][cidx]     = __floats2half2_rn(acc[mi][ni][0], acc[mi][ni][1]);
            *(__half2*)&E[r + 8][cidx] = __floats2half2_rn(acc[mi][ni][2], acc[mi][ni][3]);
        }
    }
    __syncthreads();

    // prefix: thread = (b, n) complex chain over 32 chunks
    {
        int b = tid >> 5, n = tid & 31;
        float dt = expf(log_dt[layer * H + h]);
        float Are = -expf(log_A_real[(layer * H + h) * N2 + n]);
        float Aim = A_imag[(layer * H + h) * N2 + n];
        float e = expf(Are * dt * (float)CL);
        float Wr = e * cosf(Aim * dt * (float)CL);
        float Wi = e * sinf(Aim * dt * (float)CL);
        float Ir = 0.0f, Ii = 0.0f;
        __half* Sp = g_Shi + ((size_t)h * NINST + b * 32) * 64 + 2 * n;
#pragma unroll 4
        for (int c = 0; c < NC; c++) {
            *(__half2*)(Sp + (size_t)c * 64) = __floats2half2_rn(Ir, Ii);
            float er = __half2float(E[b * 32 + c][2 * n]);
            float ei = __half2float(E[b * 32 + c][2 * n + 1]);
            float nr = fmaf(Wr, Ir, fmaf(-Wi, Ii, er));
            float ni = fmaf(Wi, Ir, fmaf( Wr, Ii, ei));
            Ir = nr; Ii = ni;
        }
    }
}

// =====================================================================
// gemm_toep: per h, Y[NINST x 128] = [U|Sinit]hi @ B2hi^T. 1-term.
// Epilogue: GELU + fp16 store (B,H,L).
// =====================================================================
#define T_BOFF  6144u
#define T_STAGE 12288u
#define T_DSMEM (3 * T_STAGE)   /* 36864 */

__global__ __launch_bounds__(256, 2) void gemm_toep(int layer)
{
    extern __shared__ __align__(16) char dsmT[];
    int tid = threadIdx.x;
    int warp = tid >> 5, lane = tid & 31;
    int grp = lane >> 2, tq = lane & 3;
    int mt = blockIdx.x, h = blockIdx.y;
    int wm = (warp >> 1) * 32, wn = (warp & 1) * 64;
    int lrow8 = (lane & 7) + (lane & 8);
    int khalf = (lane >> 4) * 16;

    int mloc = tid >> 1, ch = tid & 1;
    int m = mt * 128 + mloc;
    int bb = m >> 5, cc = m & 31;
    const __half* aUh = g_Uhi + ((size_t)(bb * H + h)) * LSEQ + cc * CL;
    const __half* aSh = g_Shi + ((size_t)h * NINST + m) * 64;
    const __half* bTh = g_T2hi + ((size_t)layer * H + h) * CL * 192;

    float acc[2][8][4];
#pragma unroll
    for (int mi = 0; mi < 2; mi++)
#pragma unroll
        for (int ni = 0; ni < 8; ni++)
#pragma unroll
            for (int r = 0; r < 4; r++) acc[mi][ni][r] = 0.0f;

#define LOAD_T(KT, S)                                                            \
    do {                                                                         \
        char* sb = dsmT + (unsigned)(S) * T_STAGE;                               \
        int k0 = (KT) * 16 + ch * 8;                                             \
        const __half* sh = (k0 < 128) ? aUh + k0 : aSh + (k0 - 128);             \
        cpa16(sb + (unsigned)(mloc * 48 + ch * 16), sh);                         \
        cpa16(sb + T_BOFF + (unsigned)(mloc * 48 + ch * 16),                     \
              bTh + (size_t)mloc * 192 + k0);                                    \
        asm volatile("cp.async.commit_group;" ::: "memory");                     \
    } while (0)

    LOAD_T(0, 0);
    LOAD_T(1, 1);
    const int NKT = 12;
    for (int kt = 0; kt < NKT; kt++) {
        int s = kt - (kt / 3) * 3;
        if (kt + 2 < NKT) asm volatile("cp.async.wait_group 1;" ::: "memory");
        else              asm volatile("cp.async.wait_group 0;" ::: "memory");
        __syncthreads();
        if (kt + 2 < NKT) {
            int s2 = (kt + 2) - ((kt + 2) / 3) * 3;
            LOAD_T(kt + 2, s2);
        }
        const char* sb = dsmT + (unsigned)s * T_STAGE;
        uint32_t ah[2][4];
#pragma unroll
        for (int mi = 0; mi < 2; mi++) {
            const char* pa = sb + (unsigned)((wm + mi * 16 + lrow8) * 48) + khalf;
            ldsm4(ah[mi][0], ah[mi][1], ah[mi][2], ah[mi][3], pa);
        }
        uint32_t bh[8][2];
#pragma unroll
        for (int p = 0; p < 4; p++) {
            const char* pb = sb + T_BOFF + (unsigned)((wn + p * 16 + lrow8) * 48) + khalf;
            ldsm4(bh[2 * p][0], bh[2 * p + 1][0], bh[2 * p][1], bh[2 * p + 1][1], pb);
        }
#pragma unroll
        for (int ni = 0; ni < 8; ni++)
#pragma unroll
            for (int mi = 0; mi < 2; mi++)
                mma_f16(acc[mi][ni], ah[mi], bh[ni][0], bh[ni][1]);
    }
#pragma unroll
    for (int mi = 0; mi < 2; mi++) {
        int r = mt * 128 + wm + mi * 16 + grp;
        int b0 = r >> 5, c0 = r & 31;
        int r1 = r + 8;
        int b1 = r1 >> 5, c1 = r1 & 31;
        __half* y0 = g_Yt16 + ((size_t)(b0 * H + h)) * LSEQ + c0 * CL;
        __half* y1 = g_Yt16 + ((size_t)(b1 * H + h)) * LSEQ + c1 * CL;
#pragma unroll
        for (int ni = 0; ni < 8; ni++) {
            int n = wn + ni * 8 + tq * 2;
            *(__half2*)(y0 + n) = __floats2half2_rn(gelu_f(acc[mi][ni][0]),
                                                    gelu_f(acc[mi][ni][1]));
            *(__half2*)(y1 + n) = __floats2half2_rn(gelu_f(acc[mi][ni][2]),
                                                    gelu_f(acc[mi][ni][3]));
        }
    }
}

// =====================================================================
// W prep: interleave rows, fp16.
// =====================================================================
__global__ __launch_bounds__(256) void w_prep(const float* __restrict__ W,
                                              const float* __restrict__ bp) {
    size_t i = (size_t)blockIdx.x * 256 + threadIdx.x;
    int col = (int)(i % H);
    int k   = (int)((i / H) % (2 * H));
    int l   = (int)(i / ((size_t)H * 2 * H));
    int orig = (k >> 1) + (k & 1) * H;
    float v = W[((size_t)l * 2 * H + orig) * H + col];
    g_Whi[i] = __float2half_rn(v);
    if (i < NLAY * 2 * H) {
        int kk = (int)(i % (2 * H));
        int ll = (int)(i / (2 * H));
        int og = (kk >> 1) + (kk & 1) * H;
        g_bint[i] = bp[ll * 2 * H + og];
    }
}

// =====================================================================
// conv GEMM + fused GLU: 1-term, A via ldmatrix.x4.trans from (B,H,L).
// =====================================================================
#define C_BOFF  4608u
#define C_STAGE 10752u
#define C_DSMEM (3 * C_STAGE)   /* 32256 */

__global__ __launch_bounds__(256, 2) void conv_gemm(int layer)
{
    extern __shared__ __align__(16) char dsm[];
    int tid = threadIdx.x;
    int warp = tid >> 5, lane = tid & 31;
    int grp = lane >> 2, tq = lane & 3;
    int n0 = blockIdx.x * 128, m0 = blockIdx.y * 128;
    int bB = m0 >> 12;
    int l0 = m0 & (LSEQ - 1);

    const __half* Wh = g_Whi + (size_t)layer * 2 * H * H;

    int wm = (warp >> 1) * 32, wn = (warp & 1) * 64;
    int lrow8 = (lane & 7) + (lane & 8);
    int khalf = (lane >> 4) * 16;
    int ktr = ((lane >> 4) & 1) * 8 + (lane & 7);
    int mby = ((lane >> 3) & 1) * 16;

    float acc[2][8][4];
#pragma unroll
    for (int mi = 0; mi < 2; mi++)
#pragma unroll
        for (int ni = 0; ni < 8; ni++)
#pragma unroll
            for (int r = 0; r < 4; r++) acc[mi][ni][r] = 0.0f;

    int fa_r = tid >> 4, fa_c = tid & 15;
    int fb_r = tid >> 1, fb_c = tid & 1;

#define LOAD_C(KT, S)                                                            \
    do {                                                                         \
        char* sb = dsm + (unsigned)(S) * C_STAGE;                                \
        cpa16(sb + (unsigned)(fa_r * 272 + fa_c * 16),                           \
              g_Yt16 + ((size_t)(bB * H + (KT) * 16 + fa_r)) * LSEQ + l0 + fa_c * 8); \
        cpa16(sb + C_BOFF + (unsigned)(fb_r * 48 + fb_c * 16),                   \
              Wh + (size_t)(n0 + fb_r) * H + (KT) * 16 + fb_c * 8);              \
        asm volatile("cp.async.commit_group;" ::: "memory");                     \
    } while (0)

    LOAD_C(0, 0);
    LOAD_C(1, 1);

    const int NKT = H / 16;   // 32
    for (int kt = 0; kt < NKT; kt++) {
        int s = kt - (kt / 3) * 3;
        if (kt + 2 < NKT) asm volatile("cp.async.wait_group 1;" ::: "memory");
        else              asm volatile("cp.async.wait_group 0;" ::: "memory");
        __syncthreads();
        if (kt + 2 < NKT) {
            int s2 = (kt + 2) - ((kt + 2) / 3) * 3;
            LOAD_C(kt + 2, s2);
        }
        const char* sb = dsm + (unsigned)s * C_STAGE;
        uint32_t ah[2][4];
#pragma unroll
        for (int mi = 0; mi < 2; mi++) {
            const char* pa = sb + (unsigned)(ktr * 272 + (wm + mi * 16) * 2 + mby);
            ldsm4t(ah[mi][0], ah[mi][1], ah[mi][2], ah[mi][3], pa);
        }
        uint32_t bh[8][2];
#pragma unroll
        for (int p = 0; p < 4; p++) {
            const char* pb = sb + C_BOFF + (unsigned)((wn + p * 16 + lrow8) * 48) + khalf;
            ldsm4(bh[2 * p][0], bh[2 * p + 1][0], bh[2 * p][1], bh[2 * p + 1][1], pb);
        }
#pragma unroll
        for (int ni = 0; ni < 8; ni++)
#pragma unroll
            for (int mi = 0; mi < 2; mi++)
                mma_f16(acc[mi][ni], ah[mi], bh[ni][0], bh[ni][1]);
    }
#pragma unroll
    for (int mi = 0; mi < 2; mi++)
#pragma unroll
        for (int ni = 0; ni < 8; ni++) {
            int r  = m0 + wm + mi * 16 + grp;
            int cb = wn + ni * 8 + tq * 2;
            float ba = g_bint[layer * 2 * H + n0 + cb];
            float bg = g_bint[layer * 2 * H + n0 + cb + 1];
            float a0 = acc[mi][ni][0] + ba, gg0 = acc[mi][ni][1] + bg;
            float a1 = acc[mi][ni][2] + ba, gg1 = acc[mi][ni][3] + bg;
            int hidx = (n0 + cb) >> 1;
            g_Zh[(size_t)r * H + hidx]       = __float2half_rn(a0 / (1.0f + expf(-gg0)));
            g_Zh[(size_t)(r + 8) * H + hidx] = __float2half_rn(a1 / (1.0f + expf(-gg1)));
        }
}

// =====================================================================
// res_ln_final: residual (fp16 xin) + LN -> fp32 out. warp per row.
// =====================================================================
__global__ __launch_bounds__(128) void res_ln_final(
    const __half* __restrict__ xin, float* __restrict__ xout,
    const float* __restrict__ gamma, const float* __restrict__ beta, int layer)
{
    int row  = blockIdx.x * 4 + (threadIdx.x >> 5);
    int lane = threadIdx.x & 31;
    const __half2* zh = (const __half2*)(g_Zh + (size_t)row * H);
    const __half2* xh = (const __half2*)(xin + (size_t)row * H);
    float4* o4       = (float4*)(xout + (size_t)row * H);
    const float4* g4 = (const float4*)(gamma + layer * H);
    const float4* e4 = (const float4*)(beta + layer * H);

    float4 v[4];
    float s = 0.0f, s2 = 0.0f;
#pragma unroll
    for (int j = 0; j < 4; j++) {
        __half2 p0 = zh[(j * 32 + lane) * 2];
        __half2 p1 = zh[(j * 32 + lane) * 2 + 1];
        __half2 x0 = xh[(j * 32 + lane) * 2];
        __half2 x1 = xh[(j * 32 + lane) * 2 + 1];
        float4 vv;
        vv.x = __low2float(p0) + __low2float(x0);
        vv.y = __high2float(p0) + __high2float(x0);
        vv.z = __low2float(p1) + __low2float(x1);
        vv.w = __high2float(p1) + __high2float(x1);
        v[j] = vv;
        s += vv.x + vv.y + vv.z + vv.w;
        s2 = fmaf(vv.x, vv.x, s2); s2 = fmaf(vv.y, vv.y, s2);
        s2 = fmaf(vv.z, vv.z, s2); s2 = fmaf(vv.w, vv.w, s2);
    }
#pragma unroll
    for (int o = 16; o; o >>= 1) {
        s  += __shfl_xor_sync(0xffffffffu, s, o);
        s2 += __shfl_xor_sync(0xffffffffu, s2, o);
    }
    float mu = s * (1.0f / H);
    float rs = rsqrtf(s2 * (1.0f / H) - mu * mu + LN_EPS);
#pragma unroll
    for (int j = 0; j < 4; j++) {
        float4 ga = g4[j * 32 + lane];
        float4 be = e4[j * 32 + lane];
        float4 vv = v[j], o;
        o.x = (vv.x - mu) * rs * ga.x + be.x;
        o.y = (vv.y - mu) * rs * ga.y + be.y;
        o.z = (vv.z - mu) * rs * ga.z + be.z;
        o.w = (vv.w - mu) * rs * ga.w + be.w;
        o4[j * 32 + lane] = o;
    }
}

// =====================================================================
// res_lnT (layers 0..2): residual + LN; writes fp16 xout (B,L,H) and
// transposed fp16 U plane (B,H,L). IN32: layer 0 reads fp32 x.
// =====================================================================
#define RL_SMEM (32 * 513 * 4)   /* 65664 */
template <int IN32>
__global__ __launch_bounds__(256) void res_lnT(
    const float* __restrict__ xin32, const __half* __restrict__ xin16,
    __half* __restrict__ xout16,
    const float* __restrict__ gamma, const float* __restrict__ beta, int layer)
{
    extern __shared__ float sv[];    // [32][513]
    int warp = threadIdx.x >> 5, lane = threadIdx.x & 31;
    int row0 = blockIdx.x * 32;
    int b = row0 >> 12;
    int l0 = row0 & (LSEQ - 1);
    const float4* g4 = (const float4*)(gamma + layer * H);
    const float4* e4 = (const float4*)(beta + layer * H);

#pragma unroll
    for (int i = 0; i < 4; i++) {
        int lr = warp * 4 + i;
        int row = row0 + lr;
        const __half2* zh = (const __half2*)(g_Zh + (size_t)row * H);
        __half2* oh = (__half2*)(xout16 + (size_t)row * H);
        float4 v[4];
        float s = 0.0f, s2 = 0.0f;
#pragma unroll
        for (int j = 0; j < 4; j++) {
            __half2 p0 = zh[(j * 32 + lane) * 2];
            __half2 p1 = zh[(j * 32 + lane) * 2 + 1];
            float4 xv;
            if (IN32) {
                xv = ((const float4*)(xin32 + (size_t)row * H))[j * 32 + lane];
            } else {
                const __half2* xh = (const __half2*)(xin16 + (size_t)row * H);
                __half2 x0 = xh[(j * 32 + lane) * 2];
                __half2 x1 = xh[(j * 32 + lane) * 2 + 1];
                xv.x = __low2float(x0); xv.y = __high2float(x0);
                xv.z = __low2float(x1); xv.w = __high2float(x1);
            }
            float4 vv;
            vv.x = __low2float(p0)  + xv.x; vv.y = __high2float(p0) + xv.y;
            vv.z = __low2float(p1)  + xv.z; vv.w = __high2float(p1) + xv.w;
            v[j] = vv;
            s += vv.x + vv.y + vv.z + vv.w;
            s2 = fmaf(vv.x, vv.x, s2); s2 = fmaf(vv.y, vv.y, s2);
            s2 = fmaf(vv.z, vv.z, s2); s2 = fmaf(vv.w, vv.w, s2);
        }
#pragma unroll
        for (int o = 16; o; o >>= 1) {
            s  += __shfl_xor_sync(0xffffffffu, s, o);
            s2 += __shfl_xor_sync(0xffffffffu, s2, o);
        }
        float mu = s * (1.0f / H);
        float rs = rsqrtf(s2 * (1.0f / H) - mu * mu + LN_EPS);
#pragma unroll
        for (int j = 0; j < 4; j++) {
            float4 ga = g4[j * 32 + lane];
            float4 be = e4[j * 32 + lane];
            float4 vv = v[j], o;
            o.x = (vv.x - mu) * rs * ga.x + be.x;
            o.y = (vv.y - mu) * rs * ga.y + be.y;
            o.z = (vv.z - mu) * rs * ga.z + be.z;
            o.w = (vv.w - mu) * rs * ga.w + be.w;
            oh[(j * 32 + lane) * 2]     = __floats2half2_rn(o.x, o.y);
            oh[(j * 32 + lane) * 2 + 1] = __floats2half2_rn(o.z, o.w);
            int hh = (j * 32 + lane) * 4;
            sv[lr * 513 + hh + 0] = o.x;
            sv[lr * 513 + hh + 1] = o.y;
            sv[lr * 513 + hh + 2] = o.z;
            sv[lr * 513 + hh + 3] = o.w;
        }
    }
    __syncthreads();
#pragma unroll 4
    for (int it = 0; it < 64; it++) {
        int h = it * 8 + warp;
        float v = sv[lane * 513 + h];
        g_Uhi[((size_t)(b * H + h)) * LSEQ + l0 + lane] = __float2half_rn(v);
    }
}

// ================= launcher =================
extern "C" void kernel_launch(void* const* d_in, const int* in_sizes, int n_in,
                              void* d_out, int out_size)
{
    const float* x          = (const float*)d_in[0];
    const float* log_dt     = (const float*)d_in[1];
    const float* A_imag     = (const float*)d_in[2];
    const float* log_A_real = (const float*)d_in[3];
    const float* C          = (const float*)d_in[4];
    const float* D          = (const float*)d_in[5];
    const float* W          = (const float*)d_in[6];
    const float* bconv      = (const float*)d_in[7];
    const float* gamma      = (const float*)d_in[8];
    const float* beta       = (const float*)d_in[9];
    float* out = (float*)d_out;

    cudaFuncSetAttribute(conv_gemm, cudaFuncAttributeMaxDynamicSharedMemorySize,
                         C_DSMEM);
    cudaFuncSetAttribute(gemm_toep, cudaFuncAttributeMaxDynamicSharedMemorySize,
                         T_DSMEM);
    cudaFuncSetAttribute(gemm_endpre, cudaFuncAttributeMaxDynamicSharedMemorySize,
                         EP_DSMEM);
    cudaFuncSetAttribute(res_lnT<0>, cudaFuncAttributeMaxDynamicSharedMemorySize,
                         RL_SMEM);
    cudaFuncSetAttribute(res_lnT<1>, cudaFuncAttributeMaxDynamicSharedMemorySize,
                         RL_SMEM);

    __half* pA; cudaGetSymbolAddress((void**)&pA, g_x16A);
    __half* pB; cudaGetSymbolAddress((void**)&pB, g_x16B);

    w_prep<<<(NLAY * 2 * H * H) / 256, 256>>>(W, bconv);
    tbuild<<<dim3(H, NLAY), 256>>>(log_dt, A_imag, log_A_real, C, D);

    dim3 tb(32, 8);
    xsplit<<<dim3(H / 32, LSEQ / 32, BSZ), tb>>>(x);   // layer-0 U plane

    for (int i = 0; i < NLAY; i++) {
        gemm_endpre<<<H, 256, EP_DSMEM>>>(log_dt, A_imag, log_A_real, i);
        gemm_toep<<<dim3(2, H), 256, T_DSMEM>>>(i);
        conv_gemm<<<dim3(2 * H / 128, MROWS / 128), 256, C_DSMEM>>>(i);
        if (i == 0)
            res_lnT<1><<<MROWS / 32, 256, RL_SMEM>>>(x, nullptr, pA,
                                                     gamma, beta, 0);
        else if (i == 1)
            res_lnT<0><<<MROWS / 32, 256, RL_SMEM>>>(nullptr, pA, pB,
                                                     gamma, beta, 1);
        else if (i == 2)
            res_lnT<0><<<MROWS / 32, 256, RL_SMEM>>>(nullptr, pB, pA,
                                                     gamma, beta, 2);
        else
            res_ln_final<<<MROWS / 4, 128>>>(pA, out, gamma, beta, 3);
    }
}